// round 6
// baseline (speedup 1.0000x reference)
#include <cuda_runtime.h>
#include <cuda_bf16.h>
#include <math.h>
#include <stdint.h>

// Problem constants
#define BBB 32
#define SSS 512
#define DDD 1024
#define HHH 16
#define DHH 64
#define LLL 4
#define DFFF 2048
#define DMEMM 512
#define TTT (BBB * SSS)   // 16384 tokens

// ---------------------------------------------------------------------------
// Scratch (static device globals — no allocation at runtime)
// ---------------------------------------------------------------------------
__device__ float g_h[(size_t)TTT * DDD];              //  64 MB
__device__ float g_tmp[(size_t)TTT * DDD];            //  64 MB
__device__ float g_pe[(size_t)SSS * DDD];             //   2 MB  PE table
__device__ __nv_bfloat16 g_hhi[(size_t)TTT * DDD];    //  32 MB
__device__ __nv_bfloat16 g_hlo[(size_t)TTT * DDD];
__device__ __nv_bfloat16 g_bhi[(size_t)TTT * DFFF];   //  64 MB  ctx / ff split
__device__ __nv_bfloat16 g_blo[(size_t)TTT * DFFF];
__device__ __nv_bfloat16 g_qkvhi[(size_t)TTT * 3 * DDD];  // 96 MB
__device__ __nv_bfloat16 g_qkvlo[(size_t)TTT * 3 * DDD];  // 96 MB
#define WTOT 34078720ULL
__device__ __nv_bfloat16 g_whi[WTOT];
__device__ __nv_bfloat16 g_wlo[WTOT];

#define OFF_QKV 0ULL
#define OFF_WO  12582912ULL
#define OFF_W1  16777216ULL
#define OFF_W2  25165824ULL
#define OFF_WOUT 33554432ULL

// ---------------------------------------------------------------------------
// PTX helpers (baseline sm_80+: mma.sync / ldmatrix / cp.async)
// ---------------------------------------------------------------------------
__device__ __forceinline__ uint32_t smem_u32(const void* p) {
    uint32_t a;
    asm("{ .reg .u64 t; cvta.to.shared.u64 t, %1; cvt.u32.u64 %0, t; }" : "=r"(a) : "l"(p));
    return a;
}

#define CP16(saddr, gptr) \
    asm volatile("cp.async.cg.shared.global [%0], [%1], 16;" :: "r"(saddr), "l"(gptr))
#define CPCOMMIT() asm volatile("cp.async.commit_group;" ::: "memory")
#define CPWAIT(n)  asm volatile("cp.async.wait_group %0;" :: "n"(n) : "memory")

#define LDSM4(r, addr)                                                          \
    asm volatile("ldmatrix.sync.aligned.m8n8.x4.shared.b16 {%0,%1,%2,%3}, [%4];" \
        : "=r"((r)[0]), "=r"((r)[1]), "=r"((r)[2]), "=r"((r)[3]) : "r"(addr))

#define LDSM4T(r, addr)                                                          \
    asm volatile("ldmatrix.sync.aligned.m8n8.x4.trans.shared.b16 {%0,%1,%2,%3}, [%4];" \
        : "=r"((r)[0]), "=r"((r)[1]), "=r"((r)[2]), "=r"((r)[3]) : "r"(addr))

#define MMA_BF16(d, a, b0v, b1v)                                                \
    asm volatile("mma.sync.aligned.m16n8k16.row.col.f32.bf16.bf16.f32 "         \
        "{%0,%1,%2,%3}, {%4,%5,%6,%7}, {%8,%9}, {%0,%1,%2,%3};"                 \
        : "+f"((d)[0]), "+f"((d)[1]), "+f"((d)[2]), "+f"((d)[3])                \
        : "r"((a)[0]), "r"((a)[1]), "r"((a)[2]), "r"((a)[3]), "r"(b0v), "r"(b1v))

__device__ __forceinline__ void split_bf16(float v, __nv_bfloat16& h, __nv_bfloat16& l) {
    h = __float2bfloat16(v);
    l = __float2bfloat16(v - __bfloat162float(h));
}
__device__ __forceinline__ uint32_t pack_hi2(float a, float b) {
    uint32_t r;
    asm("cvt.rn.bf16x2.f32 %0, %1, %2;" : "=r"(r) : "f"(b), "f"(a));
    return r;
}
__device__ __forceinline__ float bf_round(float v) {
    return __bfloat162float(__float2bfloat16(v));
}

// ---------------------------------------------------------------------------
// 0) merged weight split: all 5 weights, one launch
// ---------------------------------------------------------------------------
#define F4_QKV 3145728
#define F4_WO  (F4_QKV + 1048576)
#define F4_W1  (F4_WO + 2097152)
#define F4_W2  (F4_W1 + 2097152)
#define F4_ALL (F4_W2 + 131072)

__global__ __launch_bounds__(256)
void cvt_split_all(const float* __restrict__ Wqkv, const float* __restrict__ Wo,
                   const float* __restrict__ W1, const float* __restrict__ W2,
                   const float* __restrict__ Wout,
                   __nv_bfloat16* __restrict__ hi, __nv_bfloat16* __restrict__ lo) {
    int i = blockIdx.x * 256 + threadIdx.x;
    if (i >= F4_ALL) return;
    const float* src;
    int li;
    if (i < F4_QKV)      { src = Wqkv; li = i; }
    else if (i < F4_WO)  { src = Wo;   li = i - F4_QKV; }
    else if (i < F4_W1)  { src = W1;   li = i - F4_WO; }
    else if (i < F4_W2)  { src = W2;   li = i - F4_W1; }
    else                 { src = Wout; li = i - F4_W2; }
    float4 v = reinterpret_cast<const float4*>(src)[li];
    __nv_bfloat16 h0, h1, h2, h3, l0, l1, l2, l3;
    split_bf16(v.x, h0, l0); split_bf16(v.y, h1, l1);
    split_bf16(v.z, h2, l2); split_bf16(v.w, h3, l3);
    __nv_bfloat162 a, b;
    a.x = h0; a.y = h1; b.x = h2; b.y = h3;
    reinterpret_cast<__nv_bfloat162*>(hi)[2 * i]     = a;
    reinterpret_cast<__nv_bfloat162*>(hi)[2 * i + 1] = b;
    a.x = l0; a.y = l1; b.x = l2; b.y = l3;
    reinterpret_cast<__nv_bfloat162*>(lo)[2 * i]     = a;
    reinterpret_cast<__nv_bfloat162*>(lo)[2 * i + 1] = b;
}

// ---------------------------------------------------------------------------
// 1a) PE table
// ---------------------------------------------------------------------------
__global__ __launch_bounds__(256)
void pe_table_kernel(float* __restrict__ pe) {
    int idx = blockIdx.x * 256 + threadIdx.x;
    int d = idx & (DDD - 1);
    int s = idx >> 10;
    float div = expf((float)(d & ~1) * (-9.2103403719761836f / (float)DDD));
    float ang = (float)s * div;
    pe[idx] = (d & 1) ? cosf(ang) : sinf(ang);
}

// ---------------------------------------------------------------------------
// 1b) h[s,b,:] = x[b,s,:] + PE[s,:]   (float4 streaming, + split emit)
// ---------------------------------------------------------------------------
__global__ __launch_bounds__(256)
void add_pe_kernel(const float* __restrict__ x, const float* __restrict__ pe,
                   float* __restrict__ h,
                   __nv_bfloat16* __restrict__ hhi, __nv_bfloat16* __restrict__ hlo) {
    int i4 = blockIdx.x * 256 + threadIdx.x;
    int d4  = i4 & 255;
    int row = i4 >> 8;
    int s   = row >> 5;
    int b   = row & 31;
    float4 xv = reinterpret_cast<const float4*>(x)[((size_t)(b * SSS + s) << 8) + d4];
    float4 pv = reinterpret_cast<const float4*>(pe)[((size_t)s << 8) + d4];
    float4 v;
    v.x = xv.x + pv.x; v.y = xv.y + pv.y; v.z = xv.z + pv.z; v.w = xv.w + pv.w;
    reinterpret_cast<float4*>(h)[i4] = v;
    __nv_bfloat16 h0, h1, h2, h3, l0, l1, l2, l3;
    split_bf16(v.x, h0, l0); split_bf16(v.y, h1, l1);
    split_bf16(v.z, h2, l2); split_bf16(v.w, h3, l3);
    __nv_bfloat162 p0, p1;
    p0.x = h0; p0.y = h1; p1.x = h2; p1.y = h3;
    reinterpret_cast<__nv_bfloat162*>(hhi)[2 * i4]     = p0;
    reinterpret_cast<__nv_bfloat162*>(hhi)[2 * i4 + 1] = p1;
    p0.x = l0; p0.y = l1; p1.x = l2; p1.y = l3;
    reinterpret_cast<__nv_bfloat162*>(hlo)[2 * i4]     = p0;
    reinterpret_cast<__nv_bfloat162*>(hlo)[2 * i4 + 1] = p1;
}

// ---------------------------------------------------------------------------
// 2) HMMA GEMM (bf16x3); 2 CTAs/SM, ONE sync per k-chunk
// ---------------------------------------------------------------------------
#define SROWB 80
#define A_HI 0u
#define A_LO 10240u
#define W_HI 20480u
#define W_LO 30720u
#define STAGE_B 40960u
#define GEMM_SMEM (2 * 40960)

template <int PERM>
__device__ __forceinline__ void load_stage(
    uint32_t sbase,
    const __nv_bfloat16* __restrict__ Ahi, const __nv_bfloat16* __restrict__ Alo,
    const __nv_bfloat16* __restrict__ Whi, const __nv_bfloat16* __restrict__ Wlo,
    int m0, int n0, int K, int k0, int t) {
#pragma unroll
    for (int i = 0; i < 2; ++i) {
        int u = t + i * 256;
        int row = u >> 2, c8 = u & 3;
        int garow = m0 + row;
        if (PERM) garow = ((garow & 511) << 5) | (garow >> 9);
        const __nv_bfloat16* pa_hi = Ahi + (size_t)garow * K + k0 + c8 * 8;
        const __nv_bfloat16* pa_lo = Alo + (size_t)garow * K + k0 + c8 * 8;
        const __nv_bfloat16* pw_hi = Whi + (size_t)(n0 + row) * K + k0 + c8 * 8;
        const __nv_bfloat16* pw_lo = Wlo + (size_t)(n0 + row) * K + k0 + c8 * 8;
        uint32_t d = (uint32_t)(row * SROWB + c8 * 16);
        CP16(sbase + A_HI + d, pa_hi);
        CP16(sbase + A_LO + d, pa_lo);
        CP16(sbase + W_HI + d, pw_hi);
        CP16(sbase + W_LO + d, pw_lo);
    }
}

template <int RELU, int PERM, int SPLIT>
__global__ __launch_bounds__(256, 2)
void gemm_mma(const __nv_bfloat16* __restrict__ Ahi, const __nv_bfloat16* __restrict__ Alo,
              const __nv_bfloat16* __restrict__ Whi, const __nv_bfloat16* __restrict__ Wlo,
              const float* __restrict__ bias, float* __restrict__ C,
              __nv_bfloat16* __restrict__ Chi, __nv_bfloat16* __restrict__ Clo,
              int M, int N, int K) {
    extern __shared__ char smem[];
    const uint32_t sb = smem_u32(smem);
    const int t    = threadIdx.x;
    const int lane = t & 31;
    const int w    = t >> 5;
    const int wm   = w & 1;
    const int wn   = w >> 1;
    const int m0   = blockIdx.y * 128;
    const int n0   = blockIdx.x * 128;

    float acc[4][4][4];
#pragma unroll
    for (int a = 0; a < 4; a++)
#pragma unroll
        for (int b = 0; b < 4; b++)
#pragma unroll
            for (int c = 0; c < 4; c++) acc[a][b][c] = 0.f;

    const uint32_t a_off = (uint32_t)((wm * 64 + (lane & 15)) * SROWB + (lane >> 4) * 16);
    const int brow = wn * 32 + (lane & 7) + ((lane & 16) >> 1);
    const uint32_t b_off = (uint32_t)(brow * SROWB + ((lane >> 3) & 1) * 16);

    const int NC = K >> 5;
    load_stage<PERM>(sb, Ahi, Alo, Whi, Wlo, m0, n0, K, 0, t);
    CPCOMMIT();

    for (int c = 0; c < NC; ++c) {
        // stage-c data landed (issued last iteration / prologue); every warp is
        // past compute(c-1), so buffer (c+1)&1 is free to overwrite.
        CPWAIT(0);
        __syncthreads();
        if (c + 1 < NC) {
            load_stage<PERM>(sb + (uint32_t)((c + 1) & 1) * STAGE_B,
                             Ahi, Alo, Whi, Wlo, m0, n0, K, (c + 1) << 5, t);
            CPCOMMIT();
        }
        const uint32_t stb = sb + (uint32_t)(c & 1) * STAGE_B;
#pragma unroll
        for (int ks = 0; ks < 2; ++ks) {
            const uint32_t ao = stb + a_off + ks * 32;
            const uint32_t bo = stb + b_off + ks * 32;
            uint32_t fa_hi[4][4], fa_lo[4][4];
#pragma unroll
            for (int mi = 0; mi < 4; ++mi) {
                LDSM4(fa_hi[mi], ao + A_HI + mi * (16 * SROWB));
                LDSM4(fa_lo[mi], ao + A_LO + mi * (16 * SROWB));
            }
            uint32_t fb_hi[2][4], fb_lo[2][4];
#pragma unroll
            for (int nj = 0; nj < 2; ++nj) {
                LDSM4(fb_hi[nj], bo + W_HI + nj * (16 * SROWB));
                LDSM4(fb_lo[nj], bo + W_LO + nj * (16 * SROWB));
            }
#pragma unroll
            for (int mi = 0; mi < 4; ++mi)
#pragma unroll
                for (int ni = 0; ni < 4; ++ni) {
                    const int nj = ni >> 1, kk = (ni & 1) * 2;
                    MMA_BF16(acc[mi][ni], fa_hi[mi], fb_hi[nj][kk], fb_hi[nj][kk + 1]);
                    MMA_BF16(acc[mi][ni], fa_hi[mi], fb_lo[nj][kk], fb_lo[nj][kk + 1]);
                    MMA_BF16(acc[mi][ni], fa_lo[mi], fb_hi[nj][kk], fb_hi[nj][kk + 1]);
                }
        }
        // no trailing barrier: next iteration's top barrier provides it
    }

    const int qrow = lane >> 2;
    const int qcol = (lane & 3) * 2;
#pragma unroll
    for (int mi = 0; mi < 4; ++mi) {
        const int row0 = m0 + wm * 64 + mi * 16 + qrow;
#pragma unroll
        for (int ni = 0; ni < 4; ++ni) {
            const int col = n0 + wn * 32 + ni * 8 + qcol;
            const float bb0 = bias[col];
            const float bb1 = bias[col + 1];
            float v00 = acc[mi][ni][0] + bb0;
            float v01 = acc[mi][ni][1] + bb1;
            float v10 = acc[mi][ni][2] + bb0;
            float v11 = acc[mi][ni][3] + bb1;
            if (RELU) {
                v00 = fmaxf(v00, 0.f); v01 = fmaxf(v01, 0.f);
                v10 = fmaxf(v10, 0.f); v11 = fmaxf(v11, 0.f);
            }
            if (SPLIT) {
                __nv_bfloat16 h0, l0, h1, l1;
                __nv_bfloat162 hh, ll;
                split_bf16(v00, h0, l0); split_bf16(v01, h1, l1);
                hh.x = h0; hh.y = h1; ll.x = l0; ll.y = l1;
                *reinterpret_cast<__nv_bfloat162*>(Chi + (size_t)row0 * N + col) = hh;
                *reinterpret_cast<__nv_bfloat162*>(Clo + (size_t)row0 * N + col) = ll;
                split_bf16(v10, h0, l0); split_bf16(v11, h1, l1);
                hh.x = h0; hh.y = h1; ll.x = l0; ll.y = l1;
                *reinterpret_cast<__nv_bfloat162*>(Chi + (size_t)(row0 + 8) * N + col) = hh;
                *reinterpret_cast<__nv_bfloat162*>(Clo + (size_t)(row0 + 8) * N + col) = ll;
            } else {
                *reinterpret_cast<float2*>(C + (size_t)row0 * N + col) =
                    make_float2(v00, v01);
                *reinterpret_cast<float2*>(C + (size_t)(row0 + 8) * N + col) =
                    make_float2(v10, v11);
            }
        }
    }
}

// ---------------------------------------------------------------------------
// 3) HMMA flash attention, bf16x3 compensated (unchanged)
// ---------------------------------------------------------------------------
#define AROWB 144
#define AQ_HI 0u
#define AQ_LO 18432u
#define AST0  36864u
#define ASTG  36864u
#define AK_HI 0u
#define AK_LO 9216u
#define AV_HI 18432u
#define AV_LO 27648u
#define ATTN_SMEM (36864 + 2 * 36864)

__device__ __forceinline__ void attn_load_kv(
    uint32_t sbase, const __nv_bfloat16* __restrict__ qhi,
    const __nv_bfloat16* __restrict__ qlo, int b, int hd, int kt, int t) {
#pragma unroll
    for (int i = 0; i < 8; ++i) {
        int u = t + i * 256;
        int sel = u >> 9;
        int v = u & 511;
        int row = v >> 3, seg = v & 7;
        const __nv_bfloat16* base = (sel & 1) ? qlo : qhi;
        int off = (sel >> 1) ? 2048 : 1024;
        const __nv_bfloat16* src =
            base + ((size_t)((kt * 64 + row) * BBB + b)) * 3072 + off + hd + seg * 8;
        uint32_t dst = sbase + (uint32_t)sel * 9216u + (uint32_t)(row * AROWB + seg * 16);
        CP16(dst, src);
    }
}

__global__ __launch_bounds__(256, 2)
void attn_mma_kernel(const __nv_bfloat16* __restrict__ qhi,
                     const __nv_bfloat16* __restrict__ qlo,
                     __nv_bfloat16* __restrict__ chi, __nv_bfloat16* __restrict__ clo) {
    extern __shared__ char smem[];
    const uint32_t sb = smem_u32(smem);
    const int t    = threadIdx.x;
    const int lane = t & 31;
    const int w    = t >> 5;
    const int b    = blockIdx.y >> 4;
    const int h    = blockIdx.y & 15;
    const int q0   = blockIdx.x * 128;
    const int hd   = h * DHH;

#pragma unroll
    for (int i = 0; i < 8; ++i) {
        int u = t + i * 256;
        int ishi = (u < 1024);
        int v = u & 1023;
        int row = v >> 3, seg = v & 7;
        const __nv_bfloat16* src = (ishi ? qhi : qlo) +
            ((size_t)((q0 + row) * BBB + b)) * 3072 + hd + seg * 8;
        uint32_t dst = sb + (ishi ? AQ_HI : AQ_LO) + (uint32_t)(row * AROWB + seg * 16);
        CP16(dst, src);
    }
    CPCOMMIT();
    attn_load_kv(sb + AST0, qhi, qlo, b, hd, 0, t);
    CPCOMMIT();

    float Oa[8][4];
#pragma unroll
    for (int j = 0; j < 8; j++)
#pragma unroll
        for (int c = 0; c < 4; c++) Oa[j][c] = 0.f;
    float m0r = -1e30f, m1r = -1e30f, l0r = 0.f, l1r = 0.f;

    const uint32_t arow_off = (uint32_t)((w * 16 + (lane & 15)) * AROWB + (lane >> 4) * 16);
    const uint32_t brow_off = (uint32_t)(((lane & 7) + ((lane & 16) >> 1)) * AROWB +
                                         ((lane >> 3) & 1) * 16);
    const uint32_t vrow_off = (uint32_t)((lane & 15) * AROWB + (lane >> 4) * 16);

    for (int kt = 0; kt < 8; ++kt) {
        CPWAIT(0);
        __syncthreads();
        if (kt + 1 < 8) {
            attn_load_kv(sb + AST0 + (uint32_t)((kt + 1) & 1) * ASTG, qhi, qlo, b, hd,
                         kt + 1, t);
            CPCOMMIT();
        }
        const uint32_t stg = sb + AST0 + (uint32_t)(kt & 1) * ASTG;

        float st[8][4];
#pragma unroll
        for (int j = 0; j < 8; j++)
#pragma unroll
            for (int c = 0; c < 4; c++) st[j][c] = 0.f;
#pragma unroll
        for (int pass = 0; pass < 3; ++pass) {
            const uint32_t abase = sb + (pass == 2 ? AQ_LO : AQ_HI) + arow_off;
            const uint32_t bbase = stg + (pass == 1 ? AK_LO : AK_HI) + brow_off;
#pragma unroll
            for (int kc = 0; kc < 4; ++kc) {
                uint32_t fa[4];
                LDSM4(fa, abase + kc * 32);
#pragma unroll
                for (int g = 0; g < 4; ++g) {
                    uint32_t fb[4];
                    LDSM4(fb, bbase + g * (16 * AROWB) + kc * 32);
                    MMA_BF16(st[2 * g],     fa, fb[0], fb[1]);
                    MMA_BF16(st[2 * g + 1], fa, fb[2], fb[3]);
                }
            }
        }

        float mx0 = -1e30f, mx1 = -1e30f;
#pragma unroll
        for (int j = 0; j < 8; j++) {
            st[j][0] *= 0.125f; st[j][1] *= 0.125f;
            st[j][2] *= 0.125f; st[j][3] *= 0.125f;
            mx0 = fmaxf(mx0, fmaxf(st[j][0], st[j][1]));
            mx1 = fmaxf(mx1, fmaxf(st[j][2], st[j][3]));
        }
        mx0 = fmaxf(mx0, __shfl_xor_sync(0xffffffffu, mx0, 1));
        mx0 = fmaxf(mx0, __shfl_xor_sync(0xffffffffu, mx0, 2));
        mx1 = fmaxf(mx1, __shfl_xor_sync(0xffffffffu, mx1, 1));
        mx1 = fmaxf(mx1, __shfl_xor_sync(0xffffffffu, mx1, 2));
        const float nm0 = fmaxf(m0r, mx0), nm1 = fmaxf(m1r, mx1);
        const float al0 = __expf(m0r - nm0), al1 = __expf(m1r - nm1);
        float s0 = 0.f, s1 = 0.f;
#pragma unroll
        for (int j = 0; j < 8; j++) {
            st[j][0] = __expf(st[j][0] - nm0);
            st[j][1] = __expf(st[j][1] - nm0);
            st[j][2] = __expf(st[j][2] - nm1);
            st[j][3] = __expf(st[j][3] - nm1);
            s0 += st[j][0] + st[j][1];
            s1 += st[j][2] + st[j][3];
        }
        s0 += __shfl_xor_sync(0xffffffffu, s0, 1);
        s0 += __shfl_xor_sync(0xffffffffu, s0, 2);
        s1 += __shfl_xor_sync(0xffffffffu, s1, 1);
        s1 += __shfl_xor_sync(0xffffffffu, s1, 2);
        l0r = l0r * al0 + s0;
        l1r = l1r * al1 + s1;
        m0r = nm0; m1r = nm1;
#pragma unroll
        for (int j = 0; j < 8; j++) {
            Oa[j][0] *= al0; Oa[j][1] *= al0;
            Oa[j][2] *= al1; Oa[j][3] *= al1;
        }

#pragma unroll
        for (int kc = 0; kc < 4; ++kc) {
            uint32_t ah[4], alo[4];
            {
                const float* p0 = st[2 * kc];
                const float* p1 = st[2 * kc + 1];
                ah[0] = pack_hi2(p0[0], p0[1]);
                ah[1] = pack_hi2(p0[2], p0[3]);
                ah[2] = pack_hi2(p1[0], p1[1]);
                ah[3] = pack_hi2(p1[2], p1[3]);
                alo[0] = pack_hi2(p0[0] - bf_round(p0[0]), p0[1] - bf_round(p0[1]));
                alo[1] = pack_hi2(p0[2] - bf_round(p0[2]), p0[3] - bf_round(p0[3]));
                alo[2] = pack_hi2(p1[0] - bf_round(p1[0]), p1[1] - bf_round(p1[1]));
                alo[3] = pack_hi2(p1[2] - bf_round(p1[2]), p1[3] - bf_round(p1[3]));
            }
            const uint32_t vbase = stg + (uint32_t)(kc * 16 * AROWB) + vrow_off;
#pragma unroll
            for (int g = 0; g < 4; ++g) {
                uint32_t fvh[4], fvl[4];
                LDSM4T(fvh, vbase + AV_HI + g * 32);
                MMA_BF16(Oa[2 * g],     ah,  fvh[0], fvh[1]);
                MMA_BF16(Oa[2 * g + 1], ah,  fvh[2], fvh[3]);
                MMA_BF16(Oa[2 * g],     alo, fvh[0], fvh[1]);
                MMA_BF16(Oa[2 * g + 1], alo, fvh[2], fvh[3]);
                LDSM4T(fvl, vbase + AV_LO + g * 32);
                MMA_BF16(Oa[2 * g],     ah,  fvl[0], fvl[1]);
                MMA_BF16(Oa[2 * g + 1], ah,  fvl[2], fvl[3]);
            }
        }
    }

    const float inv0 = 1.f / l0r;
    const float inv1 = 1.f / l1r;
    const int r_lo = q0 + w * 16 + (lane >> 2);
    const int col0 = hd + (lane & 3) * 2;
#pragma unroll
    for (int j = 0; j < 8; j++) {
        const int col = col0 + j * 8;
        float v0 = Oa[j][0] * inv0, v1 = Oa[j][1] * inv0;
        float v2 = Oa[j][2] * inv1, v3 = Oa[j][3] * inv1;
        __nv_bfloat16 h0, l0, h1, l1;
        __nv_bfloat162 hh, ll;
        size_t o0 = ((size_t)(r_lo * BBB + b)) * 1024 + col;
        split_bf16(v0, h0, l0); split_bf16(v1, h1, l1);
        hh.x = h0; hh.y = h1; ll.x = l0; ll.y = l1;
        *reinterpret_cast<__nv_bfloat162*>(chi + o0) = hh;
        *reinterpret_cast<__nv_bfloat162*>(clo + o0) = ll;
        size_t o1 = ((size_t)((r_lo + 8) * BBB + b)) * 1024 + col;
        split_bf16(v2, h0, l0); split_bf16(v3, h1, l1);
        hh.x = h0; hh.y = h1; ll.x = l0; ll.y = l1;
        *reinterpret_cast<__nv_bfloat162*>(chi + o1) = hh;
        *reinterpret_cast<__nv_bfloat162*>(clo + o1) = ll;
    }
}

// ---------------------------------------------------------------------------
// 4) LayerNorm with warp-shuffle reductions (+ bf16 split emit)
// ---------------------------------------------------------------------------
__global__ __launch_bounds__(256)
void ln_kernel(const float* __restrict__ a, const float* __restrict__ r,
               const float* __restrict__ g, const float* __restrict__ b,
               float* __restrict__ out,
               __nv_bfloat16* __restrict__ ohi, __nv_bfloat16* __restrict__ olo) {
    __shared__ float red1[8];
    __shared__ float red2[8];
    const int t = threadIdx.x;
    const int lane = t & 31;
    const int w = t >> 5;
    const size_t row = blockIdx.x;
    float4 v = reinterpret_cast<const float4*>(a + row * 1024)[t];
    if (r != nullptr) {
        float4 rv = reinterpret_cast<const float4*>(r + row * 1024)[t];
        v.x += rv.x; v.y += rv.y; v.z += rv.z; v.w += rv.w;
    }
    float s = v.x + v.y + v.z + v.w;
#pragma unroll
    for (int o = 16; o > 0; o >>= 1) s += __shfl_xor_sync(0xffffffffu, s, o);
    if (lane == 0) red1[w] = s;
    __syncthreads();
    float mu = (red1[0] + red1[1] + red1[2] + red1[3] +
                red1[4] + red1[5] + red1[6] + red1[7]) * (1.f / 1024.f);
    float dx = v.x - mu, dy = v.y - mu, dz = v.z - mu, dw = v.w - mu;
    float q = dx * dx + dy * dy + dz * dz + dw * dw;
#pragma unroll
    for (int o = 16; o > 0; o >>= 1) q += __shfl_xor_sync(0xffffffffu, q, o);
    if (lane == 0) red2[w] = q;
    __syncthreads();
    float var = (red2[0] + red2[1] + red2[2] + red2[3] +
                 red2[4] + red2[5] + red2[6] + red2[7]) * (1.f / 1024.f);
    float inv = rsqrtf(var + 1e-5f);
    float4 g4 = reinterpret_cast<const float4*>(g)[t];
    float4 b4 = reinterpret_cast<const float4*>(b)[t];
    float4 o4;
    o4.x = dx * inv * g4.x + b4.x;
    o4.y = dy * inv * g4.y + b4.y;
    o4.z = dz * inv * g4.z + b4.z;
    o4.w = dw * inv * g4.w + b4.w;
    reinterpret_cast<float4*>(out + row * 1024)[t] = o4;
    if (ohi != nullptr) {
        __nv_bfloat16 h0, h1, h2, h3, l0, l1, l2, l3;
        split_bf16(o4.x, h0, l0); split_bf16(o4.y, h1, l1);
        split_bf16(o4.z, h2, l2); split_bf16(o4.w, h3, l3);
        __nv_bfloat162 p0, p1;
        p0.x = h0; p0.y = h1; p1.x = h2; p1.y = h3;
        reinterpret_cast<__nv_bfloat162*>(ohi + row * 1024)[2 * t]     = p0;
        reinterpret_cast<__nv_bfloat162*>(ohi + row * 1024)[2 * t + 1] = p1;
        p0.x = l0; p0.y = l1; p1.x = l2; p1.y = l3;
        reinterpret_cast<__nv_bfloat162*>(olo + row * 1024)[2 * t]     = p0;
        reinterpret_cast<__nv_bfloat162*>(olo + row * 1024)[2 * t + 1] = p1;
    }
}

// ---------------------------------------------------------------------------
// Host orchestration
// ---------------------------------------------------------------------------
extern "C" void kernel_launch(void* const* d_in, const int* in_sizes, int n_in,
                              void* d_out, int out_size) {
    (void)in_sizes; (void)n_in; (void)out_size;
    const float* x    = (const float*)d_in[0];
    const float* Wqkv = (const float*)d_in[1];
    const float* bqkv = (const float*)d_in[2];
    const float* Wo   = (const float*)d_in[3];
    const float* bo   = (const float*)d_in[4];
    const float* W1   = (const float*)d_in[5];
    const float* b1   = (const float*)d_in[6];
    const float* W2   = (const float*)d_in[7];
    const float* b2   = (const float*)d_in[8];
    const float* ln1g = (const float*)d_in[9];
    const float* ln1b = (const float*)d_in[10];
    const float* ln2g = (const float*)d_in[11];
    const float* ln2b = (const float*)d_in[12];
    const float* lnfg = (const float*)d_in[13];
    const float* lnfb = (const float*)d_in[14];
    const float* Wout = (const float*)d_in[15];
    const float* bout = (const float*)d_in[16];
    float* out = (float*)d_out;

    float *h, *tmp, *pe;
    __nv_bfloat16 *hhi, *hlo, *bhi, *blo, *whi, *wlo, *qvh, *qvl;
    cudaGetSymbolAddress((void**)&h,   g_h);
    cudaGetSymbolAddress((void**)&tmp, g_tmp);
    cudaGetSymbolAddress((void**)&pe,  g_pe);
    cudaGetSymbolAddress((void**)&hhi, g_hhi);
    cudaGetSymbolAddress((void**)&hlo, g_hlo);
    cudaGetSymbolAddress((void**)&bhi, g_bhi);
    cudaGetSymbolAddress((void**)&blo, g_blo);
    cudaGetSymbolAddress((void**)&whi, g_whi);
    cudaGetSymbolAddress((void**)&wlo, g_wlo);
    cudaGetSymbolAddress((void**)&qvh, g_qkvhi);
    cudaGetSymbolAddress((void**)&qvl, g_qkvlo);

    cudaFuncSetAttribute(gemm_mma<0, 0, 0>, cudaFuncAttributeMaxDynamicSharedMemorySize, GEMM_SMEM);
    cudaFuncSetAttribute(gemm_mma<0, 0, 1>, cudaFuncAttributeMaxDynamicSharedMemorySize, GEMM_SMEM);
    cudaFuncSetAttribute(gemm_mma<1, 0, 1>, cudaFuncAttributeMaxDynamicSharedMemorySize, GEMM_SMEM);
    cudaFuncSetAttribute(gemm_mma<0, 1, 0>, cudaFuncAttributeMaxDynamicSharedMemorySize, GEMM_SMEM);
    cudaFuncSetAttribute(attn_mma_kernel, cudaFuncAttributeMaxDynamicSharedMemorySize, ATTN_SMEM);

    cvt_split_all<<<(F4_ALL + 255) / 256, 256>>>(Wqkv, Wo, W1, W2, Wout, whi, wlo);
    pe_table_kernel<<<(SSS * DDD) / 256, 256>>>(pe);
    add_pe_kernel<<<(TTT * DDD / 4) / 256, 256>>>(x, pe, h, hhi, hlo);

    for (int l = 0; l < LLL; l++) {
        const __nv_bfloat16* wq_h = whi + OFF_QKV + (size_t)l * 3145728;
        const __nv_bfloat16* wq_l = wlo + OFF_QKV + (size_t)l * 3145728;
        const __nv_bfloat16* wo_h = whi + OFF_WO + (size_t)l * 1048576;
        const __nv_bfloat16* wo_l = wlo + OFF_WO + (size_t)l * 1048576;
        const __nv_bfloat16* w1_h = whi + OFF_W1 + (size_t)l * 2097152;
        const __nv_bfloat16* w1_l = wlo + OFF_W1 + (size_t)l * 2097152;
        const __nv_bfloat16* w2_h = whi + OFF_W2 + (size_t)l * 2097152;
        const __nv_bfloat16* w2_l = wlo + OFF_W2 + (size_t)l * 2097152;

        gemm_mma<0, 0, 1><<<dim3(3072 / 128, TTT / 128), 256, GEMM_SMEM>>>(
            hhi, hlo, wq_h, wq_l, bqkv + (size_t)l * 3072, nullptr, qvh, qvl,
            TTT, 3072, 1024);
        attn_mma_kernel<<<dim3(SSS / 128, BBB * HHH), 256, ATTN_SMEM>>>(
            qvh, qvl, bhi, blo);
        gemm_mma<0, 0, 0><<<dim3(1024 / 128, TTT / 128), 256, GEMM_SMEM>>>(
            bhi, blo, wo_h, wo_l, bo + (size_t)l * 1024, tmp, nullptr, nullptr,
            TTT, 1024, 1024);
        ln_kernel<<<TTT, 256>>>(h, tmp, ln1g + (size_t)l * 1024, ln1b + (size_t)l * 1024,
                                h, hhi, hlo);
        gemm_mma<1, 0, 1><<<dim3(2048 / 128, TTT / 128), 256, GEMM_SMEM>>>(
            hhi, hlo, w1_h, w1_l, b1 + (size_t)l * 2048, nullptr, bhi, blo,
            TTT, 2048, 1024);
        gemm_mma<0, 0, 0><<<dim3(1024 / 128, TTT / 128), 256, GEMM_SMEM>>>(
            bhi, blo, w2_h, w2_l, b2 + (size_t)l * 1024, tmp, nullptr, nullptr,
            TTT, 1024, 2048);
        ln_kernel<<<TTT, 256>>>(h, tmp, ln2g + (size_t)l * 1024, ln2b + (size_t)l * 1024,
                                h, hhi, hlo);
    }

    ln_kernel<<<TTT, 256>>>(h, nullptr, lnfg, lnfb, h, hhi, hlo);
    gemm_mma<0, 1, 0><<<dim3(DMEMM / 128, TTT / 128), 256, GEMM_SMEM>>>(
        hhi, hlo, whi + OFF_WOUT, wlo + OFF_WOUT, bout, out, nullptr, nullptr,
        TTT, DMEMM, 1024);
}

// round 7
// speedup vs baseline: 1.4764x; 1.4764x over previous
#include <cuda_runtime.h>
#include <cuda_fp16.h>
#include <math.h>
#include <stdint.h>

// Problem constants
#define BBB 32
#define SSS 512
#define DDD 1024
#define HHH 16
#define DHH 64
#define LLL 4
#define DFFF 2048
#define DMEMM 512
#define TTT (BBB * SSS)   // 16384 tokens

// ---------------------------------------------------------------------------
// Scratch (static device globals)
// ---------------------------------------------------------------------------
__device__ float g_h[(size_t)TTT * DDD];              //  64 MB residual
__device__ float g_tmp[(size_t)TTT * DDD];            //  64 MB
__device__ float g_pe[(size_t)SSS * DDD];             //   2 MB
__device__ __half g_hf[(size_t)TTT * DDD];            //  32 MB activations fp16
__device__ __half g_ff[(size_t)TTT * DFFF];           //  64 MB ctx / ff fp16
__device__ __half g_qkvh[(size_t)TTT * 3 * DDD];      //  96 MB qkv hi
__device__ __half g_qkvl[(size_t)TTT * 3 * DDD];      //  96 MB qkv lo
#define WTOT 34078720ULL
__device__ __half g_wh[WTOT];                         //  68 MB weights hi
__device__ __half g_wl[WTOT];                         //  68 MB weights lo

#define OFF_QKV 0ULL
#define OFF_WO  12582912ULL
#define OFF_W1  16777216ULL
#define OFF_W2  25165824ULL
#define OFF_WOUT 33554432ULL

// ---------------------------------------------------------------------------
// PTX helpers (baseline sm_80+)
// ---------------------------------------------------------------------------
__device__ __forceinline__ uint32_t smem_u32(const void* p) {
    uint32_t a;
    asm("{ .reg .u64 t; cvta.to.shared.u64 t, %1; cvt.u32.u64 %0, t; }" : "=r"(a) : "l"(p));
    return a;
}

#define CP16(saddr, gptr) \
    asm volatile("cp.async.cg.shared.global [%0], [%1], 16;" :: "r"(saddr), "l"(gptr))
#define CPCOMMIT() asm volatile("cp.async.commit_group;" ::: "memory")
#define CPWAIT(n)  asm volatile("cp.async.wait_group %0;" :: "n"(n) : "memory")

#define LDSM4(r, addr)                                                          \
    asm volatile("ldmatrix.sync.aligned.m8n8.x4.shared.b16 {%0,%1,%2,%3}, [%4];" \
        : "=r"((r)[0]), "=r"((r)[1]), "=r"((r)[2]), "=r"((r)[3]) : "r"(addr))

#define LDSM4T(r, addr)                                                          \
    asm volatile("ldmatrix.sync.aligned.m8n8.x4.trans.shared.b16 {%0,%1,%2,%3}, [%4];" \
        : "=r"((r)[0]), "=r"((r)[1]), "=r"((r)[2]), "=r"((r)[3]) : "r"(addr))

#define MMA_F16(d, a, b0v, b1v)                                                 \
    asm volatile("mma.sync.aligned.m16n8k16.row.col.f32.f16.f16.f32 "           \
        "{%0,%1,%2,%3}, {%4,%5,%6,%7}, {%8,%9}, {%0,%1,%2,%3};"                 \
        : "+f"((d)[0]), "+f"((d)[1]), "+f"((d)[2]), "+f"((d)[3])                \
        : "r"((a)[0]), "r"((a)[1]), "r"((a)[2]), "r"((a)[3]), "r"(b0v), "r"(b1v))

__device__ __forceinline__ void split_f16(float v, __half& h, __half& l) {
    h = __float2half_rn(v);
    l = __float2half_rn(v - __half2float(h));
}
// pack (elem0=a, elem1=b) into f16x2
__device__ __forceinline__ uint32_t pack_h2(float a, float b) {
    uint32_t r;
    asm("cvt.rn.f16x2.f32 %0, %1, %2;" : "=r"(r) : "f"(b), "f"(a));
    return r;
}

// ---------------------------------------------------------------------------
// 0) merged weight split (fp16 hi/lo), one launch
// ---------------------------------------------------------------------------
#define F4_QKV 3145728
#define F4_WO  (F4_QKV + 1048576)
#define F4_W1  (F4_WO + 2097152)
#define F4_W2  (F4_W1 + 2097152)
#define F4_ALL (F4_W2 + 131072)

__global__ __launch_bounds__(256)
void cvt_split_all(const float* __restrict__ Wqkv, const float* __restrict__ Wo,
                   const float* __restrict__ W1, const float* __restrict__ W2,
                   const float* __restrict__ Wout,
                   __half* __restrict__ hi, __half* __restrict__ lo) {
    int i = blockIdx.x * 256 + threadIdx.x;
    if (i >= F4_ALL) return;
    const float* src;
    int li;
    if (i < F4_QKV)      { src = Wqkv; li = i; }
    else if (i < F4_WO)  { src = Wo;   li = i - F4_QKV; }
    else if (i < F4_W1)  { src = W1;   li = i - F4_WO; }
    else if (i < F4_W2)  { src = W2;   li = i - F4_W1; }
    else                 { src = Wout; li = i - F4_W2; }
    float4 v = reinterpret_cast<const float4*>(src)[li];
    __half h0, h1, h2, h3, l0, l1, l2, l3;
    split_f16(v.x, h0, l0); split_f16(v.y, h1, l1);
    split_f16(v.z, h2, l2); split_f16(v.w, h3, l3);
    reinterpret_cast<__half2*>(hi)[2 * i]     = __halves2half2(h0, h1);
    reinterpret_cast<__half2*>(hi)[2 * i + 1] = __halves2half2(h2, h3);
    reinterpret_cast<__half2*>(lo)[2 * i]     = __halves2half2(l0, l1);
    reinterpret_cast<__half2*>(lo)[2 * i + 1] = __halves2half2(l2, l3);
}

// ---------------------------------------------------------------------------
// 1a) PE table
// ---------------------------------------------------------------------------
__global__ __launch_bounds__(256)
void pe_table_kernel(float* __restrict__ pe) {
    int idx = blockIdx.x * 256 + threadIdx.x;
    int d = idx & (DDD - 1);
    int s = idx >> 10;
    float div = expf((float)(d & ~1) * (-9.2103403719761836f / (float)DDD));
    float ang = (float)s * div;
    pe[idx] = (d & 1) ? cosf(ang) : sinf(ang);
}

// ---------------------------------------------------------------------------
// 1b) h[s,b,:] = x[b,s,:] + PE[s,:]   (+ fp16 emit)
// ---------------------------------------------------------------------------
__global__ __launch_bounds__(256)
void add_pe_kernel(const float* __restrict__ x, const float* __restrict__ pe,
                   float* __restrict__ h, __half* __restrict__ hf) {
    int i4 = blockIdx.x * 256 + threadIdx.x;
    int d4  = i4 & 255;
    int row = i4 >> 8;
    int s   = row >> 5;
    int b   = row & 31;
    float4 xv = reinterpret_cast<const float4*>(x)[((size_t)(b * SSS + s) << 8) + d4];
    float4 pv = reinterpret_cast<const float4*>(pe)[((size_t)s << 8) + d4];
    float4 v;
    v.x = xv.x + pv.x; v.y = xv.y + pv.y; v.z = xv.z + pv.z; v.w = xv.w + pv.w;
    reinterpret_cast<float4*>(h)[i4] = v;
    reinterpret_cast<__half2*>(hf)[2 * i4] =
        __halves2half2(__float2half_rn(v.x), __float2half_rn(v.y));
    reinterpret_cast<__half2*>(hf)[2 * i4 + 1] =
        __halves2half2(__float2half_rn(v.z), __float2half_rn(v.w));
}

// ---------------------------------------------------------------------------
// 2) HMMA GEMM, fp16 2-pass: C = A @ (Wh+Wl)^T + bias
//    BM=128, BN=128, BK=32, 256 thr, warp tile 64x32, 2 CTAs/SM.
//    OUTMODE: 0 = float C, 1 = single fp16 out, 2 = fp16 hi+lo out.
// ---------------------------------------------------------------------------
#define SROWB 80
#define GA_OFF 0u
#define GWH_OFF 10240u
#define GWL_OFF 20480u
#define STAGE_B 30720u
#define GEMM_SMEM (2 * 30720)

template <int PERM>
__device__ __forceinline__ void load_stage(
    uint32_t sbase, const __half* __restrict__ A,
    const __half* __restrict__ Wh, const __half* __restrict__ Wl,
    int m0, int n0, int K, int k0, int t) {
#pragma unroll
    for (int i = 0; i < 6; ++i) {
        int u = t + i * 256;                 // 0..1535
        int sel = u >> 9;                    // 0 A, 1 Wh, 2 Wl
        int v = u & 511;
        int row = v >> 2, c8 = v & 3;
        const __half* src;
        if (sel == 0) {
            int garow = m0 + row;
            if (PERM) garow = ((garow & 511) << 5) | (garow >> 9);
            src = A + (size_t)garow * K + k0 + c8 * 8;
        } else if (sel == 1) {
            src = Wh + (size_t)(n0 + row) * K + k0 + c8 * 8;
        } else {
            src = Wl + (size_t)(n0 + row) * K + k0 + c8 * 8;
        }
        uint32_t dst = sbase + (uint32_t)sel * 10240u + (uint32_t)(row * SROWB + c8 * 16);
        CP16(dst, src);
    }
}

template <int RELU, int PERM, int OUTMODE>
__global__ __launch_bounds__(256, 2)
void gemm_mma(const __half* __restrict__ A,
              const __half* __restrict__ Wh, const __half* __restrict__ Wl,
              const float* __restrict__ bias, float* __restrict__ C,
              __half* __restrict__ Ch, __half* __restrict__ Cl,
              int M, int N, int K) {
    extern __shared__ char smem[];
    const uint32_t sb = smem_u32(smem);
    const int t    = threadIdx.x;
    const int lane = t & 31;
    const int w    = t >> 5;
    const int wm   = w & 1;
    const int wn   = w >> 1;
    const int m0   = blockIdx.y * 128;
    const int n0   = blockIdx.x * 128;

    float acc[4][4][4];
#pragma unroll
    for (int a = 0; a < 4; a++)
#pragma unroll
        for (int b = 0; b < 4; b++)
#pragma unroll
            for (int c = 0; c < 4; c++) acc[a][b][c] = 0.f;

    const uint32_t a_off = (uint32_t)((wm * 64 + (lane & 15)) * SROWB + (lane >> 4) * 16);
    const int brow = wn * 32 + (lane & 7) + ((lane & 16) >> 1);
    const uint32_t b_off = (uint32_t)(brow * SROWB + ((lane >> 3) & 1) * 16);

    const int NC = K >> 5;
    load_stage<PERM>(sb, A, Wh, Wl, m0, n0, K, 0, t);
    CPCOMMIT();

    for (int c = 0; c < NC; ++c) {
        CPWAIT(0);
        __syncthreads();
        if (c + 1 < NC) {
            load_stage<PERM>(sb + (uint32_t)((c + 1) & 1) * STAGE_B,
                             A, Wh, Wl, m0, n0, K, (c + 1) << 5, t);
            CPCOMMIT();
        }
        const uint32_t stb = sb + (uint32_t)(c & 1) * STAGE_B;
#pragma unroll
        for (int ks = 0; ks < 2; ++ks) {
            const uint32_t ao = stb + a_off + ks * 32;
            const uint32_t bo = stb + b_off + ks * 32;
            uint32_t fa[4][4];
#pragma unroll
            for (int mi = 0; mi < 4; ++mi)
                LDSM4(fa[mi], ao + GA_OFF + mi * (16 * SROWB));
            uint32_t fbh[2][4], fbl[2][4];
#pragma unroll
            for (int nj = 0; nj < 2; ++nj) {
                LDSM4(fbh[nj], bo + GWH_OFF + nj * (16 * SROWB));
                LDSM4(fbl[nj], bo + GWL_OFF + nj * (16 * SROWB));
            }
#pragma unroll
            for (int mi = 0; mi < 4; ++mi)
#pragma unroll
                for (int ni = 0; ni < 4; ++ni) {
                    const int nj = ni >> 1, kk = (ni & 1) * 2;
                    MMA_F16(acc[mi][ni], fa[mi], fbh[nj][kk], fbh[nj][kk + 1]);
                    MMA_F16(acc[mi][ni], fa[mi], fbl[nj][kk], fbl[nj][kk + 1]);
                }
        }
    }

    const int qrow = lane >> 2;
    const int qcol = (lane & 3) * 2;
#pragma unroll
    for (int mi = 0; mi < 4; ++mi) {
        const int row0 = m0 + wm * 64 + mi * 16 + qrow;
#pragma unroll
        for (int ni = 0; ni < 4; ++ni) {
            const int col = n0 + wn * 32 + ni * 8 + qcol;
            const float bb0 = bias[col];
            const float bb1 = bias[col + 1];
            float v00 = acc[mi][ni][0] + bb0;
            float v01 = acc[mi][ni][1] + bb1;
            float v10 = acc[mi][ni][2] + bb0;
            float v11 = acc[mi][ni][3] + bb1;
            if (RELU) {
                v00 = fmaxf(v00, 0.f); v01 = fmaxf(v01, 0.f);
                v10 = fmaxf(v10, 0.f); v11 = fmaxf(v11, 0.f);
            }
            if (OUTMODE == 0) {
                *reinterpret_cast<float2*>(C + (size_t)row0 * N + col) =
                    make_float2(v00, v01);
                *reinterpret_cast<float2*>(C + (size_t)(row0 + 8) * N + col) =
                    make_float2(v10, v11);
            } else if (OUTMODE == 1) {
                *reinterpret_cast<__half2*>(Ch + (size_t)row0 * N + col) =
                    __halves2half2(__float2half_rn(v00), __float2half_rn(v01));
                *reinterpret_cast<__half2*>(Ch + (size_t)(row0 + 8) * N + col) =
                    __halves2half2(__float2half_rn(v10), __float2half_rn(v11));
            } else {
                __half h0, l0, h1, l1;
                split_f16(v00, h0, l0); split_f16(v01, h1, l1);
                *reinterpret_cast<__half2*>(Ch + (size_t)row0 * N + col) = __halves2half2(h0, h1);
                *reinterpret_cast<__half2*>(Cl + (size_t)row0 * N + col) = __halves2half2(l0, l1);
                split_f16(v10, h0, l0); split_f16(v11, h1, l1);
                *reinterpret_cast<__half2*>(Ch + (size_t)(row0 + 8) * N + col) = __halves2half2(h0, h1);
                *reinterpret_cast<__half2*>(Cl + (size_t)(row0 + 8) * N + col) = __halves2half2(l0, l1);
            }
        }
    }
}

// ---------------------------------------------------------------------------
// 3) HMMA flash attention, fp16 2-pass.
//    Q single fp16; K,V fp16 hi+lo. P packed to fp16 (single).
// ---------------------------------------------------------------------------
#define AROWB 144
#define AQ_OFF 0u
#define AST0   18432u
#define ASTG   36864u
#define AKH 0u
#define AKL 9216u
#define AVH 18432u
#define AVL 27648u
#define ATTN_SMEM (18432 + 2 * 36864)

__device__ __forceinline__ void attn_load_kv(
    uint32_t sbase, const __half* __restrict__ qh, const __half* __restrict__ ql,
    int b, int hd, int kt, int t) {
#pragma unroll
    for (int i = 0; i < 8; ++i) {
        int u = t + i * 256;             // 0..2047
        int sel = u >> 9;                // 0 Kh, 1 Kl, 2 Vh, 3 Vl
        int v = u & 511;
        int row = v >> 3, seg = v & 7;
        const __half* base = (sel & 1) ? ql : qh;
        int off = (sel >> 1) ? 2048 : 1024;
        const __half* src =
            base + ((size_t)((kt * 64 + row) * BBB + b)) * 3072 + off + hd + seg * 8;
        uint32_t dst = sbase + (uint32_t)sel * 9216u + (uint32_t)(row * AROWB + seg * 16);
        CP16(dst, src);
    }
}

__global__ __launch_bounds__(256, 2)
void attn_mma_kernel(const __half* __restrict__ qh, const __half* __restrict__ ql,
                     __half* __restrict__ ctx) {
    extern __shared__ char smem[];
    const uint32_t sb = smem_u32(smem);
    const int t    = threadIdx.x;
    const int lane = t & 31;
    const int w    = t >> 5;
    const int b    = blockIdx.y >> 4;
    const int h    = blockIdx.y & 15;
    const int q0   = blockIdx.x * 128;
    const int hd   = h * DHH;

    // load Q (128 x 64 fp16, single)
#pragma unroll
    for (int i = 0; i < 4; ++i) {
        int u = t + i * 256;
        int row = u >> 3, seg = u & 7;
        const __half* src = qh + ((size_t)((q0 + row) * BBB + b)) * 3072 + hd + seg * 8;
        uint32_t dst = sb + AQ_OFF + (uint32_t)(row * AROWB + seg * 16);
        CP16(dst, src);
    }
    CPCOMMIT();
    attn_load_kv(sb + AST0, qh, ql, b, hd, 0, t);
    CPCOMMIT();

    float Oa[8][4];
#pragma unroll
    for (int j = 0; j < 8; j++)
#pragma unroll
        for (int c = 0; c < 4; c++) Oa[j][c] = 0.f;
    float m0r = -1e30f, m1r = -1e30f, l0r = 0.f, l1r = 0.f;

    const uint32_t arow_off = (uint32_t)((w * 16 + (lane & 15)) * AROWB + (lane >> 4) * 16);
    const uint32_t brow_off = (uint32_t)(((lane & 7) + ((lane & 16) >> 1)) * AROWB +
                                         ((lane >> 3) & 1) * 16);
    const uint32_t vrow_off = (uint32_t)((lane & 15) * AROWB + (lane >> 4) * 16);

    for (int kt = 0; kt < 8; ++kt) {
        CPWAIT(0);
        __syncthreads();
        if (kt + 1 < 8) {
            attn_load_kv(sb + AST0 + (uint32_t)((kt + 1) & 1) * ASTG, qh, ql, b, hd,
                         kt + 1, t);
            CPCOMMIT();
        }
        const uint32_t stg = sb + AST0 + (uint32_t)(kt & 1) * ASTG;

        // ---- S = Q (Kh + Kl)^T : 2 passes, fa shared across passes ----
        float st[8][4];
#pragma unroll
        for (int j = 0; j < 8; j++)
#pragma unroll
            for (int c = 0; c < 4; c++) st[j][c] = 0.f;
#pragma unroll
        for (int kc = 0; kc < 4; ++kc) {
            uint32_t fa[4];
            LDSM4(fa, sb + AQ_OFF + arow_off + kc * 32);
#pragma unroll
            for (int g = 0; g < 4; ++g) {
                uint32_t fbh[4], fbl[4];
                LDSM4(fbh, stg + AKH + brow_off + g * (16 * AROWB) + kc * 32);
                MMA_F16(st[2 * g],     fa, fbh[0], fbh[1]);
                MMA_F16(st[2 * g + 1], fa, fbh[2], fbh[3]);
                LDSM4(fbl, stg + AKL + brow_off + g * (16 * AROWB) + kc * 32);
                MMA_F16(st[2 * g],     fa, fbl[0], fbl[1]);
                MMA_F16(st[2 * g + 1], fa, fbl[2], fbl[3]);
            }
        }

        // ---- online softmax ----
        float mx0 = -1e30f, mx1 = -1e30f;
#pragma unroll
        for (int j = 0; j < 8; j++) {
            st[j][0] *= 0.125f; st[j][1] *= 0.125f;
            st[j][2] *= 0.125f; st[j][3] *= 0.125f;
            mx0 = fmaxf(mx0, fmaxf(st[j][0], st[j][1]));
            mx1 = fmaxf(mx1, fmaxf(st[j][2], st[j][3]));
        }
        mx0 = fmaxf(mx0, __shfl_xor_sync(0xffffffffu, mx0, 1));
        mx0 = fmaxf(mx0, __shfl_xor_sync(0xffffffffu, mx0, 2));
        mx1 = fmaxf(mx1, __shfl_xor_sync(0xffffffffu, mx1, 1));
        mx1 = fmaxf(mx1, __shfl_xor_sync(0xffffffffu, mx1, 2));
        const float nm0 = fmaxf(m0r, mx0), nm1 = fmaxf(m1r, mx1);
        const float al0 = __expf(m0r - nm0), al1 = __expf(m1r - nm1);
        float s0 = 0.f, s1 = 0.f;
#pragma unroll
        for (int j = 0; j < 8; j++) {
            st[j][0] = __expf(st[j][0] - nm0);
            st[j][1] = __expf(st[j][1] - nm0);
            st[j][2] = __expf(st[j][2] - nm1);
            st[j][3] = __expf(st[j][3] - nm1);
            s0 += st[j][0] + st[j][1];
            s1 += st[j][2] + st[j][3];
        }
        s0 += __shfl_xor_sync(0xffffffffu, s0, 1);
        s0 += __shfl_xor_sync(0xffffffffu, s0, 2);
        s1 += __shfl_xor_sync(0xffffffffu, s1, 1);
        s1 += __shfl_xor_sync(0xffffffffu, s1, 2);
        l0r = l0r * al0 + s0;
        l1r = l1r * al1 + s1;
        m0r = nm0; m1r = nm1;
#pragma unroll
        for (int j = 0; j < 8; j++) {
            Oa[j][0] *= al0; Oa[j][1] *= al0;
            Oa[j][2] *= al1; Oa[j][3] *= al1;
        }

        // ---- O += P (Vh + Vl) : P single fp16, 2 passes ----
#pragma unroll
        for (int kc = 0; kc < 4; ++kc) {
            uint32_t ph[4];
            {
                const float* p0 = st[2 * kc];
                const float* p1 = st[2 * kc + 1];
                ph[0] = pack_h2(p0[0], p0[1]);
                ph[1] = pack_h2(p0[2], p0[3]);
                ph[2] = pack_h2(p1[0], p1[1]);
                ph[3] = pack_h2(p1[2], p1[3]);
            }
            const uint32_t vbase = stg + (uint32_t)(kc * 16 * AROWB) + vrow_off;
#pragma unroll
            for (int g = 0; g < 4; ++g) {
                uint32_t fvh[4], fvl[4];
                LDSM4T(fvh, vbase + AVH + g * 32);
                MMA_F16(Oa[2 * g],     ph, fvh[0], fvh[1]);
                MMA_F16(Oa[2 * g + 1], ph, fvh[2], fvh[3]);
                LDSM4T(fvl, vbase + AVL + g * 32);
                MMA_F16(Oa[2 * g],     ph, fvl[0], fvl[1]);
                MMA_F16(Oa[2 * g + 1], ph, fvl[2], fvl[3]);
            }
        }
    }

    // ---- epilogue: ctx (single fp16) ----
    const float inv0 = 1.f / l0r;
    const float inv1 = 1.f / l1r;
    const int r_lo = q0 + w * 16 + (lane >> 2);
    const int col0 = hd + (lane & 3) * 2;
#pragma unroll
    for (int j = 0; j < 8; j++) {
        const int col = col0 + j * 8;
        size_t o0 = ((size_t)(r_lo * BBB + b)) * 1024 + col;
        size_t o1 = ((size_t)((r_lo + 8) * BBB + b)) * 1024 + col;
        *reinterpret_cast<__half2*>(ctx + o0) =
            __halves2half2(__float2half_rn(Oa[j][0] * inv0),
                           __float2half_rn(Oa[j][1] * inv0));
        *reinterpret_cast<__half2*>(ctx + o1) =
            __halves2half2(__float2half_rn(Oa[j][2] * inv1),
                           __float2half_rn(Oa[j][3] * inv1));
    }
}

// ---------------------------------------------------------------------------
// 4) LayerNorm, warp-shuffle reductions (+ fp16 emit)
// ---------------------------------------------------------------------------
__global__ __launch_bounds__(256)
void ln_kernel(const float* __restrict__ a, const float* __restrict__ r,
               const float* __restrict__ g, const float* __restrict__ b,
               float* __restrict__ out, __half* __restrict__ of) {
    __shared__ float red1[8];
    __shared__ float red2[8];
    const int t = threadIdx.x;
    const int lane = t & 31;
    const int w = t >> 5;
    const size_t row = blockIdx.x;
    float4 v = reinterpret_cast<const float4*>(a + row * 1024)[t];
    if (r != nullptr) {
        float4 rv = reinterpret_cast<const float4*>(r + row * 1024)[t];
        v.x += rv.x; v.y += rv.y; v.z += rv.z; v.w += rv.w;
    }
    float s = v.x + v.y + v.z + v.w;
#pragma unroll
    for (int o = 16; o > 0; o >>= 1) s += __shfl_xor_sync(0xffffffffu, s, o);
    if (lane == 0) red1[w] = s;
    __syncthreads();
    float mu = (red1[0] + red1[1] + red1[2] + red1[3] +
                red1[4] + red1[5] + red1[6] + red1[7]) * (1.f / 1024.f);
    float dx = v.x - mu, dy = v.y - mu, dz = v.z - mu, dw = v.w - mu;
    float q = dx * dx + dy * dy + dz * dz + dw * dw;
#pragma unroll
    for (int o = 16; o > 0; o >>= 1) q += __shfl_xor_sync(0xffffffffu, q, o);
    if (lane == 0) red2[w] = q;
    __syncthreads();
    float var = (red2[0] + red2[1] + red2[2] + red2[3] +
                 red2[4] + red2[5] + red2[6] + red2[7]) * (1.f / 1024.f);
    float inv = rsqrtf(var + 1e-5f);
    float4 g4 = reinterpret_cast<const float4*>(g)[t];
    float4 b4 = reinterpret_cast<const float4*>(b)[t];
    float4 o4;
    o4.x = dx * inv * g4.x + b4.x;
    o4.y = dy * inv * g4.y + b4.y;
    o4.z = dz * inv * g4.z + b4.z;
    o4.w = dw * inv * g4.w + b4.w;
    reinterpret_cast<float4*>(out + row * 1024)[t] = o4;
    if (of != nullptr) {
        reinterpret_cast<__half2*>(of + row * 1024)[2 * t] =
            __halves2half2(__float2half_rn(o4.x), __float2half_rn(o4.y));
        reinterpret_cast<__half2*>(of + row * 1024)[2 * t + 1] =
            __halves2half2(__float2half_rn(o4.z), __float2half_rn(o4.w));
    }
}

// ---------------------------------------------------------------------------
// Host orchestration
// ---------------------------------------------------------------------------
extern "C" void kernel_launch(void* const* d_in, const int* in_sizes, int n_in,
                              void* d_out, int out_size) {
    (void)in_sizes; (void)n_in; (void)out_size;
    const float* x    = (const float*)d_in[0];
    const float* Wqkv = (const float*)d_in[1];
    const float* bqkv = (const float*)d_in[2];
    const float* Wo   = (const float*)d_in[3];
    const float* bo   = (const float*)d_in[4];
    const float* W1   = (const float*)d_in[5];
    const float* b1   = (const float*)d_in[6];
    const float* W2   = (const float*)d_in[7];
    const float* b2   = (const float*)d_in[8];
    const float* ln1g = (const float*)d_in[9];
    const float* ln1b = (const float*)d_in[10];
    const float* ln2g = (const float*)d_in[11];
    const float* ln2b = (const float*)d_in[12];
    const float* lnfg = (const float*)d_in[13];
    const float* lnfb = (const float*)d_in[14];
    const float* Wout = (const float*)d_in[15];
    const float* bout = (const float*)d_in[16];
    float* out = (float*)d_out;

    float *h, *tmp, *pe;
    __half *hf, *ff, *qvh, *qvl, *wh, *wl;
    cudaGetSymbolAddress((void**)&h,   g_h);
    cudaGetSymbolAddress((void**)&tmp, g_tmp);
    cudaGetSymbolAddress((void**)&pe,  g_pe);
    cudaGetSymbolAddress((void**)&hf,  g_hf);
    cudaGetSymbolAddress((void**)&ff,  g_ff);
    cudaGetSymbolAddress((void**)&qvh, g_qkvh);
    cudaGetSymbolAddress((void**)&qvl, g_qkvl);
    cudaGetSymbolAddress((void**)&wh,  g_wh);
    cudaGetSymbolAddress((void**)&wl,  g_wl);

    cudaFuncSetAttribute(gemm_mma<0, 0, 0>, cudaFuncAttributeMaxDynamicSharedMemorySize, GEMM_SMEM);
    cudaFuncSetAttribute(gemm_mma<0, 0, 2>, cudaFuncAttributeMaxDynamicSharedMemorySize, GEMM_SMEM);
    cudaFuncSetAttribute(gemm_mma<1, 0, 1>, cudaFuncAttributeMaxDynamicSharedMemorySize, GEMM_SMEM);
    cudaFuncSetAttribute(gemm_mma<0, 1, 0>, cudaFuncAttributeMaxDynamicSharedMemorySize, GEMM_SMEM);
    cudaFuncSetAttribute(attn_mma_kernel, cudaFuncAttributeMaxDynamicSharedMemorySize, ATTN_SMEM);

    cvt_split_all<<<(F4_ALL + 255) / 256, 256>>>(Wqkv, Wo, W1, W2, Wout, wh, wl);
    pe_table_kernel<<<(SSS * DDD) / 256, 256>>>(pe);
    add_pe_kernel<<<(TTT * DDD / 4) / 256, 256>>>(x, pe, h, hf);

    for (int l = 0; l < LLL; l++) {
        const __half* wq_h = wh + OFF_QKV + (size_t)l * 3145728;
        const __half* wq_l = wl + OFF_QKV + (size_t)l * 3145728;
        const __half* wo_h = wh + OFF_WO + (size_t)l * 1048576;
        const __half* wo_l = wl + OFF_WO + (size_t)l * 1048576;
        const __half* w1_h = wh + OFF_W1 + (size_t)l * 2097152;
        const __half* w1_l = wl + OFF_W1 + (size_t)l * 2097152;
        const __half* w2_h = wh + OFF_W2 + (size_t)l * 2097152;
        const __half* w2_l = wl + OFF_W2 + (size_t)l * 2097152;

        // qkv (fp16 hi+lo) = h @ Wqkv^T + bqkv
        gemm_mma<0, 0, 2><<<dim3(3072 / 128, TTT / 128), 256, GEMM_SMEM>>>(
            hf, wq_h, wq_l, bqkv + (size_t)l * 3072, nullptr, qvh, qvl,
            TTT, 3072, 1024);
        // ctx (fp16) = flash attention
        attn_mma_kernel<<<dim3(SSS / 128, BBB * HHH), 256, ATTN_SMEM>>>(qvh, qvl, ff);
        // tmp = ctx @ Wo^T + bo
        gemm_mma<0, 0, 0><<<dim3(1024 / 128, TTT / 128), 256, GEMM_SMEM>>>(
            ff, wo_h, wo_l, bo + (size_t)l * 1024, tmp, nullptr, nullptr,
            TTT, 1024, 1024);
        // h = LN(h + tmp), emit fp16
        ln_kernel<<<TTT, 256>>>(h, tmp, ln1g + (size_t)l * 1024, ln1b + (size_t)l * 1024,
                                h, hf);
        // ff (fp16) = relu(h @ W1^T + b1)
        gemm_mma<1, 0, 1><<<dim3(2048 / 128, TTT / 128), 256, GEMM_SMEM>>>(
            hf, w1_h, w1_l, b1 + (size_t)l * 2048, nullptr, ff, nullptr,
            TTT, 2048, 1024);
        // tmp = ff @ W2^T + b2
        gemm_mma<0, 0, 0><<<dim3(1024 / 128, TTT / 128), 256, GEMM_SMEM>>>(
            ff, w2_h, w2_l, b2 + (size_t)l * 1024, tmp, nullptr, nullptr,
            TTT, 1024, 2048);
        // h = LN(h + ff2), emit fp16
        ln_kernel<<<TTT, 256>>>(h, tmp, ln2g + (size_t)l * 1024, ln2b + (size_t)l * 1024,
                                h, hf);
    }

    ln_kernel<<<TTT, 256>>>(h, nullptr, lnfg, lnfb, h, hf);
    gemm_mma<0, 1, 0><<<dim3(DMEMM / 128, TTT / 128), 256, GEMM_SMEM>>>(
        hf, wh + OFF_WOUT, wl + OFF_WOUT, bout, out, nullptr, nullptr,
        TTT, DMEMM, 1024);
}

// round 8
// speedup vs baseline: 1.4789x; 1.0017x over previous
#include <cuda_runtime.h>
#include <cuda_fp16.h>
#include <math.h>
#include <stdint.h>

// Problem constants
#define BBB 32
#define SSS 512
#define DDD 1024
#define HHH 16
#define DHH 64
#define LLL 4
#define DFFF 2048
#define DMEMM 512
#define TTT (BBB * SSS)   // 16384 tokens

// ---------------------------------------------------------------------------
// Scratch (static device globals)
// ---------------------------------------------------------------------------
__device__ float g_h[(size_t)TTT * DDD];              //  64 MB residual
__device__ float g_tmp[(size_t)TTT * DDD];            //  64 MB
__device__ float g_pe[(size_t)SSS * DDD];             //   2 MB
__device__ __half g_hf[(size_t)TTT * DDD];            //  32 MB activations fp16
__device__ __half g_ff[(size_t)TTT * DFFF];           //  64 MB ctx / ff fp16
__device__ __half g_qkvh[(size_t)TTT * 3 * DDD];      //  96 MB qkv hi
__device__ __half g_qkvl[(size_t)TTT * 3 * DDD];      //  96 MB qkv lo
#define WTOT 34078720ULL
__device__ __half g_wh[WTOT];                         //  68 MB weights hi
__device__ __half g_wl[WTOT];                         //  68 MB weights lo

#define OFF_QKV 0ULL
#define OFF_WO  12582912ULL
#define OFF_W1  16777216ULL
#define OFF_W2  25165824ULL
#define OFF_WOUT 33554432ULL

// ---------------------------------------------------------------------------
// PTX helpers (baseline sm_80+)
// ---------------------------------------------------------------------------
__device__ __forceinline__ uint32_t smem_u32(const void* p) {
    uint32_t a;
    asm("{ .reg .u64 t; cvta.to.shared.u64 t, %1; cvt.u32.u64 %0, t; }" : "=r"(a) : "l"(p));
    return a;
}

#define CP16(saddr, gptr) \
    asm volatile("cp.async.cg.shared.global [%0], [%1], 16;" :: "r"(saddr), "l"(gptr))
#define CPCOMMIT() asm volatile("cp.async.commit_group;" ::: "memory")
#define CPWAIT(n)  asm volatile("cp.async.wait_group %0;" :: "n"(n) : "memory")

#define LDSM4(r, addr)                                                          \
    asm volatile("ldmatrix.sync.aligned.m8n8.x4.shared.b16 {%0,%1,%2,%3}, [%4];" \
        : "=r"((r)[0]), "=r"((r)[1]), "=r"((r)[2]), "=r"((r)[3]) : "r"(addr))

#define LDSM4T(r, addr)                                                          \
    asm volatile("ldmatrix.sync.aligned.m8n8.x4.trans.shared.b16 {%0,%1,%2,%3}, [%4];" \
        : "=r"((r)[0]), "=r"((r)[1]), "=r"((r)[2]), "=r"((r)[3]) : "r"(addr))

#define MMA_F16(d, a, b0v, b1v)                                                 \
    asm volatile("mma.sync.aligned.m16n8k16.row.col.f32.f16.f16.f32 "           \
        "{%0,%1,%2,%3}, {%4,%5,%6,%7}, {%8,%9}, {%0,%1,%2,%3};"                 \
        : "+f"((d)[0]), "+f"((d)[1]), "+f"((d)[2]), "+f"((d)[3])                \
        : "r"((a)[0]), "r"((a)[1]), "r"((a)[2]), "r"((a)[3]), "r"(b0v), "r"(b1v))

#define EX2_H2(d, s) asm("ex2.approx.f16x2 %0, %1;" : "=r"(d) : "r"(s))

__device__ __forceinline__ void split_f16(float v, __half& h, __half& l) {
    h = __float2half_rn(v);
    l = __float2half_rn(v - __half2float(h));
}
// pack (elem0=a, elem1=b) into f16x2
__device__ __forceinline__ uint32_t pack_h2(float a, float b) {
    uint32_t r;
    asm("cvt.rn.f16x2.f32 %0, %1, %2;" : "=r"(r) : "f"(b), "f"(a));
    return r;
}
__device__ __forceinline__ float2 unpack_h2(uint32_t u) {
    __half2 h = *reinterpret_cast<__half2*>(&u);
    return __half22float2(h);
}

// ---------------------------------------------------------------------------
// 0) merged weight split (fp16 hi/lo), one launch
// ---------------------------------------------------------------------------
#define F4_QKV 3145728
#define F4_WO  (F4_QKV + 1048576)
#define F4_W1  (F4_WO + 2097152)
#define F4_W2  (F4_W1 + 2097152)
#define F4_ALL (F4_W2 + 131072)

__global__ __launch_bounds__(256)
void cvt_split_all(const float* __restrict__ Wqkv, const float* __restrict__ Wo,
                   const float* __restrict__ W1, const float* __restrict__ W2,
                   const float* __restrict__ Wout,
                   __half* __restrict__ hi, __half* __restrict__ lo) {
    int i = blockIdx.x * 256 + threadIdx.x;
    if (i >= F4_ALL) return;
    const float* src;
    int li;
    if (i < F4_QKV)      { src = Wqkv; li = i; }
    else if (i < F4_WO)  { src = Wo;   li = i - F4_QKV; }
    else if (i < F4_W1)  { src = W1;   li = i - F4_WO; }
    else if (i < F4_W2)  { src = W2;   li = i - F4_W1; }
    else                 { src = Wout; li = i - F4_W2; }
    float4 v = reinterpret_cast<const float4*>(src)[li];
    __half h0, h1, h2, h3, l0, l1, l2, l3;
    split_f16(v.x, h0, l0); split_f16(v.y, h1, l1);
    split_f16(v.z, h2, l2); split_f16(v.w, h3, l3);
    reinterpret_cast<__half2*>(hi)[2 * i]     = __halves2half2(h0, h1);
    reinterpret_cast<__half2*>(hi)[2 * i + 1] = __halves2half2(h2, h3);
    reinterpret_cast<__half2*>(lo)[2 * i]     = __halves2half2(l0, l1);
    reinterpret_cast<__half2*>(lo)[2 * i + 1] = __halves2half2(l2, l3);
}

// ---------------------------------------------------------------------------
// 1a) PE table
// ---------------------------------------------------------------------------
__global__ __launch_bounds__(256)
void pe_table_kernel(float* __restrict__ pe) {
    int idx = blockIdx.x * 256 + threadIdx.x;
    int d = idx & (DDD - 1);
    int s = idx >> 10;
    float div = expf((float)(d & ~1) * (-9.2103403719761836f / (float)DDD));
    float ang = (float)s * div;
    pe[idx] = (d & 1) ? cosf(ang) : sinf(ang);
}

// ---------------------------------------------------------------------------
// 1b) h[s,b,:] = x[b,s,:] + PE[s,:]   (+ fp16 emit)
// ---------------------------------------------------------------------------
__global__ __launch_bounds__(256)
void add_pe_kernel(const float* __restrict__ x, const float* __restrict__ pe,
                   float* __restrict__ h, __half* __restrict__ hf) {
    int i4 = blockIdx.x * 256 + threadIdx.x;
    int d4  = i4 & 255;
    int row = i4 >> 8;
    int s   = row >> 5;
    int b   = row & 31;
    float4 xv = reinterpret_cast<const float4*>(x)[((size_t)(b * SSS + s) << 8) + d4];
    float4 pv = reinterpret_cast<const float4*>(pe)[((size_t)s << 8) + d4];
    float4 v;
    v.x = xv.x + pv.x; v.y = xv.y + pv.y; v.z = xv.z + pv.z; v.w = xv.w + pv.w;
    reinterpret_cast<float4*>(h)[i4] = v;
    reinterpret_cast<__half2*>(hf)[2 * i4] =
        __halves2half2(__float2half_rn(v.x), __float2half_rn(v.y));
    reinterpret_cast<__half2*>(hf)[2 * i4 + 1] =
        __halves2half2(__float2half_rn(v.z), __float2half_rn(v.w));
}

// ---------------------------------------------------------------------------
// 2) HMMA GEMM, fp16 2-pass: C = A @ (Wh+Wl)^T + bias
//    nj-blocked inner loop (24 live frag regs) for better LDSM/MMA pipelining.
// ---------------------------------------------------------------------------
#define SROWB 80
#define GWH_OFF 10240u
#define GWL_OFF 20480u
#define STAGE_B 30720u
#define GEMM_SMEM (2 * 30720)

template <int PERM>
__device__ __forceinline__ void load_stage(
    uint32_t sbase, const __half* __restrict__ A,
    const __half* __restrict__ Wh, const __half* __restrict__ Wl,
    int m0, int n0, int K, int k0, int t) {
#pragma unroll
    for (int i = 0; i < 6; ++i) {
        int u = t + i * 256;                 // 0..1535
        int sel = u >> 9;                    // 0 A, 1 Wh, 2 Wl
        int v = u & 511;
        int row = v >> 2, c8 = v & 3;
        const __half* src;
        if (sel == 0) {
            int garow = m0 + row;
            if (PERM) garow = ((garow & 511) << 5) | (garow >> 9);
            src = A + (size_t)garow * K + k0 + c8 * 8;
        } else if (sel == 1) {
            src = Wh + (size_t)(n0 + row) * K + k0 + c8 * 8;
        } else {
            src = Wl + (size_t)(n0 + row) * K + k0 + c8 * 8;
        }
        uint32_t dst = sbase + (uint32_t)sel * 10240u + (uint32_t)(row * SROWB + c8 * 16);
        CP16(dst, src);
    }
}

template <int RELU, int PERM, int OUTMODE>
__global__ __launch_bounds__(256, 2)
void gemm_mma(const __half* __restrict__ A,
              const __half* __restrict__ Wh, const __half* __restrict__ Wl,
              const float* __restrict__ bias, float* __restrict__ C,
              __half* __restrict__ Ch, __half* __restrict__ Cl,
              int M, int N, int K) {
    extern __shared__ char smem[];
    const uint32_t sb = smem_u32(smem);
    const int t    = threadIdx.x;
    const int lane = t & 31;
    const int w    = t >> 5;
    const int wm   = w & 1;
    const int wn   = w >> 1;
    const int m0   = blockIdx.y * 128;
    const int n0   = blockIdx.x * 128;

    float acc[4][4][4];
#pragma unroll
    for (int a = 0; a < 4; a++)
#pragma unroll
        for (int b = 0; b < 4; b++)
#pragma unroll
            for (int c = 0; c < 4; c++) acc[a][b][c] = 0.f;

    const uint32_t a_off = (uint32_t)((wm * 64 + (lane & 15)) * SROWB + (lane >> 4) * 16);
    const int brow = wn * 32 + (lane & 7) + ((lane & 16) >> 1);
    const uint32_t b_off = (uint32_t)(brow * SROWB + ((lane >> 3) & 1) * 16);

    const int NC = K >> 5;
    load_stage<PERM>(sb, A, Wh, Wl, m0, n0, K, 0, t);
    CPCOMMIT();

    for (int c = 0; c < NC; ++c) {
        CPWAIT(0);
        __syncthreads();
        if (c + 1 < NC) {
            load_stage<PERM>(sb + (uint32_t)((c + 1) & 1) * STAGE_B,
                             A, Wh, Wl, m0, n0, K, (c + 1) << 5, t);
            CPCOMMIT();
        }
        const uint32_t stb = sb + (uint32_t)(c & 1) * STAGE_B;
#pragma unroll
        for (int ks = 0; ks < 2; ++ks) {
            const uint32_t ao = stb + a_off + ks * 32;
            const uint32_t bo = stb + b_off + ks * 32;
            uint32_t fa[4][4];
#pragma unroll
            for (int mi = 0; mi < 4; ++mi)
                LDSM4(fa[mi], ao + mi * (16 * SROWB));
#pragma unroll
            for (int nj = 0; nj < 2; ++nj) {
                uint32_t fbh[4], fbl[4];
                LDSM4(fbh, bo + GWH_OFF + nj * (16 * SROWB));
                LDSM4(fbl, bo + GWL_OFF + nj * (16 * SROWB));
#pragma unroll
                for (int mi = 0; mi < 4; ++mi) {
                    MMA_F16(acc[mi][2 * nj],     fa[mi], fbh[0], fbh[1]);
                    MMA_F16(acc[mi][2 * nj + 1], fa[mi], fbh[2], fbh[3]);
                    MMA_F16(acc[mi][2 * nj],     fa[mi], fbl[0], fbl[1]);
                    MMA_F16(acc[mi][2 * nj + 1], fa[mi], fbl[2], fbl[3]);
                }
            }
        }
    }

    const int qrow = lane >> 2;
    const int qcol = (lane & 3) * 2;
#pragma unroll
    for (int mi = 0; mi < 4; ++mi) {
        const int row0 = m0 + wm * 64 + mi * 16 + qrow;
#pragma unroll
        for (int ni = 0; ni < 4; ++ni) {
            const int col = n0 + wn * 32 + ni * 8 + qcol;
            const float bb0 = bias[col];
            const float bb1 = bias[col + 1];
            float v00 = acc[mi][ni][0] + bb0;
            float v01 = acc[mi][ni][1] + bb1;
            float v10 = acc[mi][ni][2] + bb0;
            float v11 = acc[mi][ni][3] + bb1;
            if (RELU) {
                v00 = fmaxf(v00, 0.f); v01 = fmaxf(v01, 0.f);
                v10 = fmaxf(v10, 0.f); v11 = fmaxf(v11, 0.f);
            }
            if (OUTMODE == 0) {
                *reinterpret_cast<float2*>(C + (size_t)row0 * N + col) =
                    make_float2(v00, v01);
                *reinterpret_cast<float2*>(C + (size_t)(row0 + 8) * N + col) =
                    make_float2(v10, v11);
            } else if (OUTMODE == 1) {
                *reinterpret_cast<__half2*>(Ch + (size_t)row0 * N + col) =
                    __halves2half2(__float2half_rn(v00), __float2half_rn(v01));
                *reinterpret_cast<__half2*>(Ch + (size_t)(row0 + 8) * N + col) =
                    __halves2half2(__float2half_rn(v10), __float2half_rn(v11));
            } else {
                __half h0, l0, h1, l1;
                split_f16(v00, h0, l0); split_f16(v01, h1, l1);
                *reinterpret_cast<__half2*>(Ch + (size_t)row0 * N + col) = __halves2half2(h0, h1);
                *reinterpret_cast<__half2*>(Cl + (size_t)row0 * N + col) = __halves2half2(l0, l1);
                split_f16(v10, h0, l0); split_f16(v11, h1, l1);
                *reinterpret_cast<__half2*>(Ch + (size_t)(row0 + 8) * N + col) = __halves2half2(h0, h1);
                *reinterpret_cast<__half2*>(Cl + (size_t)(row0 + 8) * N + col) = __halves2half2(l0, l1);
            }
        }
    }
}

// ---------------------------------------------------------------------------
// 3) HMMA flash attention, fp16 2-pass, base-2 softmax with ex2.approx.f16x2
// ---------------------------------------------------------------------------
#define AROWB 144
#define AQ_OFF 0u
#define AST0   18432u
#define ASTG   36864u
#define AKH 0u
#define AKL 9216u
#define AVH 18432u
#define AVL 27648u
#define ATTN_SMEM (18432 + 2 * 36864)
// 0.125 (1/sqrt(64)) * log2(e)
#define C_SCALE 0.18033688011112042f

__device__ __forceinline__ void attn_load_kv(
    uint32_t sbase, const __half* __restrict__ qh, const __half* __restrict__ ql,
    int b, int hd, int kt, int t) {
#pragma unroll
    for (int i = 0; i < 8; ++i) {
        int u = t + i * 256;             // 0..2047
        int sel = u >> 9;                // 0 Kh, 1 Kl, 2 Vh, 3 Vl
        int v = u & 511;
        int row = v >> 3, seg = v & 7;
        const __half* base = (sel & 1) ? ql : qh;
        int off = (sel >> 1) ? 2048 : 1024;
        const __half* src =
            base + ((size_t)((kt * 64 + row) * BBB + b)) * 3072 + off + hd + seg * 8;
        uint32_t dst = sbase + (uint32_t)sel * 9216u + (uint32_t)(row * AROWB + seg * 16);
        CP16(dst, src);
    }
}

__global__ __launch_bounds__(256, 2)
void attn_mma_kernel(const __half* __restrict__ qh, const __half* __restrict__ ql,
                     __half* __restrict__ ctx) {
    extern __shared__ char smem[];
    const uint32_t sb = smem_u32(smem);
    const int t    = threadIdx.x;
    const int lane = t & 31;
    const int w    = t >> 5;
    const int b    = blockIdx.y >> 4;
    const int h    = blockIdx.y & 15;
    const int q0   = blockIdx.x * 128;
    const int hd   = h * DHH;

    // load Q (128 x 64 fp16, single)
#pragma unroll
    for (int i = 0; i < 4; ++i) {
        int u = t + i * 256;
        int row = u >> 3, seg = u & 7;
        const __half* src = qh + ((size_t)((q0 + row) * BBB + b)) * 3072 + hd + seg * 8;
        uint32_t dst = sb + AQ_OFF + (uint32_t)(row * AROWB + seg * 16);
        CP16(dst, src);
    }
    CPCOMMIT();
    attn_load_kv(sb + AST0, qh, ql, b, hd, 0, t);
    CPCOMMIT();

    float Oa[8][4];
#pragma unroll
    for (int j = 0; j < 8; j++)
#pragma unroll
        for (int c = 0; c < 4; c++) Oa[j][c] = 0.f;
    float m0r = -1e30f, m1r = -1e30f, l0r = 0.f, l1r = 0.f;

    const uint32_t arow_off = (uint32_t)((w * 16 + (lane & 15)) * AROWB + (lane >> 4) * 16);
    const uint32_t brow_off = (uint32_t)(((lane & 7) + ((lane & 16) >> 1)) * AROWB +
                                         ((lane >> 3) & 1) * 16);
    const uint32_t vrow_off = (uint32_t)((lane & 15) * AROWB + (lane >> 4) * 16);

    for (int kt = 0; kt < 8; ++kt) {
        CPWAIT(0);
        __syncthreads();
        if (kt + 1 < 8) {
            attn_load_kv(sb + AST0 + (uint32_t)((kt + 1) & 1) * ASTG, qh, ql, b, hd,
                         kt + 1, t);
            CPCOMMIT();
        }
        const uint32_t stg = sb + AST0 + (uint32_t)(kt & 1) * ASTG;

        // ---- S = Q (Kh + Kl)^T : 2 passes ----
        float st[8][4];
#pragma unroll
        for (int j = 0; j < 8; j++)
#pragma unroll
            for (int c = 0; c < 4; c++) st[j][c] = 0.f;
#pragma unroll
        for (int kc = 0; kc < 4; ++kc) {
            uint32_t fa[4];
            LDSM4(fa, sb + AQ_OFF + arow_off + kc * 32);
#pragma unroll
            for (int g = 0; g < 4; ++g) {
                uint32_t fbh[4], fbl[4];
                LDSM4(fbh, stg + AKH + brow_off + g * (16 * AROWB) + kc * 32);
                MMA_F16(st[2 * g],     fa, fbh[0], fbh[1]);
                MMA_F16(st[2 * g + 1], fa, fbh[2], fbh[3]);
                LDSM4(fbl, stg + AKL + brow_off + g * (16 * AROWB) + kc * 32);
                MMA_F16(st[2 * g],     fa, fbl[0], fbl[1]);
                MMA_F16(st[2 * g + 1], fa, fbl[2], fbl[3]);
            }
        }

        // ---- online softmax in base-2 ----
        float mx0 = -1e30f, mx1 = -1e30f;
#pragma unroll
        for (int j = 0; j < 8; j++) {
            st[j][0] *= C_SCALE; st[j][1] *= C_SCALE;
            st[j][2] *= C_SCALE; st[j][3] *= C_SCALE;
            mx0 = fmaxf(mx0, fmaxf(st[j][0], st[j][1]));
            mx1 = fmaxf(mx1, fmaxf(st[j][2], st[j][3]));
        }
        mx0 = fmaxf(mx0, __shfl_xor_sync(0xffffffffu, mx0, 1));
        mx0 = fmaxf(mx0, __shfl_xor_sync(0xffffffffu, mx0, 2));
        mx1 = fmaxf(mx1, __shfl_xor_sync(0xffffffffu, mx1, 1));
        mx1 = fmaxf(mx1, __shfl_xor_sync(0xffffffffu, mx1, 2));
        const float nm0 = fmaxf(m0r, mx0), nm1 = fmaxf(m1r, mx1);
        const float al0 = exp2f(m0r - nm0), al1 = exp2f(m1r - nm1);

        // P = 2^(st - m) packed to fp16 pairs; sums in fp32
        uint32_t pp[8][2];
        float s0 = 0.f, s1 = 0.f;
#pragma unroll
        for (int j = 0; j < 8; j++) {
            uint32_t q0p = pack_h2(st[j][0] - nm0, st[j][1] - nm0);
            uint32_t q1p = pack_h2(st[j][2] - nm1, st[j][3] - nm1);
            EX2_H2(pp[j][0], q0p);
            EX2_H2(pp[j][1], q1p);
            float2 v0 = unpack_h2(pp[j][0]);
            float2 v1 = unpack_h2(pp[j][1]);
            s0 += v0.x + v0.y;
            s1 += v1.x + v1.y;
        }
        s0 += __shfl_xor_sync(0xffffffffu, s0, 1);
        s0 += __shfl_xor_sync(0xffffffffu, s0, 2);
        s1 += __shfl_xor_sync(0xffffffffu, s1, 1);
        s1 += __shfl_xor_sync(0xffffffffu, s1, 2);
        l0r = l0r * al0 + s0;
        l1r = l1r * al1 + s1;
        m0r = nm0; m1r = nm1;
#pragma unroll
        for (int j = 0; j < 8; j++) {
            Oa[j][0] *= al0; Oa[j][1] *= al0;
            Oa[j][2] *= al1; Oa[j][3] *= al1;
        }

        // ---- O += P (Vh + Vl) : P fp16 (from ex2), 2 passes ----
#pragma unroll
        for (int kc = 0; kc < 4; ++kc) {
            uint32_t ph[4];
            ph[0] = pp[2 * kc][0];
            ph[1] = pp[2 * kc][1];
            ph[2] = pp[2 * kc + 1][0];
            ph[3] = pp[2 * kc + 1][1];
            const uint32_t vbase = stg + (uint32_t)(kc * 16 * AROWB) + vrow_off;
#pragma unroll
            for (int g = 0; g < 4; ++g) {
                uint32_t fvh[4], fvl[4];
                LDSM4T(fvh, vbase + AVH + g * 32);
                MMA_F16(Oa[2 * g],     ph, fvh[0], fvh[1]);
                MMA_F16(Oa[2 * g + 1], ph, fvh[2], fvh[3]);
                LDSM4T(fvl, vbase + AVL + g * 32);
                MMA_F16(Oa[2 * g],     ph, fvl[0], fvl[1]);
                MMA_F16(Oa[2 * g + 1], ph, fvl[2], fvl[3]);
            }
        }
    }

    // ---- epilogue: ctx (single fp16) ----
    const float inv0 = 1.f / l0r;
    const float inv1 = 1.f / l1r;
    const int r_lo = q0 + w * 16 + (lane >> 2);
    const int col0 = hd + (lane & 3) * 2;
#pragma unroll
    for (int j = 0; j < 8; j++) {
        const int col = col0 + j * 8;
        size_t o0 = ((size_t)(r_lo * BBB + b)) * 1024 + col;
        size_t o1 = ((size_t)((r_lo + 8) * BBB + b)) * 1024 + col;
        *reinterpret_cast<__half2*>(ctx + o0) =
            __halves2half2(__float2half_rn(Oa[j][0] * inv0),
                           __float2half_rn(Oa[j][1] * inv0));
        *reinterpret_cast<__half2*>(ctx + o1) =
            __halves2half2(__float2half_rn(Oa[j][2] * inv1),
                           __float2half_rn(Oa[j][3] * inv1));
    }
}

// ---------------------------------------------------------------------------
// 4) LayerNorm, warp-shuffle reductions (+ fp16 emit)
// ---------------------------------------------------------------------------
__global__ __launch_bounds__(256)
void ln_kernel(const float* __restrict__ a, const float* __restrict__ r,
               const float* __restrict__ g, const float* __restrict__ b,
               float* __restrict__ out, __half* __restrict__ of) {
    __shared__ float red1[8];
    __shared__ float red2[8];
    const int t = threadIdx.x;
    const int lane = t & 31;
    const int w = t >> 5;
    const size_t row = blockIdx.x;
    float4 v = reinterpret_cast<const float4*>(a + row * 1024)[t];
    if (r != nullptr) {
        float4 rv = reinterpret_cast<const float4*>(r + row * 1024)[t];
        v.x += rv.x; v.y += rv.y; v.z += rv.z; v.w += rv.w;
    }
    float s = v.x + v.y + v.z + v.w;
#pragma unroll
    for (int o = 16; o > 0; o >>= 1) s += __shfl_xor_sync(0xffffffffu, s, o);
    if (lane == 0) red1[w] = s;
    __syncthreads();
    float mu = (red1[0] + red1[1] + red1[2] + red1[3] +
                red1[4] + red1[5] + red1[6] + red1[7]) * (1.f / 1024.f);
    float dx = v.x - mu, dy = v.y - mu, dz = v.z - mu, dw = v.w - mu;
    float q = dx * dx + dy * dy + dz * dz + dw * dw;
#pragma unroll
    for (int o = 16; o > 0; o >>= 1) q += __shfl_xor_sync(0xffffffffu, q, o);
    if (lane == 0) red2[w] = q;
    __syncthreads();
    float var = (red2[0] + red2[1] + red2[2] + red2[3] +
                 red2[4] + red2[5] + red2[6] + red2[7]) * (1.f / 1024.f);
    float inv = rsqrtf(var + 1e-5f);
    float4 g4 = reinterpret_cast<const float4*>(g)[t];
    float4 b4 = reinterpret_cast<const float4*>(b)[t];
    float4 o4;
    o4.x = dx * inv * g4.x + b4.x;
    o4.y = dy * inv * g4.y + b4.y;
    o4.z = dz * inv * g4.z + b4.z;
    o4.w = dw * inv * g4.w + b4.w;
    reinterpret_cast<float4*>(out + row * 1024)[t] = o4;
    if (of != nullptr) {
        reinterpret_cast<__half2*>(of + row * 1024)[2 * t] =
            __halves2half2(__float2half_rn(o4.x), __float2half_rn(o4.y));
        reinterpret_cast<__half2*>(of + row * 1024)[2 * t + 1] =
            __halves2half2(__float2half_rn(o4.z), __float2half_rn(o4.w));
    }
}

// ---------------------------------------------------------------------------
// Host orchestration
// ---------------------------------------------------------------------------
extern "C" void kernel_launch(void* const* d_in, const int* in_sizes, int n_in,
                              void* d_out, int out_size) {
    (void)in_sizes; (void)n_in; (void)out_size;
    const float* x    = (const float*)d_in[0];
    const float* Wqkv = (const float*)d_in[1];
    const float* bqkv = (const float*)d_in[2];
    const float* Wo   = (const float*)d_in[3];
    const float* bo   = (const float*)d_in[4];
    const float* W1   = (const float*)d_in[5];
    const float* b1   = (const float*)d_in[6];
    const float* W2   = (const float*)d_in[7];
    const float* b2   = (const float*)d_in[8];
    const float* ln1g = (const float*)d_in[9];
    const float* ln1b = (const float*)d_in[10];
    const float* ln2g = (const float*)d_in[11];
    const float* ln2b = (const float*)d_in[12];
    const float* lnfg = (const float*)d_in[13];
    const float* lnfb = (const float*)d_in[14];
    const float* Wout = (const float*)d_in[15];
    const float* bout = (const float*)d_in[16];
    float* out = (float*)d_out;

    float *h, *tmp, *pe;
    __half *hf, *ff, *qvh, *qvl, *wh, *wl;
    cudaGetSymbolAddress((void**)&h,   g_h);
    cudaGetSymbolAddress((void**)&tmp, g_tmp);
    cudaGetSymbolAddress((void**)&pe,  g_pe);
    cudaGetSymbolAddress((void**)&hf,  g_hf);
    cudaGetSymbolAddress((void**)&ff,  g_ff);
    cudaGetSymbolAddress((void**)&qvh, g_qkvh);
    cudaGetSymbolAddress((void**)&qvl, g_qkvl);
    cudaGetSymbolAddress((void**)&wh,  g_wh);
    cudaGetSymbolAddress((void**)&wl,  g_wl);

    cudaFuncSetAttribute(gemm_mma<0, 0, 0>, cudaFuncAttributeMaxDynamicSharedMemorySize, GEMM_SMEM);
    cudaFuncSetAttribute(gemm_mma<0, 0, 2>, cudaFuncAttributeMaxDynamicSharedMemorySize, GEMM_SMEM);
    cudaFuncSetAttribute(gemm_mma<1, 0, 1>, cudaFuncAttributeMaxDynamicSharedMemorySize, GEMM_SMEM);
    cudaFuncSetAttribute(gemm_mma<0, 1, 0>, cudaFuncAttributeMaxDynamicSharedMemorySize, GEMM_SMEM);
    cudaFuncSetAttribute(attn_mma_kernel, cudaFuncAttributeMaxDynamicSharedMemorySize, ATTN_SMEM);

    cvt_split_all<<<(F4_ALL + 255) / 256, 256>>>(Wqkv, Wo, W1, W2, Wout, wh, wl);
    pe_table_kernel<<<(SSS * DDD) / 256, 256>>>(pe);
    add_pe_kernel<<<(TTT * DDD / 4) / 256, 256>>>(x, pe, h, hf);

    for (int l = 0; l < LLL; l++) {
        const __half* wq_h = wh + OFF_QKV + (size_t)l * 3145728;
        const __half* wq_l = wl + OFF_QKV + (size_t)l * 3145728;
        const __half* wo_h = wh + OFF_WO + (size_t)l * 1048576;
        const __half* wo_l = wl + OFF_WO + (size_t)l * 1048576;
        const __half* w1_h = wh + OFF_W1 + (size_t)l * 2097152;
        const __half* w1_l = wl + OFF_W1 + (size_t)l * 2097152;
        const __half* w2_h = wh + OFF_W2 + (size_t)l * 2097152;
        const __half* w2_l = wl + OFF_W2 + (size_t)l * 2097152;

        // qkv (fp16 hi+lo) = h @ Wqkv^T + bqkv
        gemm_mma<0, 0, 2><<<dim3(3072 / 128, TTT / 128), 256, GEMM_SMEM>>>(
            hf, wq_h, wq_l, bqkv + (size_t)l * 3072, nullptr, qvh, qvl,
            TTT, 3072, 1024);
        // ctx (fp16) = flash attention
        attn_mma_kernel<<<dim3(SSS / 128, BBB * HHH), 256, ATTN_SMEM>>>(qvh, qvl, ff);
        // tmp = ctx @ Wo^T + bo
        gemm_mma<0, 0, 0><<<dim3(1024 / 128, TTT / 128), 256, GEMM_SMEM>>>(
            ff, wo_h, wo_l, bo + (size_t)l * 1024, tmp, nullptr, nullptr,
            TTT, 1024, 1024);
        // h = LN(h + tmp), emit fp16
        ln_kernel<<<TTT, 256>>>(h, tmp, ln1g + (size_t)l * 1024, ln1b + (size_t)l * 1024,
                                h, hf);
        // ff (fp16) = relu(h @ W1^T + b1)
        gemm_mma<1, 0, 1><<<dim3(2048 / 128, TTT / 128), 256, GEMM_SMEM>>>(
            hf, w1_h, w1_l, b1 + (size_t)l * 2048, nullptr, ff, nullptr,
            TTT, 2048, 1024);
        // tmp = ff @ W2^T + b2
        gemm_mma<0, 0, 0><<<dim3(1024 / 128, TTT / 128), 256, GEMM_SMEM>>>(
            ff, w2_h, w2_l, b2 + (size_t)l * 1024, tmp, nullptr, nullptr,
            TTT, 1024, 2048);
        // h = LN(h + ff2), emit fp16
        ln_kernel<<<TTT, 256>>>(h, tmp, ln2g + (size_t)l * 1024, ln2b + (size_t)l * 1024,
                                h, hf);
    }

    ln_kernel<<<TTT, 256>>>(h, nullptr, lnfg, lnfb, h, hf);
    gemm_mma<0, 1, 0><<<dim3(DMEMM / 128, TTT / 128), 256, GEMM_SMEM>>>(
        hf, wh + OFF_WOUT, wl + OFF_WOUT, bout, out, nullptr, nullptr,
        TTT, DMEMM, 1024);
}

// round 9
// speedup vs baseline: 1.6717x; 1.1304x over previous
#include <cuda_runtime.h>
#include <cuda_fp16.h>
#include <math.h>
#include <stdint.h>

// Problem constants
#define BBB 32
#define SSS 512
#define DDD 1024
#define HHH 16
#define DHH 64
#define LLL 4
#define DFFF 2048
#define DMEMM 512
#define TTT (BBB * SSS)   // 16384 tokens

// ---------------------------------------------------------------------------
// Scratch (static device globals)
// ---------------------------------------------------------------------------
__device__ float g_h[(size_t)TTT * DDD];              //  64 MB residual
__device__ float g_tmp[(size_t)TTT * DDD];            //  64 MB
__device__ float g_pe[(size_t)SSS * DDD];             //   2 MB
__device__ __half g_hf[(size_t)TTT * DDD];            //  32 MB activations fp16
__device__ __half g_ff[(size_t)TTT * DFFF];           //  64 MB ctx / ff fp16
__device__ __half g_qkvh[(size_t)TTT * 3 * DDD];      //  96 MB qkv hi
__device__ __half g_qkvl[(size_t)TTT * 3 * DDD];      //  96 MB qkv lo
#define WTOT 34078720ULL
__device__ __half g_wh[WTOT];                         //  68 MB weights hi
__device__ __half g_wl[WTOT];                         //  68 MB weights lo

#define OFF_QKV 0ULL
#define OFF_WO  12582912ULL
#define OFF_W1  16777216ULL
#define OFF_W2  25165824ULL
#define OFF_WOUT 33554432ULL

// ---------------------------------------------------------------------------
// PTX helpers (baseline sm_80+)
// ---------------------------------------------------------------------------
__device__ __forceinline__ uint32_t smem_u32(const void* p) {
    uint32_t a;
    asm("{ .reg .u64 t; cvta.to.shared.u64 t, %1; cvt.u32.u64 %0, t; }" : "=r"(a) : "l"(p));
    return a;
}

#define CP16(saddr, gptr) \
    asm volatile("cp.async.cg.shared.global [%0], [%1], 16;" :: "r"(saddr), "l"(gptr))
#define CPCOMMIT() asm volatile("cp.async.commit_group;" ::: "memory")
#define CPWAIT(n)  asm volatile("cp.async.wait_group %0;" :: "n"(n) : "memory")

#define LDSM4(r, addr)                                                          \
    asm volatile("ldmatrix.sync.aligned.m8n8.x4.shared.b16 {%0,%1,%2,%3}, [%4];" \
        : "=r"((r)[0]), "=r"((r)[1]), "=r"((r)[2]), "=r"((r)[3]) : "r"(addr))

#define LDSM4T(r, addr)                                                          \
    asm volatile("ldmatrix.sync.aligned.m8n8.x4.trans.shared.b16 {%0,%1,%2,%3}, [%4];" \
        : "=r"((r)[0]), "=r"((r)[1]), "=r"((r)[2]), "=r"((r)[3]) : "r"(addr))

#define MMA_F16(d, a, b0v, b1v)                                                 \
    asm volatile("mma.sync.aligned.m16n8k16.row.col.f32.f16.f16.f32 "           \
        "{%0,%1,%2,%3}, {%4,%5,%6,%7}, {%8,%9}, {%0,%1,%2,%3};"                 \
        : "+f"((d)[0]), "+f"((d)[1]), "+f"((d)[2]), "+f"((d)[3])                \
        : "r"((a)[0]), "r"((a)[1]), "r"((a)[2]), "r"((a)[3]), "r"(b0v), "r"(b1v))

#define EX2_H2(d, s) asm("ex2.approx.f16x2 %0, %1;" : "=r"(d) : "r"(s))

__device__ __forceinline__ void split_f16(float v, __half& h, __half& l) {
    h = __float2half_rn(v);
    l = __float2half_rn(v - __half2float(h));
}
__device__ __forceinline__ uint32_t pack_h2(float a, float b) {
    uint32_t r;
    asm("cvt.rn.f16x2.f32 %0, %1, %2;" : "=r"(r) : "f"(b), "f"(a));
    return r;
}
__device__ __forceinline__ float2 unpack_h2(uint32_t u) {
    __half2 h = *reinterpret_cast<__half2*>(&u);
    return __half22float2(h);
}

// ---------------------------------------------------------------------------
// 0) merged weight split (fp16 hi/lo), one launch
// ---------------------------------------------------------------------------
#define F4_QKV 3145728
#define F4_WO  (F4_QKV + 1048576)
#define F4_W1  (F4_WO + 2097152)
#define F4_W2  (F4_W1 + 2097152)
#define F4_ALL (F4_W2 + 131072)

__global__ __launch_bounds__(256)
void cvt_split_all(const float* __restrict__ Wqkv, const float* __restrict__ Wo,
                   const float* __restrict__ W1, const float* __restrict__ W2,
                   const float* __restrict__ Wout,
                   __half* __restrict__ hi, __half* __restrict__ lo) {
    int i = blockIdx.x * 256 + threadIdx.x;
    if (i >= F4_ALL) return;
    const float* src;
    int li;
    if (i < F4_QKV)      { src = Wqkv; li = i; }
    else if (i < F4_WO)  { src = Wo;   li = i - F4_QKV; }
    else if (i < F4_W1)  { src = W1;   li = i - F4_WO; }
    else if (i < F4_W2)  { src = W2;   li = i - F4_W1; }
    else                 { src = Wout; li = i - F4_W2; }
    float4 v = reinterpret_cast<const float4*>(src)[li];
    __half h0, h1, h2, h3, l0, l1, l2, l3;
    split_f16(v.x, h0, l0); split_f16(v.y, h1, l1);
    split_f16(v.z, h2, l2); split_f16(v.w, h3, l3);
    reinterpret_cast<__half2*>(hi)[2 * i]     = __halves2half2(h0, h1);
    reinterpret_cast<__half2*>(hi)[2 * i + 1] = __halves2half2(h2, h3);
    reinterpret_cast<__half2*>(lo)[2 * i]     = __halves2half2(l0, l1);
    reinterpret_cast<__half2*>(lo)[2 * i + 1] = __halves2half2(l2, l3);
}

// ---------------------------------------------------------------------------
// 1a) PE table
// ---------------------------------------------------------------------------
__global__ __launch_bounds__(256)
void pe_table_kernel(float* __restrict__ pe) {
    int idx = blockIdx.x * 256 + threadIdx.x;
    int d = idx & (DDD - 1);
    int s = idx >> 10;
    float div = expf((float)(d & ~1) * (-9.2103403719761836f / (float)DDD));
    float ang = (float)s * div;
    pe[idx] = (d & 1) ? cosf(ang) : sinf(ang);
}

// ---------------------------------------------------------------------------
// 1b) h[s,b,:] = x[b,s,:] + PE[s,:]   (+ fp16 emit)
// ---------------------------------------------------------------------------
__global__ __launch_bounds__(256)
void add_pe_kernel(const float* __restrict__ x, const float* __restrict__ pe,
                   float* __restrict__ h, __half* __restrict__ hf) {
    int i4 = blockIdx.x * 256 + threadIdx.x;
    int d4  = i4 & 255;
    int row = i4 >> 8;
    int s   = row >> 5;
    int b   = row & 31;
    float4 xv = reinterpret_cast<const float4*>(x)[((size_t)(b * SSS + s) << 8) + d4];
    float4 pv = reinterpret_cast<const float4*>(pe)[((size_t)s << 8) + d4];
    float4 v;
    v.x = xv.x + pv.x; v.y = xv.y + pv.y; v.z = xv.z + pv.z; v.w = xv.w + pv.w;
    reinterpret_cast<float4*>(h)[i4] = v;
    reinterpret_cast<__half2*>(hf)[2 * i4] =
        __halves2half2(__float2half_rn(v.x), __float2half_rn(v.y));
    reinterpret_cast<__half2*>(hf)[2 * i4 + 1] =
        __halves2half2(__float2half_rn(v.z), __float2half_rn(v.w));
}

// ---------------------------------------------------------------------------
// 2) HMMA GEMM, fp16: C = A @ (Wh [+ Wl])^T + bias
//    TWOPASS=1: compensated 2-pass weights; TWOPASS=0: single pass.
// ---------------------------------------------------------------------------
#define SROWB 80
#define GWH_OFF 10240u
#define GWL_OFF 20480u
#define STAGE_B 30720u
#define GEMM_SMEM (2 * 30720)

template <int PERM, int TWOPASS>
__device__ __forceinline__ void load_stage(
    uint32_t sbase, const __half* __restrict__ A,
    const __half* __restrict__ Wh, const __half* __restrict__ Wl,
    int m0, int n0, int K, int k0, int t) {
#pragma unroll
    for (int i = 0; i < (TWOPASS ? 6 : 4); ++i) {
        int u = t + i * 256;                 // 0..1535 (or 0..1023)
        int sel = u >> 9;                    // 0 A, 1 Wh, 2 Wl
        int v = u & 511;
        int row = v >> 2, c8 = v & 3;
        const __half* src;
        if (sel == 0) {
            int garow = m0 + row;
            if (PERM) garow = ((garow & 511) << 5) | (garow >> 9);
            src = A + (size_t)garow * K + k0 + c8 * 8;
        } else if (sel == 1) {
            src = Wh + (size_t)(n0 + row) * K + k0 + c8 * 8;
        } else {
            src = Wl + (size_t)(n0 + row) * K + k0 + c8 * 8;
        }
        uint32_t dst = sbase + (uint32_t)sel * 10240u + (uint32_t)(row * SROWB + c8 * 16);
        CP16(dst, src);
    }
}

template <int RELU, int PERM, int OUTMODE, int TWOPASS>
__global__ __launch_bounds__(256, 2)
void gemm_mma(const __half* __restrict__ A,
              const __half* __restrict__ Wh, const __half* __restrict__ Wl,
              const float* __restrict__ bias, float* __restrict__ C,
              __half* __restrict__ Ch, __half* __restrict__ Cl,
              int M, int N, int K) {
    extern __shared__ char smem[];
    const uint32_t sb = smem_u32(smem);
    const int t    = threadIdx.x;
    const int lane = t & 31;
    const int w    = t >> 5;
    const int wm   = w & 1;
    const int wn   = w >> 1;
    const int m0   = blockIdx.y * 128;
    const int n0   = blockIdx.x * 128;

    float acc[4][4][4];
#pragma unroll
    for (int a = 0; a < 4; a++)
#pragma unroll
        for (int b = 0; b < 4; b++)
#pragma unroll
            for (int c = 0; c < 4; c++) acc[a][b][c] = 0.f;

    const uint32_t a_off = (uint32_t)((wm * 64 + (lane & 15)) * SROWB + (lane >> 4) * 16);
    const int brow = wn * 32 + (lane & 7) + ((lane & 16) >> 1);
    const uint32_t b_off = (uint32_t)(brow * SROWB + ((lane >> 3) & 1) * 16);

    const int NC = K >> 5;
    load_stage<PERM, TWOPASS>(sb, A, Wh, Wl, m0, n0, K, 0, t);
    CPCOMMIT();

    for (int c = 0; c < NC; ++c) {
        CPWAIT(0);
        __syncthreads();
        if (c + 1 < NC) {
            load_stage<PERM, TWOPASS>(sb + (uint32_t)((c + 1) & 1) * STAGE_B,
                                      A, Wh, Wl, m0, n0, K, (c + 1) << 5, t);
            CPCOMMIT();
        }
        const uint32_t stb = sb + (uint32_t)(c & 1) * STAGE_B;
#pragma unroll
        for (int ks = 0; ks < 2; ++ks) {
            const uint32_t ao = stb + a_off + ks * 32;
            const uint32_t bo = stb + b_off + ks * 32;
            uint32_t fa[4][4];
#pragma unroll
            for (int mi = 0; mi < 4; ++mi)
                LDSM4(fa[mi], ao + mi * (16 * SROWB));
#pragma unroll
            for (int nj = 0; nj < 2; ++nj) {
                uint32_t fbh[4];
                LDSM4(fbh, bo + GWH_OFF + nj * (16 * SROWB));
#pragma unroll
                for (int mi = 0; mi < 4; ++mi) {
                    MMA_F16(acc[mi][2 * nj],     fa[mi], fbh[0], fbh[1]);
                    MMA_F16(acc[mi][2 * nj + 1], fa[mi], fbh[2], fbh[3]);
                }
                if (TWOPASS) {
                    uint32_t fbl[4];
                    LDSM4(fbl, bo + GWL_OFF + nj * (16 * SROWB));
#pragma unroll
                    for (int mi = 0; mi < 4; ++mi) {
                        MMA_F16(acc[mi][2 * nj],     fa[mi], fbl[0], fbl[1]);
                        MMA_F16(acc[mi][2 * nj + 1], fa[mi], fbl[2], fbl[3]);
                    }
                }
            }
        }
    }

    const int qrow = lane >> 2;
    const int qcol = (lane & 3) * 2;
#pragma unroll
    for (int mi = 0; mi < 4; ++mi) {
        const int row0 = m0 + wm * 64 + mi * 16 + qrow;
#pragma unroll
        for (int ni = 0; ni < 4; ++ni) {
            const int col = n0 + wn * 32 + ni * 8 + qcol;
            const float bb0 = bias[col];
            const float bb1 = bias[col + 1];
            float v00 = acc[mi][ni][0] + bb0;
            float v01 = acc[mi][ni][1] + bb1;
            float v10 = acc[mi][ni][2] + bb0;
            float v11 = acc[mi][ni][3] + bb1;
            if (RELU) {
                v00 = fmaxf(v00, 0.f); v01 = fmaxf(v01, 0.f);
                v10 = fmaxf(v10, 0.f); v11 = fmaxf(v11, 0.f);
            }
            if (OUTMODE == 0) {
                *reinterpret_cast<float2*>(C + (size_t)row0 * N + col) =
                    make_float2(v00, v01);
                *reinterpret_cast<float2*>(C + (size_t)(row0 + 8) * N + col) =
                    make_float2(v10, v11);
            } else if (OUTMODE == 1) {
                *reinterpret_cast<__half2*>(Ch + (size_t)row0 * N + col) =
                    __halves2half2(__float2half_rn(v00), __float2half_rn(v01));
                *reinterpret_cast<__half2*>(Ch + (size_t)(row0 + 8) * N + col) =
                    __halves2half2(__float2half_rn(v10), __float2half_rn(v11));
            } else {
                __half h0, l0, h1, l1;
                split_f16(v00, h0, l0); split_f16(v01, h1, l1);
                *reinterpret_cast<__half2*>(Ch + (size_t)row0 * N + col) = __halves2half2(h0, h1);
                *reinterpret_cast<__half2*>(Cl + (size_t)row0 * N + col) = __halves2half2(l0, l1);
                split_f16(v10, h0, l0); split_f16(v11, h1, l1);
                *reinterpret_cast<__half2*>(Ch + (size_t)(row0 + 8) * N + col) = __halves2half2(h0, h1);
                *reinterpret_cast<__half2*>(Cl + (size_t)(row0 + 8) * N + col) = __halves2half2(l0, l1);
            }
        }
    }
}

// ---------------------------------------------------------------------------
// 3) HMMA flash attention, fp16 2-pass, base-2 softmax with ex2.approx.f16x2
// ---------------------------------------------------------------------------
#define AROWB 144
#define AQ_OFF 0u
#define AST0   18432u
#define ASTG   36864u
#define AKH 0u
#define AKL 9216u
#define AVH 18432u
#define AVL 27648u
#define ATTN_SMEM (18432 + 2 * 36864)
// 0.125 (1/sqrt(64)) * log2(e)
#define C_SCALE 0.18033688011112042f

__device__ __forceinline__ void attn_load_kv(
    uint32_t sbase, const __half* __restrict__ qh, const __half* __restrict__ ql,
    int b, int hd, int kt, int t) {
#pragma unroll
    for (int i = 0; i < 8; ++i) {
        int u = t + i * 256;             // 0..2047
        int sel = u >> 9;                // 0 Kh, 1 Kl, 2 Vh, 3 Vl
        int v = u & 511;
        int row = v >> 3, seg = v & 7;
        const __half* base = (sel & 1) ? ql : qh;
        int off = (sel >> 1) ? 2048 : 1024;
        const __half* src =
            base + ((size_t)((kt * 64 + row) * BBB + b)) * 3072 + off + hd + seg * 8;
        uint32_t dst = sbase + (uint32_t)sel * 9216u + (uint32_t)(row * AROWB + seg * 16);
        CP16(dst, src);
    }
}

__global__ __launch_bounds__(256, 2)
void attn_mma_kernel(const __half* __restrict__ qh, const __half* __restrict__ ql,
                     __half* __restrict__ ctx) {
    extern __shared__ char smem[];
    const uint32_t sb = smem_u32(smem);
    const int t    = threadIdx.x;
    const int lane = t & 31;
    const int w    = t >> 5;
    const int b    = blockIdx.y >> 4;
    const int h    = blockIdx.y & 15;
    const int q0   = blockIdx.x * 128;
    const int hd   = h * DHH;

    // load Q (128 x 64 fp16, single)
#pragma unroll
    for (int i = 0; i < 4; ++i) {
        int u = t + i * 256;
        int row = u >> 3, seg = u & 7;
        const __half* src = qh + ((size_t)((q0 + row) * BBB + b)) * 3072 + hd + seg * 8;
        uint32_t dst = sb + AQ_OFF + (uint32_t)(row * AROWB + seg * 16);
        CP16(dst, src);
    }
    CPCOMMIT();
    attn_load_kv(sb + AST0, qh, ql, b, hd, 0, t);
    CPCOMMIT();

    float Oa[8][4];
#pragma unroll
    for (int j = 0; j < 8; j++)
#pragma unroll
        for (int c = 0; c < 4; c++) Oa[j][c] = 0.f;
    float m0r = -1e30f, m1r = -1e30f, l0r = 0.f, l1r = 0.f;

    const uint32_t arow_off = (uint32_t)((w * 16 + (lane & 15)) * AROWB + (lane >> 4) * 16);
    const uint32_t brow_off = (uint32_t)(((lane & 7) + ((lane & 16) >> 1)) * AROWB +
                                         ((lane >> 3) & 1) * 16);
    const uint32_t vrow_off = (uint32_t)((lane & 15) * AROWB + (lane >> 4) * 16);

    for (int kt = 0; kt < 8; ++kt) {
        CPWAIT(0);
        __syncthreads();
        if (kt + 1 < 8) {
            attn_load_kv(sb + AST0 + (uint32_t)((kt + 1) & 1) * ASTG, qh, ql, b, hd,
                         kt + 1, t);
            CPCOMMIT();
        }
        const uint32_t stg = sb + AST0 + (uint32_t)(kt & 1) * ASTG;

        // ---- S = Q (Kh + Kl)^T : 2 passes ----
        float st[8][4];
#pragma unroll
        for (int j = 0; j < 8; j++)
#pragma unroll
            for (int c = 0; c < 4; c++) st[j][c] = 0.f;
#pragma unroll
        for (int kc = 0; kc < 4; ++kc) {
            uint32_t fa[4];
            LDSM4(fa, sb + AQ_OFF + arow_off + kc * 32);
#pragma unroll
            for (int g = 0; g < 4; ++g) {
                uint32_t fbh[4], fbl[4];
                LDSM4(fbh, stg + AKH + brow_off + g * (16 * AROWB) + kc * 32);
                MMA_F16(st[2 * g],     fa, fbh[0], fbh[1]);
                MMA_F16(st[2 * g + 1], fa, fbh[2], fbh[3]);
                LDSM4(fbl, stg + AKL + brow_off + g * (16 * AROWB) + kc * 32);
                MMA_F16(st[2 * g],     fa, fbl[0], fbl[1]);
                MMA_F16(st[2 * g + 1], fa, fbl[2], fbl[3]);
            }
        }

        // ---- online softmax in base-2 ----
        float mx0 = -1e30f, mx1 = -1e30f;
#pragma unroll
        for (int j = 0; j < 8; j++) {
            st[j][0] *= C_SCALE; st[j][1] *= C_SCALE;
            st[j][2] *= C_SCALE; st[j][3] *= C_SCALE;
            mx0 = fmaxf(mx0, fmaxf(st[j][0], st[j][1]));
            mx1 = fmaxf(mx1, fmaxf(st[j][2], st[j][3]));
        }
        mx0 = fmaxf(mx0, __shfl_xor_sync(0xffffffffu, mx0, 1));
        mx0 = fmaxf(mx0, __shfl_xor_sync(0xffffffffu, mx0, 2));
        mx1 = fmaxf(mx1, __shfl_xor_sync(0xffffffffu, mx1, 1));
        mx1 = fmaxf(mx1, __shfl_xor_sync(0xffffffffu, mx1, 2));
        const float nm0 = fmaxf(m0r, mx0), nm1 = fmaxf(m1r, mx1);
        const float al0 = exp2f(m0r - nm0), al1 = exp2f(m1r - nm1);

        uint32_t pp[8][2];
        float s0 = 0.f, s1 = 0.f;
#pragma unroll
        for (int j = 0; j < 8; j++) {
            uint32_t q0p = pack_h2(st[j][0] - nm0, st[j][1] - nm0);
            uint32_t q1p = pack_h2(st[j][2] - nm1, st[j][3] - nm1);
            EX2_H2(pp[j][0], q0p);
            EX2_H2(pp[j][1], q1p);
            float2 v0 = unpack_h2(pp[j][0]);
            float2 v1 = unpack_h2(pp[j][1]);
            s0 += v0.x + v0.y;
            s1 += v1.x + v1.y;
        }
        s0 += __shfl_xor_sync(0xffffffffu, s0, 1);
        s0 += __shfl_xor_sync(0xffffffffu, s0, 2);
        s1 += __shfl_xor_sync(0xffffffffu, s1, 1);
        s1 += __shfl_xor_sync(0xffffffffu, s1, 2);
        l0r = l0r * al0 + s0;
        l1r = l1r * al1 + s1;
        m0r = nm0; m1r = nm1;
#pragma unroll
        for (int j = 0; j < 8; j++) {
            Oa[j][0] *= al0; Oa[j][1] *= al0;
            Oa[j][2] *= al1; Oa[j][3] *= al1;
        }

        // ---- O += P (Vh + Vl) ----
#pragma unroll
        for (int kc = 0; kc < 4; ++kc) {
            uint32_t ph[4];
            ph[0] = pp[2 * kc][0];
            ph[1] = pp[2 * kc][1];
            ph[2] = pp[2 * kc + 1][0];
            ph[3] = pp[2 * kc + 1][1];
            const uint32_t vbase = stg + (uint32_t)(kc * 16 * AROWB) + vrow_off;
#pragma unroll
            for (int g = 0; g < 4; ++g) {
                uint32_t fvh[4], fvl[4];
                LDSM4T(fvh, vbase + AVH + g * 32);
                MMA_F16(Oa[2 * g],     ph, fvh[0], fvh[1]);
                MMA_F16(Oa[2 * g + 1], ph, fvh[2], fvh[3]);
                LDSM4T(fvl, vbase + AVL + g * 32);
                MMA_F16(Oa[2 * g],     ph, fvl[0], fvl[1]);
                MMA_F16(Oa[2 * g + 1], ph, fvl[2], fvl[3]);
            }
        }
    }

    // ---- epilogue: ctx (single fp16) ----
    const float inv0 = 1.f / l0r;
    const float inv1 = 1.f / l1r;
    const int r_lo = q0 + w * 16 + (lane >> 2);
    const int col0 = hd + (lane & 3) * 2;
#pragma unroll
    for (int j = 0; j < 8; j++) {
        const int col = col0 + j * 8;
        size_t o0 = ((size_t)(r_lo * BBB + b)) * 1024 + col;
        size_t o1 = ((size_t)((r_lo + 8) * BBB + b)) * 1024 + col;
        *reinterpret_cast<__half2*>(ctx + o0) =
            __halves2half2(__float2half_rn(Oa[j][0] * inv0),
                           __float2half_rn(Oa[j][1] * inv0));
        *reinterpret_cast<__half2*>(ctx + o1) =
            __halves2half2(__float2half_rn(Oa[j][2] * inv1),
                           __float2half_rn(Oa[j][3] * inv1));
    }
}

// ---------------------------------------------------------------------------
// 4) LayerNorm, warp-shuffle reductions (+ fp16 emit)
// ---------------------------------------------------------------------------
__global__ __launch_bounds__(256)
void ln_kernel(const float* __restrict__ a, const float* __restrict__ r,
               const float* __restrict__ g, const float* __restrict__ b,
               float* __restrict__ out, __half* __restrict__ of) {
    __shared__ float red1[8];
    __shared__ float red2[8];
    const int t = threadIdx.x;
    const int lane = t & 31;
    const int w = t >> 5;
    const size_t row = blockIdx.x;
    float4 v = reinterpret_cast<const float4*>(a + row * 1024)[t];
    if (r != nullptr) {
        float4 rv = reinterpret_cast<const float4*>(r + row * 1024)[t];
        v.x += rv.x; v.y += rv.y; v.z += rv.z; v.w += rv.w;
    }
    float s = v.x + v.y + v.z + v.w;
#pragma unroll
    for (int o = 16; o > 0; o >>= 1) s += __shfl_xor_sync(0xffffffffu, s, o);
    if (lane == 0) red1[w] = s;
    __syncthreads();
    float mu = (red1[0] + red1[1] + red1[2] + red1[3] +
                red1[4] + red1[5] + red1[6] + red1[7]) * (1.f / 1024.f);
    float dx = v.x - mu, dy = v.y - mu, dz = v.z - mu, dw = v.w - mu;
    float q = dx * dx + dy * dy + dz * dz + dw * dw;
#pragma unroll
    for (int o = 16; o > 0; o >>= 1) q += __shfl_xor_sync(0xffffffffu, q, o);
    if (lane == 0) red2[w] = q;
    __syncthreads();
    float var = (red2[0] + red2[1] + red2[2] + red2[3] +
                 red2[4] + red2[5] + red2[6] + red2[7]) * (1.f / 1024.f);
    float inv = rsqrtf(var + 1e-5f);
    float4 g4 = reinterpret_cast<const float4*>(g)[t];
    float4 b4 = reinterpret_cast<const float4*>(b)[t];
    float4 o4;
    o4.x = dx * inv * g4.x + b4.x;
    o4.y = dy * inv * g4.y + b4.y;
    o4.z = dz * inv * g4.z + b4.z;
    o4.w = dw * inv * g4.w + b4.w;
    reinterpret_cast<float4*>(out + row * 1024)[t] = o4;
    if (of != nullptr) {
        reinterpret_cast<__half2*>(of + row * 1024)[2 * t] =
            __halves2half2(__float2half_rn(o4.x), __float2half_rn(o4.y));
        reinterpret_cast<__half2*>(of + row * 1024)[2 * t + 1] =
            __halves2half2(__float2half_rn(o4.z), __float2half_rn(o4.w));
    }
}

// ---------------------------------------------------------------------------
// Host orchestration
// ---------------------------------------------------------------------------
extern "C" void kernel_launch(void* const* d_in, const int* in_sizes, int n_in,
                              void* d_out, int out_size) {
    (void)in_sizes; (void)n_in; (void)out_size;
    const float* x    = (const float*)d_in[0];
    const float* Wqkv = (const float*)d_in[1];
    const float* bqkv = (const float*)d_in[2];
    const float* Wo   = (const float*)d_in[3];
    const float* bo   = (const float*)d_in[4];
    const float* W1   = (const float*)d_in[5];
    const float* b1   = (const float*)d_in[6];
    const float* W2   = (const float*)d_in[7];
    const float* b2   = (const float*)d_in[8];
    const float* ln1g = (const float*)d_in[9];
    const float* ln1b = (const float*)d_in[10];
    const float* ln2g = (const float*)d_in[11];
    const float* ln2b = (const float*)d_in[12];
    const float* lnfg = (const float*)d_in[13];
    const float* lnfb = (const float*)d_in[14];
    const float* Wout = (const float*)d_in[15];
    const float* bout = (const float*)d_in[16];
    float* out = (float*)d_out;

    float *h, *tmp, *pe;
    __half *hf, *ff, *qvh, *qvl, *wh, *wl;
    cudaGetSymbolAddress((void**)&h,   g_h);
    cudaGetSymbolAddress((void**)&tmp, g_tmp);
    cudaGetSymbolAddress((void**)&pe,  g_pe);
    cudaGetSymbolAddress((void**)&hf,  g_hf);
    cudaGetSymbolAddress((void**)&ff,  g_ff);
    cudaGetSymbolAddress((void**)&qvh, g_qkvh);
    cudaGetSymbolAddress((void**)&qvl, g_qkvl);
    cudaGetSymbolAddress((void**)&wh,  g_wh);
    cudaGetSymbolAddress((void**)&wl,  g_wl);

    cudaFuncSetAttribute(gemm_mma<0, 0, 2, 1>, cudaFuncAttributeMaxDynamicSharedMemorySize, GEMM_SMEM);
    cudaFuncSetAttribute(gemm_mma<0, 0, 0, 0>, cudaFuncAttributeMaxDynamicSharedMemorySize, GEMM_SMEM);
    cudaFuncSetAttribute(gemm_mma<1, 0, 1, 1>, cudaFuncAttributeMaxDynamicSharedMemorySize, GEMM_SMEM);
    cudaFuncSetAttribute(gemm_mma<0, 1, 0, 1>, cudaFuncAttributeMaxDynamicSharedMemorySize, GEMM_SMEM);
    cudaFuncSetAttribute(attn_mma_kernel, cudaFuncAttributeMaxDynamicSharedMemorySize, ATTN_SMEM);

    cvt_split_all<<<(F4_ALL + 255) / 256, 256>>>(Wqkv, Wo, W1, W2, Wout, wh, wl);
    pe_table_kernel<<<(SSS * DDD) / 256, 256>>>(pe);
    add_pe_kernel<<<(TTT * DDD / 4) / 256, 256>>>(x, pe, h, hf);

    for (int l = 0; l < LLL; l++) {
        const __half* wq_h = wh + OFF_QKV + (size_t)l * 3145728;
        const __half* wq_l = wl + OFF_QKV + (size_t)l * 3145728;
        const __half* wo_h = wh + OFF_WO + (size_t)l * 1048576;
        const __half* w1_h = wh + OFF_W1 + (size_t)l * 2097152;
        const __half* w1_l = wl + OFF_W1 + (size_t)l * 2097152;
        const __half* w2_h = wh + OFF_W2 + (size_t)l * 2097152;

        // qkv (fp16 hi+lo) = h @ Wqkv^T + bqkv   [2-pass]
        gemm_mma<0, 0, 2, 1><<<dim3(3072 / 128, TTT / 128), 256, GEMM_SMEM>>>(
            hf, wq_h, wq_l, bqkv + (size_t)l * 3072, nullptr, qvh, qvl,
            TTT, 3072, 1024);
        // ctx (fp16) = flash attention
        attn_mma_kernel<<<dim3(SSS / 128, BBB * HHH), 256, ATTN_SMEM>>>(qvh, qvl, ff);
        // tmp = ctx @ Wo^T + bo   [single-pass: output goes through residual+LN]
        gemm_mma<0, 0, 0, 0><<<dim3(1024 / 128, TTT / 128), 256, GEMM_SMEM>>>(
            ff, wo_h, nullptr, bo + (size_t)l * 1024, tmp, nullptr, nullptr,
            TTT, 1024, 1024);
        // h = LN(h + tmp), emit fp16
        ln_kernel<<<TTT, 256>>>(h, tmp, ln1g + (size_t)l * 1024, ln1b + (size_t)l * 1024,
                                h, hf);
        // ff (fp16) = relu(h @ W1^T + b1)   [2-pass]
        gemm_mma<1, 0, 1, 1><<<dim3(2048 / 128, TTT / 128), 256, GEMM_SMEM>>>(
            hf, w1_h, w1_l, b1 + (size_t)l * 2048, nullptr, ff, nullptr,
            TTT, 2048, 1024);
        // tmp = ff @ W2^T + b2   [single-pass: output goes through residual+LN]
        gemm_mma<0, 0, 0, 0><<<dim3(1024 / 128, TTT / 128), 256, GEMM_SMEM>>>(
            ff, w2_h, nullptr, b2 + (size_t)l * 1024, tmp, nullptr, nullptr,
            TTT, 1024, 2048);
        // h = LN(h + ff2), emit fp16
        ln_kernel<<<TTT, 256>>>(h, tmp, ln2g + (size_t)l * 1024, ln2b + (size_t)l * 1024,
                                h, hf);
    }

    ln_kernel<<<TTT, 256>>>(h, nullptr, lnfg, lnfb, h, hf);
    // out = h_final @ Wout^T + bout   [2-pass, direct output]
    gemm_mma<0, 1, 0, 1><<<dim3(DMEMM / 128, TTT / 128), 256, GEMM_SMEM>>>(
        hf, wh + OFF_WOUT, wl + OFF_WOUT, bout, out, nullptr, nullptr,
        TTT, DMEMM, 1024);
}

// round 10
// speedup vs baseline: 1.9654x; 1.1757x over previous
#include <cuda_runtime.h>
#include <cuda_fp16.h>
#include <math.h>
#include <stdint.h>

// Problem constants
#define BBB 32
#define SSS 512
#define DDD 1024
#define HHH 16
#define DHH 64
#define LLL 4
#define DFFF 2048
#define DMEMM 512
#define TTT (BBB * SSS)   // 16384 tokens

// ---------------------------------------------------------------------------
// Scratch (static device globals)
// ---------------------------------------------------------------------------
__device__ float g_h[(size_t)TTT * DDD];              //  64 MB residual
__device__ float g_tmp[(size_t)TTT * DDD];            //  64 MB
__device__ float g_pe[(size_t)SSS * DDD];             //   2 MB
__device__ __half g_hf[(size_t)TTT * DDD];            //  32 MB activations fp16
__device__ __half g_ff[(size_t)TTT * DFFF];           //  64 MB ctx / ff fp16
__device__ __half g_qkvh[(size_t)TTT * 3 * DDD];      //  96 MB qkv fp16
#define WTOT 34078720ULL
__device__ __half g_wh[WTOT];                         //  68 MB weights hi
__device__ __half g_wl[WTOT];                         //  68 MB weights lo

#define OFF_QKV 0ULL
#define OFF_WO  12582912ULL
#define OFF_W1  16777216ULL
#define OFF_W2  25165824ULL
#define OFF_WOUT 33554432ULL

// ---------------------------------------------------------------------------
// PTX helpers (baseline sm_80+)
// ---------------------------------------------------------------------------
__device__ __forceinline__ uint32_t smem_u32(const void* p) {
    uint32_t a;
    asm("{ .reg .u64 t; cvta.to.shared.u64 t, %1; cvt.u32.u64 %0, t; }" : "=r"(a) : "l"(p));
    return a;
}

#define CP16(saddr, gptr) \
    asm volatile("cp.async.cg.shared.global [%0], [%1], 16;" :: "r"(saddr), "l"(gptr))
#define CPCOMMIT() asm volatile("cp.async.commit_group;" ::: "memory")
#define CPWAIT(n)  asm volatile("cp.async.wait_group %0;" :: "n"(n) : "memory")

#define LDSM4(r, addr)                                                          \
    asm volatile("ldmatrix.sync.aligned.m8n8.x4.shared.b16 {%0,%1,%2,%3}, [%4];" \
        : "=r"((r)[0]), "=r"((r)[1]), "=r"((r)[2]), "=r"((r)[3]) : "r"(addr))

#define LDSM4T(r, addr)                                                          \
    asm volatile("ldmatrix.sync.aligned.m8n8.x4.trans.shared.b16 {%0,%1,%2,%3}, [%4];" \
        : "=r"((r)[0]), "=r"((r)[1]), "=r"((r)[2]), "=r"((r)[3]) : "r"(addr))

#define MMA_F16(d, a, b0v, b1v)                                                 \
    asm volatile("mma.sync.aligned.m16n8k16.row.col.f32.f16.f16.f32 "           \
        "{%0,%1,%2,%3}, {%4,%5,%6,%7}, {%8,%9}, {%0,%1,%2,%3};"                 \
        : "+f"((d)[0]), "+f"((d)[1]), "+f"((d)[2]), "+f"((d)[3])                \
        : "r"((a)[0]), "r"((a)[1]), "r"((a)[2]), "r"((a)[3]), "r"(b0v), "r"(b1v))

#define EX2_H2(d, s) asm("ex2.approx.f16x2 %0, %1;" : "=r"(d) : "r"(s))

__device__ __forceinline__ void split_f16(float v, __half& h, __half& l) {
    h = __float2half_rn(v);
    l = __float2half_rn(v - __half2float(h));
}
__device__ __forceinline__ uint32_t pack_h2(float a, float b) {
    uint32_t r;
    asm("cvt.rn.f16x2.f32 %0, %1, %2;" : "=r"(r) : "f"(b), "f"(a));
    return r;
}
__device__ __forceinline__ float2 unpack_h2(uint32_t u) {
    __half2 h = *reinterpret_cast<__half2*>(&u);
    return __half22float2(h);
}

// ---------------------------------------------------------------------------
// 0) merged weight split (fp16 hi/lo), one launch
// ---------------------------------------------------------------------------
#define F4_QKV 3145728
#define F4_WO  (F4_QKV + 1048576)
#define F4_W1  (F4_WO + 2097152)
#define F4_W2  (F4_W1 + 2097152)
#define F4_ALL (F4_W2 + 131072)

__global__ __launch_bounds__(256)
void cvt_split_all(const float* __restrict__ Wqkv, const float* __restrict__ Wo,
                   const float* __restrict__ W1, const float* __restrict__ W2,
                   const float* __restrict__ Wout,
                   __half* __restrict__ hi, __half* __restrict__ lo) {
    int i = blockIdx.x * 256 + threadIdx.x;
    if (i >= F4_ALL) return;
    const float* src;
    int li;
    if (i < F4_QKV)      { src = Wqkv; li = i; }
    else if (i < F4_WO)  { src = Wo;   li = i - F4_QKV; }
    else if (i < F4_W1)  { src = W1;   li = i - F4_WO; }
    else if (i < F4_W2)  { src = W2;   li = i - F4_W1; }
    else                 { src = Wout; li = i - F4_W2; }
    float4 v = reinterpret_cast<const float4*>(src)[li];
    __half h0, h1, h2, h3, l0, l1, l2, l3;
    split_f16(v.x, h0, l0); split_f16(v.y, h1, l1);
    split_f16(v.z, h2, l2); split_f16(v.w, h3, l3);
    reinterpret_cast<__half2*>(hi)[2 * i]     = __halves2half2(h0, h1);
    reinterpret_cast<__half2*>(hi)[2 * i + 1] = __halves2half2(h2, h3);
    reinterpret_cast<__half2*>(lo)[2 * i]     = __halves2half2(l0, l1);
    reinterpret_cast<__half2*>(lo)[2 * i + 1] = __halves2half2(l2, l3);
}

// ---------------------------------------------------------------------------
// 1a) PE table
// ---------------------------------------------------------------------------
__global__ __launch_bounds__(256)
void pe_table_kernel(float* __restrict__ pe) {
    int idx = blockIdx.x * 256 + threadIdx.x;
    int d = idx & (DDD - 1);
    int s = idx >> 10;
    float div = expf((float)(d & ~1) * (-9.2103403719761836f / (float)DDD));
    float ang = (float)s * div;
    pe[idx] = (d & 1) ? cosf(ang) : sinf(ang);
}

// ---------------------------------------------------------------------------
// 1b) h[s,b,:] = x[b,s,:] + PE[s,:]   (+ fp16 emit)
// ---------------------------------------------------------------------------
__global__ __launch_bounds__(256)
void add_pe_kernel(const float* __restrict__ x, const float* __restrict__ pe,
                   float* __restrict__ h, __half* __restrict__ hf) {
    int i4 = blockIdx.x * 256 + threadIdx.x;
    int d4  = i4 & 255;
    int row = i4 >> 8;
    int s   = row >> 5;
    int b   = row & 31;
    float4 xv = reinterpret_cast<const float4*>(x)[((size_t)(b * SSS + s) << 8) + d4];
    float4 pv = reinterpret_cast<const float4*>(pe)[((size_t)s << 8) + d4];
    float4 v;
    v.x = xv.x + pv.x; v.y = xv.y + pv.y; v.z = xv.z + pv.z; v.w = xv.w + pv.w;
    reinterpret_cast<float4*>(h)[i4] = v;
    reinterpret_cast<__half2*>(hf)[2 * i4] =
        __halves2half2(__float2half_rn(v.x), __float2half_rn(v.y));
    reinterpret_cast<__half2*>(hf)[2 * i4 + 1] =
        __halves2half2(__float2half_rn(v.z), __float2half_rn(v.w));
}

// ---------------------------------------------------------------------------
// 2) HMMA GEMM, fp16: C = A @ (Wh [+ Wl])^T + bias
//    TWOPASS=1: compensated 2-pass weights; TWOPASS=0: single pass.
//    OUTMODE: 0 = float C, 1 = single fp16 out.
// ---------------------------------------------------------------------------
#define SROWB 80
#define GWH_OFF 10240u
#define GWL_OFF 20480u
#define STAGE_B 30720u
#define GEMM_SMEM (2 * 30720)

template <int PERM, int TWOPASS>
__device__ __forceinline__ void load_stage(
    uint32_t sbase, const __half* __restrict__ A,
    const __half* __restrict__ Wh, const __half* __restrict__ Wl,
    int m0, int n0, int K, int k0, int t) {
#pragma unroll
    for (int i = 0; i < (TWOPASS ? 6 : 4); ++i) {
        int u = t + i * 256;
        int sel = u >> 9;                    // 0 A, 1 Wh, 2 Wl
        int v = u & 511;
        int row = v >> 2, c8 = v & 3;
        const __half* src;
        if (sel == 0) {
            int garow = m0 + row;
            if (PERM) garow = ((garow & 511) << 5) | (garow >> 9);
            src = A + (size_t)garow * K + k0 + c8 * 8;
        } else if (sel == 1) {
            src = Wh + (size_t)(n0 + row) * K + k0 + c8 * 8;
        } else {
            src = Wl + (size_t)(n0 + row) * K + k0 + c8 * 8;
        }
        uint32_t dst = sbase + (uint32_t)sel * 10240u + (uint32_t)(row * SROWB + c8 * 16);
        CP16(dst, src);
    }
}

template <int RELU, int PERM, int OUTMODE, int TWOPASS>
__global__ __launch_bounds__(256, 2)
void gemm_mma(const __half* __restrict__ A,
              const __half* __restrict__ Wh, const __half* __restrict__ Wl,
              const float* __restrict__ bias, float* __restrict__ C,
              __half* __restrict__ Ch,
              int M, int N, int K) {
    extern __shared__ char smem[];
    const uint32_t sb = smem_u32(smem);
    const int t    = threadIdx.x;
    const int lane = t & 31;
    const int w    = t >> 5;
    const int wm   = w & 1;
    const int wn   = w >> 1;
    const int m0   = blockIdx.y * 128;
    const int n0   = blockIdx.x * 128;

    float acc[4][4][4];
#pragma unroll
    for (int a = 0; a < 4; a++)
#pragma unroll
        for (int b = 0; b < 4; b++)
#pragma unroll
            for (int c = 0; c < 4; c++) acc[a][b][c] = 0.f;

    const uint32_t a_off = (uint32_t)((wm * 64 + (lane & 15)) * SROWB + (lane >> 4) * 16);
    const int brow = wn * 32 + (lane & 7) + ((lane & 16) >> 1);
    const uint32_t b_off = (uint32_t)(brow * SROWB + ((lane >> 3) & 1) * 16);

    const int NC = K >> 5;
    load_stage<PERM, TWOPASS>(sb, A, Wh, Wl, m0, n0, K, 0, t);
    CPCOMMIT();

    for (int c = 0; c < NC; ++c) {
        CPWAIT(0);
        __syncthreads();
        if (c + 1 < NC) {
            load_stage<PERM, TWOPASS>(sb + (uint32_t)((c + 1) & 1) * STAGE_B,
                                      A, Wh, Wl, m0, n0, K, (c + 1) << 5, t);
            CPCOMMIT();
        }
        const uint32_t stb = sb + (uint32_t)(c & 1) * STAGE_B;
#pragma unroll
        for (int ks = 0; ks < 2; ++ks) {
            const uint32_t ao = stb + a_off + ks * 32;
            const uint32_t bo = stb + b_off + ks * 32;
            uint32_t fa[4][4];
#pragma unroll
            for (int mi = 0; mi < 4; ++mi)
                LDSM4(fa[mi], ao + mi * (16 * SROWB));
#pragma unroll
            for (int nj = 0; nj < 2; ++nj) {
                uint32_t fbh[4];
                LDSM4(fbh, bo + GWH_OFF + nj * (16 * SROWB));
#pragma unroll
                for (int mi = 0; mi < 4; ++mi) {
                    MMA_F16(acc[mi][2 * nj],     fa[mi], fbh[0], fbh[1]);
                    MMA_F16(acc[mi][2 * nj + 1], fa[mi], fbh[2], fbh[3]);
                }
                if (TWOPASS) {
                    uint32_t fbl[4];
                    LDSM4(fbl, bo + GWL_OFF + nj * (16 * SROWB));
#pragma unroll
                    for (int mi = 0; mi < 4; ++mi) {
                        MMA_F16(acc[mi][2 * nj],     fa[mi], fbl[0], fbl[1]);
                        MMA_F16(acc[mi][2 * nj + 1], fa[mi], fbl[2], fbl[3]);
                    }
                }
            }
        }
    }

    const int qrow = lane >> 2;
    const int qcol = (lane & 3) * 2;
#pragma unroll
    for (int mi = 0; mi < 4; ++mi) {
        const int row0 = m0 + wm * 64 + mi * 16 + qrow;
#pragma unroll
        for (int ni = 0; ni < 4; ++ni) {
            const int col = n0 + wn * 32 + ni * 8 + qcol;
            const float bb0 = bias[col];
            const float bb1 = bias[col + 1];
            float v00 = acc[mi][ni][0] + bb0;
            float v01 = acc[mi][ni][1] + bb1;
            float v10 = acc[mi][ni][2] + bb0;
            float v11 = acc[mi][ni][3] + bb1;
            if (RELU) {
                v00 = fmaxf(v00, 0.f); v01 = fmaxf(v01, 0.f);
                v10 = fmaxf(v10, 0.f); v11 = fmaxf(v11, 0.f);
            }
            if (OUTMODE == 0) {
                *reinterpret_cast<float2*>(C + (size_t)row0 * N + col) =
                    make_float2(v00, v01);
                *reinterpret_cast<float2*>(C + (size_t)(row0 + 8) * N + col) =
                    make_float2(v10, v11);
            } else {
                *reinterpret_cast<__half2*>(Ch + (size_t)row0 * N + col) =
                    __halves2half2(__float2half_rn(v00), __float2half_rn(v01));
                *reinterpret_cast<__half2*>(Ch + (size_t)(row0 + 8) * N + col) =
                    __halves2half2(__float2half_rn(v10), __float2half_rn(v11));
            }
        }
    }
}

// ---------------------------------------------------------------------------
// 3) HMMA flash attention, all-fp16 single-pass (Q, K, V single fp16),
//    base-2 softmax with ex2.approx.f16x2.
// ---------------------------------------------------------------------------
#define AROWB 144
#define AQ_OFF 0u
#define AST0   18432u
#define ASTG   18432u
#define AK_OFF 0u
#define AV_OFF 9216u
#define ATTN_SMEM (18432 + 2 * 18432)
// 0.125 (1/sqrt(64)) * log2(e)
#define C_SCALE 0.18033688011112042f

__device__ __forceinline__ void attn_load_kv(
    uint32_t sbase, const __half* __restrict__ qkv, int b, int hd, int kt, int t) {
#pragma unroll
    for (int i = 0; i < 4; ++i) {
        int u = t + i * 256;             // 0..1023
        int sel = u >> 9;                // 0 K, 1 V
        int v = u & 511;
        int row = v >> 3, seg = v & 7;
        int off = sel ? 2048 : 1024;
        const __half* src =
            qkv + ((size_t)((kt * 64 + row) * BBB + b)) * 3072 + off + hd + seg * 8;
        uint32_t dst = sbase + (uint32_t)sel * 9216u + (uint32_t)(row * AROWB + seg * 16);
        CP16(dst, src);
    }
}

__global__ __launch_bounds__(256, 2)
void attn_mma_kernel(const __half* __restrict__ qkv, __half* __restrict__ ctx) {
    extern __shared__ char smem[];
    const uint32_t sb = smem_u32(smem);
    const int t    = threadIdx.x;
    const int lane = t & 31;
    const int w    = t >> 5;
    const int b    = blockIdx.y >> 4;
    const int h    = blockIdx.y & 15;
    const int q0   = blockIdx.x * 128;
    const int hd   = h * DHH;

    // load Q (128 x 64 fp16)
#pragma unroll
    for (int i = 0; i < 4; ++i) {
        int u = t + i * 256;
        int row = u >> 3, seg = u & 7;
        const __half* src = qkv + ((size_t)((q0 + row) * BBB + b)) * 3072 + hd + seg * 8;
        uint32_t dst = sb + AQ_OFF + (uint32_t)(row * AROWB + seg * 16);
        CP16(dst, src);
    }
    CPCOMMIT();
    attn_load_kv(sb + AST0, qkv, b, hd, 0, t);
    CPCOMMIT();

    float Oa[8][4];
#pragma unroll
    for (int j = 0; j < 8; j++)
#pragma unroll
        for (int c = 0; c < 4; c++) Oa[j][c] = 0.f;
    float m0r = -1e30f, m1r = -1e30f, l0r = 0.f, l1r = 0.f;

    const uint32_t arow_off = (uint32_t)((w * 16 + (lane & 15)) * AROWB + (lane >> 4) * 16);
    const uint32_t brow_off = (uint32_t)(((lane & 7) + ((lane & 16) >> 1)) * AROWB +
                                         ((lane >> 3) & 1) * 16);
    const uint32_t vrow_off = (uint32_t)((lane & 15) * AROWB + (lane >> 4) * 16);

    for (int kt = 0; kt < 8; ++kt) {
        CPWAIT(0);
        __syncthreads();
        if (kt + 1 < 8) {
            attn_load_kv(sb + AST0 + (uint32_t)((kt + 1) & 1) * ASTG, qkv, b, hd,
                         kt + 1, t);
            CPCOMMIT();
        }
        const uint32_t stg = sb + AST0 + (uint32_t)(kt & 1) * ASTG;

        // ---- S = Q K^T (single pass) ----
        float st[8][4];
#pragma unroll
        for (int j = 0; j < 8; j++)
#pragma unroll
            for (int c = 0; c < 4; c++) st[j][c] = 0.f;
#pragma unroll
        for (int kc = 0; kc < 4; ++kc) {
            uint32_t fa[4];
            LDSM4(fa, sb + AQ_OFF + arow_off + kc * 32);
#pragma unroll
            for (int g = 0; g < 4; ++g) {
                uint32_t fb[4];
                LDSM4(fb, stg + AK_OFF + brow_off + g * (16 * AROWB) + kc * 32);
                MMA_F16(st[2 * g],     fa, fb[0], fb[1]);
                MMA_F16(st[2 * g + 1], fa, fb[2], fb[3]);
            }
        }

        // ---- online softmax in base-2 ----
        float mx0 = -1e30f, mx1 = -1e30f;
#pragma unroll
        for (int j = 0; j < 8; j++) {
            st[j][0] *= C_SCALE; st[j][1] *= C_SCALE;
            st[j][2] *= C_SCALE; st[j][3] *= C_SCALE;
            mx0 = fmaxf(mx0, fmaxf(st[j][0], st[j][1]));
            mx1 = fmaxf(mx1, fmaxf(st[j][2], st[j][3]));
        }
        mx0 = fmaxf(mx0, __shfl_xor_sync(0xffffffffu, mx0, 1));
        mx0 = fmaxf(mx0, __shfl_xor_sync(0xffffffffu, mx0, 2));
        mx1 = fmaxf(mx1, __shfl_xor_sync(0xffffffffu, mx1, 1));
        mx1 = fmaxf(mx1, __shfl_xor_sync(0xffffffffu, mx1, 2));
        const float nm0 = fmaxf(m0r, mx0), nm1 = fmaxf(m1r, mx1);
        const float al0 = exp2f(m0r - nm0), al1 = exp2f(m1r - nm1);

        uint32_t pp[8][2];
        float s0 = 0.f, s1 = 0.f;
#pragma unroll
        for (int j = 0; j < 8; j++) {
            uint32_t q0p = pack_h2(st[j][0] - nm0, st[j][1] - nm0);
            uint32_t q1p = pack_h2(st[j][2] - nm1, st[j][3] - nm1);
            EX2_H2(pp[j][0], q0p);
            EX2_H2(pp[j][1], q1p);
            float2 v0 = unpack_h2(pp[j][0]);
            float2 v1 = unpack_h2(pp[j][1]);
            s0 += v0.x + v0.y;
            s1 += v1.x + v1.y;
        }
        s0 += __shfl_xor_sync(0xffffffffu, s0, 1);
        s0 += __shfl_xor_sync(0xffffffffu, s0, 2);
        s1 += __shfl_xor_sync(0xffffffffu, s1, 1);
        s1 += __shfl_xor_sync(0xffffffffu, s1, 2);
        l0r = l0r * al0 + s0;
        l1r = l1r * al1 + s1;
        m0r = nm0; m1r = nm1;
#pragma unroll
        for (int j = 0; j < 8; j++) {
            Oa[j][0] *= al0; Oa[j][1] *= al0;
            Oa[j][2] *= al1; Oa[j][3] *= al1;
        }

        // ---- O += P V (single pass) ----
#pragma unroll
        for (int kc = 0; kc < 4; ++kc) {
            uint32_t ph[4];
            ph[0] = pp[2 * kc][0];
            ph[1] = pp[2 * kc][1];
            ph[2] = pp[2 * kc + 1][0];
            ph[3] = pp[2 * kc + 1][1];
            const uint32_t vbase = stg + AV_OFF + (uint32_t)(kc * 16 * AROWB) + vrow_off;
#pragma unroll
            for (int g = 0; g < 4; ++g) {
                uint32_t fv[4];
                LDSM4T(fv, vbase + g * 32);
                MMA_F16(Oa[2 * g],     ph, fv[0], fv[1]);
                MMA_F16(Oa[2 * g + 1], ph, fv[2], fv[3]);
            }
        }
    }

    // ---- epilogue: ctx (single fp16) ----
    const float inv0 = 1.f / l0r;
    const float inv1 = 1.f / l1r;
    const int r_lo = q0 + w * 16 + (lane >> 2);
    const int col0 = hd + (lane & 3) * 2;
#pragma unroll
    for (int j = 0; j < 8; j++) {
        const int col = col0 + j * 8;
        size_t o0 = ((size_t)(r_lo * BBB + b)) * 1024 + col;
        size_t o1 = ((size_t)((r_lo + 8) * BBB + b)) * 1024 + col;
        *reinterpret_cast<__half2*>(ctx + o0) =
            __halves2half2(__float2half_rn(Oa[j][0] * inv0),
                           __float2half_rn(Oa[j][1] * inv0));
        *reinterpret_cast<__half2*>(ctx + o1) =
            __halves2half2(__float2half_rn(Oa[j][2] * inv1),
                           __float2half_rn(Oa[j][3] * inv1));
    }
}

// ---------------------------------------------------------------------------
// 4) LayerNorm, warp-shuffle reductions (+ fp16 emit)
// ---------------------------------------------------------------------------
__global__ __launch_bounds__(256)
void ln_kernel(const float* __restrict__ a, const float* __restrict__ r,
               const float* __restrict__ g, const float* __restrict__ b,
               float* __restrict__ out, __half* __restrict__ of) {
    __shared__ float red1[8];
    __shared__ float red2[8];
    const int t = threadIdx.x;
    const int lane = t & 31;
    const int w = t >> 5;
    const size_t row = blockIdx.x;
    float4 v = reinterpret_cast<const float4*>(a + row * 1024)[t];
    if (r != nullptr) {
        float4 rv = reinterpret_cast<const float4*>(r + row * 1024)[t];
        v.x += rv.x; v.y += rv.y; v.z += rv.z; v.w += rv.w;
    }
    float s = v.x + v.y + v.z + v.w;
#pragma unroll
    for (int o = 16; o > 0; o >>= 1) s += __shfl_xor_sync(0xffffffffu, s, o);
    if (lane == 0) red1[w] = s;
    __syncthreads();
    float mu = (red1[0] + red1[1] + red1[2] + red1[3] +
                red1[4] + red1[5] + red1[6] + red1[7]) * (1.f / 1024.f);
    float dx = v.x - mu, dy = v.y - mu, dz = v.z - mu, dw = v.w - mu;
    float q = dx * dx + dy * dy + dz * dz + dw * dw;
#pragma unroll
    for (int o = 16; o > 0; o >>= 1) q += __shfl_xor_sync(0xffffffffu, q, o);
    if (lane == 0) red2[w] = q;
    __syncthreads();
    float var = (red2[0] + red2[1] + red2[2] + red2[3] +
                 red2[4] + red2[5] + red2[6] + red2[7]) * (1.f / 1024.f);
    float inv = rsqrtf(var + 1e-5f);
    float4 g4 = reinterpret_cast<const float4*>(g)[t];
    float4 b4 = reinterpret_cast<const float4*>(b)[t];
    float4 o4;
    o4.x = dx * inv * g4.x + b4.x;
    o4.y = dy * inv * g4.y + b4.y;
    o4.z = dz * inv * g4.z + b4.z;
    o4.w = dw * inv * g4.w + b4.w;
    reinterpret_cast<float4*>(out + row * 1024)[t] = o4;
    if (of != nullptr) {
        reinterpret_cast<__half2*>(of + row * 1024)[2 * t] =
            __halves2half2(__float2half_rn(o4.x), __float2half_rn(o4.y));
        reinterpret_cast<__half2*>(of + row * 1024)[2 * t + 1] =
            __halves2half2(__float2half_rn(o4.z), __float2half_rn(o4.w));
    }
}

// ---------------------------------------------------------------------------
// Host orchestration
// ---------------------------------------------------------------------------
extern "C" void kernel_launch(void* const* d_in, const int* in_sizes, int n_in,
                              void* d_out, int out_size) {
    (void)in_sizes; (void)n_in; (void)out_size;
    const float* x    = (const float*)d_in[0];
    const float* Wqkv = (const float*)d_in[1];
    const float* bqkv = (const float*)d_in[2];
    const float* Wo   = (const float*)d_in[3];
    const float* bo   = (const float*)d_in[4];
    const float* W1   = (const float*)d_in[5];
    const float* b1   = (const float*)d_in[6];
    const float* W2   = (const float*)d_in[7];
    const float* b2   = (const float*)d_in[8];
    const float* ln1g = (const float*)d_in[9];
    const float* ln1b = (const float*)d_in[10];
    const float* ln2g = (const float*)d_in[11];
    const float* ln2b = (const float*)d_in[12];
    const float* lnfg = (const float*)d_in[13];
    const float* lnfb = (const float*)d_in[14];
    const float* Wout = (const float*)d_in[15];
    const float* bout = (const float*)d_in[16];
    float* out = (float*)d_out;

    float *h, *tmp, *pe;
    __half *hf, *ff, *qvh, *wh, *wl;
    cudaGetSymbolAddress((void**)&h,   g_h);
    cudaGetSymbolAddress((void**)&tmp, g_tmp);
    cudaGetSymbolAddress((void**)&pe,  g_pe);
    cudaGetSymbolAddress((void**)&hf,  g_hf);
    cudaGetSymbolAddress((void**)&ff,  g_ff);
    cudaGetSymbolAddress((void**)&qvh, g_qkvh);
    cudaGetSymbolAddress((void**)&wh,  g_wh);
    cudaGetSymbolAddress((void**)&wl,  g_wl);

    cudaFuncSetAttribute(gemm_mma<0, 0, 1, 1>, cudaFuncAttributeMaxDynamicSharedMemorySize, GEMM_SMEM);
    cudaFuncSetAttribute(gemm_mma<0, 0, 0, 0>, cudaFuncAttributeMaxDynamicSharedMemorySize, GEMM_SMEM);
    cudaFuncSetAttribute(gemm_mma<1, 0, 1, 0>, cudaFuncAttributeMaxDynamicSharedMemorySize, GEMM_SMEM);
    cudaFuncSetAttribute(gemm_mma<0, 1, 0, 1>, cudaFuncAttributeMaxDynamicSharedMemorySize, GEMM_SMEM);
    cudaFuncSetAttribute(attn_mma_kernel, cudaFuncAttributeMaxDynamicSharedMemorySize, ATTN_SMEM);

    cvt_split_all<<<(F4_ALL + 255) / 256, 256>>>(Wqkv, Wo, W1, W2, Wout, wh, wl);
    pe_table_kernel<<<(SSS * DDD) / 256, 256>>>(pe);
    add_pe_kernel<<<(TTT * DDD / 4) / 256, 256>>>(x, pe, h, hf);

    for (int l = 0; l < LLL; l++) {
        const __half* wq_h = wh + OFF_QKV + (size_t)l * 3145728;
        const __half* wq_l = wl + OFF_QKV + (size_t)l * 3145728;
        const __half* wo_h = wh + OFF_WO + (size_t)l * 1048576;
        const __half* w1_h = wh + OFF_W1 + (size_t)l * 2097152;
        const __half* w2_h = wh + OFF_W2 + (size_t)l * 2097152;

        // qkv (single fp16) = h @ Wqkv^T + bqkv   [2-pass weights]
        gemm_mma<0, 0, 1, 1><<<dim3(3072 / 128, TTT / 128), 256, GEMM_SMEM>>>(
            hf, wq_h, wq_l, bqkv + (size_t)l * 3072, nullptr, qvh,
            TTT, 3072, 1024);
        // ctx (fp16) = flash attention (all single-pass)
        attn_mma_kernel<<<dim3(SSS / 128, BBB * HHH), 256, ATTN_SMEM>>>(qvh, ff);
        // tmp = ctx @ Wo^T + bo   [single-pass]
        gemm_mma<0, 0, 0, 0><<<dim3(1024 / 128, TTT / 128), 256, GEMM_SMEM>>>(
            ff, wo_h, nullptr, bo + (size_t)l * 1024, tmp, nullptr,
            TTT, 1024, 1024);
        // h = LN(h + tmp), emit fp16
        ln_kernel<<<TTT, 256>>>(h, tmp, ln1g + (size_t)l * 1024, ln1b + (size_t)l * 1024,
                                h, hf);
        // ff (fp16) = relu(h @ W1^T + b1)   [single-pass]
        gemm_mma<1, 0, 1, 0><<<dim3(2048 / 128, TTT / 128), 256, GEMM_SMEM>>>(
            hf, w1_h, nullptr, b1 + (size_t)l * 2048, nullptr, ff,
            TTT, 2048, 1024);
        // tmp = ff @ W2^T + b2   [single-pass]
        gemm_mma<0, 0, 0, 0><<<dim3(1024 / 128, TTT / 128), 256, GEMM_SMEM>>>(
            ff, w2_h, nullptr, b2 + (size_t)l * 1024, tmp, nullptr,
            TTT, 1024, 2048);
        // h = LN(h + ff2), emit fp16
        ln_kernel<<<TTT, 256>>>(h, tmp, ln2g + (size_t)l * 1024, ln2b + (size_t)l * 1024,
                                h, hf);
    }

    ln_kernel<<<TTT, 256>>>(h, nullptr, lnfg, lnfb, h, hf);
    // out = h_final @ Wout^T + bout   [2-pass, direct output]
    gemm_mma<0, 1, 0, 1><<<dim3(DMEMM / 128, TTT / 128), 256, GEMM_SMEM>>>(
        hf, wh + OFF_WOUT, wl + OFF_WOUT, bout, out, nullptr,
        TTT, DMEMM, 1024);
}

// round 11
// speedup vs baseline: 2.3158x; 1.1783x over previous
#include <cuda_runtime.h>
#include <cuda_fp16.h>
#include <math.h>
#include <stdint.h>

// Problem constants
#define BBB 32
#define SSS 512
#define DDD 1024
#define HHH 16
#define DHH 64
#define LLL 4
#define DFFF 2048
#define DMEMM 512
#define TTT (BBB * SSS)   // 16384 tokens

// ---------------------------------------------------------------------------
// Scratch (static device globals)
// ---------------------------------------------------------------------------
__device__ float g_h[(size_t)TTT * DDD];              //  64 MB residual
__device__ float g_tmp[(size_t)TTT * DDD];            //  64 MB
__device__ float g_pe[(size_t)SSS * DDD];             //   2 MB
__device__ __half g_hf[(size_t)TTT * DDD];            //  32 MB activations fp16
__device__ __half g_ff[(size_t)TTT * DFFF];           //  64 MB ctx / ff fp16
__device__ __half g_qkvh[(size_t)TTT * 3 * DDD];      //  96 MB qkv fp16
#define WTOT 34078720ULL
__device__ __half g_wh[WTOT];                         //  68 MB weights hi
__device__ __half g_wl[WTOT];                         //  68 MB weights lo (Wout only used)

#define OFF_QKV 0ULL
#define OFF_WO  12582912ULL
#define OFF_W1  16777216ULL
#define OFF_W2  25165824ULL
#define OFF_WOUT 33554432ULL

// ---------------------------------------------------------------------------
// PTX helpers (baseline sm_80+)
// ---------------------------------------------------------------------------
__device__ __forceinline__ uint32_t smem_u32(const void* p) {
    uint32_t a;
    asm("{ .reg .u64 t; cvta.to.shared.u64 t, %1; cvt.u32.u64 %0, t; }" : "=r"(a) : "l"(p));
    return a;
}

#define CP16(saddr, gptr) \
    asm volatile("cp.async.cg.shared.global [%0], [%1], 16;" :: "r"(saddr), "l"(gptr))
#define CPCOMMIT() asm volatile("cp.async.commit_group;" ::: "memory")
#define CPWAIT(n)  asm volatile("cp.async.wait_group %0;" :: "n"(n) : "memory")

#define LDSM4(r, addr)                                                          \
    asm volatile("ldmatrix.sync.aligned.m8n8.x4.shared.b16 {%0,%1,%2,%3}, [%4];" \
        : "=r"((r)[0]), "=r"((r)[1]), "=r"((r)[2]), "=r"((r)[3]) : "r"(addr))

#define LDSM4T(r, addr)                                                          \
    asm volatile("ldmatrix.sync.aligned.m8n8.x4.trans.shared.b16 {%0,%1,%2,%3}, [%4];" \
        : "=r"((r)[0]), "=r"((r)[1]), "=r"((r)[2]), "=r"((r)[3]) : "r"(addr))

#define MMA_F16(d, a, b0v, b1v)                                                 \
    asm volatile("mma.sync.aligned.m16n8k16.row.col.f32.f16.f16.f32 "           \
        "{%0,%1,%2,%3}, {%4,%5,%6,%7}, {%8,%9}, {%0,%1,%2,%3};"                 \
        : "+f"((d)[0]), "+f"((d)[1]), "+f"((d)[2]), "+f"((d)[3])                \
        : "r"((a)[0]), "r"((a)[1]), "r"((a)[2]), "r"((a)[3]), "r"(b0v), "r"(b1v))

#define EX2_H2(d, s) asm("ex2.approx.f16x2 %0, %1;" : "=r"(d) : "r"(s))

__device__ __forceinline__ void split_f16(float v, __half& h, __half& l) {
    h = __float2half_rn(v);
    l = __float2half_rn(v - __half2float(h));
}
__device__ __forceinline__ uint32_t pack_h2(float a, float b) {
    uint32_t r;
    asm("cvt.rn.f16x2.f32 %0, %1, %2;" : "=r"(r) : "f"(b), "f"(a));
    return r;
}
__device__ __forceinline__ float2 unpack_h2(uint32_t u) {
    __half2 h = *reinterpret_cast<__half2*>(&u);
    return __half22float2(h);
}

// ---------------------------------------------------------------------------
// 0) merged weight split (fp16 hi/lo), one launch
// ---------------------------------------------------------------------------
#define F4_QKV 3145728
#define F4_WO  (F4_QKV + 1048576)
#define F4_W1  (F4_WO + 2097152)
#define F4_W2  (F4_W1 + 2097152)
#define F4_ALL (F4_W2 + 131072)

__global__ __launch_bounds__(256)
void cvt_split_all(const float* __restrict__ Wqkv, const float* __restrict__ Wo,
                   const float* __restrict__ W1, const float* __restrict__ W2,
                   const float* __restrict__ Wout,
                   __half* __restrict__ hi, __half* __restrict__ lo) {
    int i = blockIdx.x * 256 + threadIdx.x;
    if (i >= F4_ALL) return;
    const float* src;
    int li;
    if (i < F4_QKV)      { src = Wqkv; li = i; }
    else if (i < F4_WO)  { src = Wo;   li = i - F4_QKV; }
    else if (i < F4_W1)  { src = W1;   li = i - F4_WO; }
    else if (i < F4_W2)  { src = W2;   li = i - F4_W1; }
    else                 { src = Wout; li = i - F4_W2; }
    float4 v = reinterpret_cast<const float4*>(src)[li];
    __half h0, h1, h2, h3, l0, l1, l2, l3;
    split_f16(v.x, h0, l0); split_f16(v.y, h1, l1);
    split_f16(v.z, h2, l2); split_f16(v.w, h3, l3);
    reinterpret_cast<__half2*>(hi)[2 * i]     = __halves2half2(h0, h1);
    reinterpret_cast<__half2*>(hi)[2 * i + 1] = __halves2half2(h2, h3);
    reinterpret_cast<__half2*>(lo)[2 * i]     = __halves2half2(l0, l1);
    reinterpret_cast<__half2*>(lo)[2 * i + 1] = __halves2half2(l2, l3);
}

// ---------------------------------------------------------------------------
// 1a) PE table
// ---------------------------------------------------------------------------
__global__ __launch_bounds__(256)
void pe_table_kernel(float* __restrict__ pe) {
    int idx = blockIdx.x * 256 + threadIdx.x;
    int d = idx & (DDD - 1);
    int s = idx >> 10;
    float div = expf((float)(d & ~1) * (-9.2103403719761836f / (float)DDD));
    float ang = (float)s * div;
    pe[idx] = (d & 1) ? cosf(ang) : sinf(ang);
}

// ---------------------------------------------------------------------------
// 1b) h[s,b,:] = x[b,s,:] + PE[s,:]   (+ fp16 emit)
// ---------------------------------------------------------------------------
__global__ __launch_bounds__(256)
void add_pe_kernel(const float* __restrict__ x, const float* __restrict__ pe,
                   float* __restrict__ h, __half* __restrict__ hf) {
    int i4 = blockIdx.x * 256 + threadIdx.x;
    int d4  = i4 & 255;
    int row = i4 >> 8;
    int s   = row >> 5;
    int b   = row & 31;
    float4 xv = reinterpret_cast<const float4*>(x)[((size_t)(b * SSS + s) << 8) + d4];
    float4 pv = reinterpret_cast<const float4*>(pe)[((size_t)s << 8) + d4];
    float4 v;
    v.x = xv.x + pv.x; v.y = xv.y + pv.y; v.z = xv.z + pv.z; v.w = xv.w + pv.w;
    reinterpret_cast<float4*>(h)[i4] = v;
    reinterpret_cast<__half2*>(hf)[2 * i4] =
        __halves2half2(__float2half_rn(v.x), __float2half_rn(v.y));
    reinterpret_cast<__half2*>(hf)[2 * i4 + 1] =
        __halves2half2(__float2half_rn(v.z), __float2half_rn(v.w));
}

// ---------------------------------------------------------------------------
// 2) HMMA GEMM, fp16: C = A @ (Wh [+ Wl])^T + bias
//    TWOPASS=1: compensated 2-pass weights; TWOPASS=0: single pass.
//    OUTMODE: 0 = float C, 1 = single fp16 out.
// ---------------------------------------------------------------------------
#define SROWB 80
#define GWH_OFF 10240u
#define GWL_OFF 20480u
#define STAGE_B 30720u
#define GEMM_SMEM (2 * 30720)

template <int PERM, int TWOPASS>
__device__ __forceinline__ void load_stage(
    uint32_t sbase, const __half* __restrict__ A,
    const __half* __restrict__ Wh, const __half* __restrict__ Wl,
    int m0, int n0, int K, int k0, int t) {
#pragma unroll
    for (int i = 0; i < (TWOPASS ? 6 : 4); ++i) {
        int u = t + i * 256;
        int sel = u >> 9;                    // 0 A, 1 Wh, 2 Wl
        int v = u & 511;
        int row = v >> 2, c8 = v & 3;
        const __half* src;
        if (sel == 0) {
            int garow = m0 + row;
            if (PERM) garow = ((garow & 511) << 5) | (garow >> 9);
            src = A + (size_t)garow * K + k0 + c8 * 8;
        } else if (sel == 1) {
            src = Wh + (size_t)(n0 + row) * K + k0 + c8 * 8;
        } else {
            src = Wl + (size_t)(n0 + row) * K + k0 + c8 * 8;
        }
        uint32_t dst = sbase + (uint32_t)sel * 10240u + (uint32_t)(row * SROWB + c8 * 16);
        CP16(dst, src);
    }
}

template <int RELU, int PERM, int OUTMODE, int TWOPASS>
__global__ __launch_bounds__(256, 2)
void gemm_mma(const __half* __restrict__ A,
              const __half* __restrict__ Wh, const __half* __restrict__ Wl,
              const float* __restrict__ bias, float* __restrict__ C,
              __half* __restrict__ Ch,
              int M, int N, int K) {
    extern __shared__ char smem[];
    const uint32_t sb = smem_u32(smem);
    const int t    = threadIdx.x;
    const int lane = t & 31;
    const int w    = t >> 5;
    const int wm   = w & 1;
    const int wn   = w >> 1;
    const int m0   = blockIdx.y * 128;
    const int n0   = blockIdx.x * 128;

    float acc[4][4][4];
#pragma unroll
    for (int a = 0; a < 4; a++)
#pragma unroll
        for (int b = 0; b < 4; b++)
#pragma unroll
            for (int c = 0; c < 4; c++) acc[a][b][c] = 0.f;

    const uint32_t a_off = (uint32_t)((wm * 64 + (lane & 15)) * SROWB + (lane >> 4) * 16);
    const int brow = wn * 32 + (lane & 7) + ((lane & 16) >> 1);
    const uint32_t b_off = (uint32_t)(brow * SROWB + ((lane >> 3) & 1) * 16);

    const int NC = K >> 5;
    load_stage<PERM, TWOPASS>(sb, A, Wh, Wl, m0, n0, K, 0, t);
    CPCOMMIT();

    for (int c = 0; c < NC; ++c) {
        CPWAIT(0);
        __syncthreads();
        if (c + 1 < NC) {
            load_stage<PERM, TWOPASS>(sb + (uint32_t)((c + 1) & 1) * STAGE_B,
                                      A, Wh, Wl, m0, n0, K, (c + 1) << 5, t);
            CPCOMMIT();
        }
        const uint32_t stb = sb + (uint32_t)(c & 1) * STAGE_B;
#pragma unroll
        for (int ks = 0; ks < 2; ++ks) {
            const uint32_t ao = stb + a_off + ks * 32;
            const uint32_t bo = stb + b_off + ks * 32;
            uint32_t fa[4][4];
#pragma unroll
            for (int mi = 0; mi < 4; ++mi)
                LDSM4(fa[mi], ao + mi * (16 * SROWB));
#pragma unroll
            for (int nj = 0; nj < 2; ++nj) {
                uint32_t fbh[4];
                LDSM4(fbh, bo + GWH_OFF + nj * (16 * SROWB));
#pragma unroll
                for (int mi = 0; mi < 4; ++mi) {
                    MMA_F16(acc[mi][2 * nj],     fa[mi], fbh[0], fbh[1]);
                    MMA_F16(acc[mi][2 * nj + 1], fa[mi], fbh[2], fbh[3]);
                }
                if (TWOPASS) {
                    uint32_t fbl[4];
                    LDSM4(fbl, bo + GWL_OFF + nj * (16 * SROWB));
#pragma unroll
                    for (int mi = 0; mi < 4; ++mi) {
                        MMA_F16(acc[mi][2 * nj],     fa[mi], fbl[0], fbl[1]);
                        MMA_F16(acc[mi][2 * nj + 1], fa[mi], fbl[2], fbl[3]);
                    }
                }
            }
        }
    }

    const int qrow = lane >> 2;
    const int qcol = (lane & 3) * 2;
#pragma unroll
    for (int mi = 0; mi < 4; ++mi) {
        const int row0 = m0 + wm * 64 + mi * 16 + qrow;
#pragma unroll
        for (int ni = 0; ni < 4; ++ni) {
            const int col = n0 + wn * 32 + ni * 8 + qcol;
            const float bb0 = bias[col];
            const float bb1 = bias[col + 1];
            float v00 = acc[mi][ni][0] + bb0;
            float v01 = acc[mi][ni][1] + bb1;
            float v10 = acc[mi][ni][2] + bb0;
            float v11 = acc[mi][ni][3] + bb1;
            if (RELU) {
                v00 = fmaxf(v00, 0.f); v01 = fmaxf(v01, 0.f);
                v10 = fmaxf(v10, 0.f); v11 = fmaxf(v11, 0.f);
            }
            if (OUTMODE == 0) {
                *reinterpret_cast<float2*>(C + (size_t)row0 * N + col) =
                    make_float2(v00, v01);
                *reinterpret_cast<float2*>(C + (size_t)(row0 + 8) * N + col) =
                    make_float2(v10, v11);
            } else {
                *reinterpret_cast<__half2*>(Ch + (size_t)row0 * N + col) =
                    __halves2half2(__float2half_rn(v00), __float2half_rn(v01));
                *reinterpret_cast<__half2*>(Ch + (size_t)(row0 + 8) * N + col) =
                    __halves2half2(__float2half_rn(v10), __float2half_rn(v11));
            }
        }
    }
}

// ---------------------------------------------------------------------------
// 3) HMMA flash attention, all-fp16 single-pass, base-2 softmax (ex2.f16x2)
// ---------------------------------------------------------------------------
#define AROWB 144
#define AQ_OFF 0u
#define AST0   18432u
#define ASTG   18432u
#define AK_OFF 0u
#define AV_OFF 9216u
#define ATTN_SMEM (18432 + 2 * 18432)
// 0.125 (1/sqrt(64)) * log2(e)
#define C_SCALE 0.18033688011112042f

__device__ __forceinline__ void attn_load_kv(
    uint32_t sbase, const __half* __restrict__ qkv, int b, int hd, int kt, int t) {
#pragma unroll
    for (int i = 0; i < 4; ++i) {
        int u = t + i * 256;             // 0..1023
        int sel = u >> 9;                // 0 K, 1 V
        int v = u & 511;
        int row = v >> 3, seg = v & 7;
        int off = sel ? 2048 : 1024;
        const __half* src =
            qkv + ((size_t)((kt * 64 + row) * BBB + b)) * 3072 + off + hd + seg * 8;
        uint32_t dst = sbase + (uint32_t)sel * 9216u + (uint32_t)(row * AROWB + seg * 16);
        CP16(dst, src);
    }
}

__global__ __launch_bounds__(256, 2)
void attn_mma_kernel(const __half* __restrict__ qkv, __half* __restrict__ ctx) {
    extern __shared__ char smem[];
    const uint32_t sb = smem_u32(smem);
    const int t    = threadIdx.x;
    const int lane = t & 31;
    const int w    = t >> 5;
    const int b    = blockIdx.y >> 4;
    const int h    = blockIdx.y & 15;
    const int q0   = blockIdx.x * 128;
    const int hd   = h * DHH;

    // load Q (128 x 64 fp16)
#pragma unroll
    for (int i = 0; i < 4; ++i) {
        int u = t + i * 256;
        int row = u >> 3, seg = u & 7;
        const __half* src = qkv + ((size_t)((q0 + row) * BBB + b)) * 3072 + hd + seg * 8;
        uint32_t dst = sb + AQ_OFF + (uint32_t)(row * AROWB + seg * 16);
        CP16(dst, src);
    }
    CPCOMMIT();
    attn_load_kv(sb + AST0, qkv, b, hd, 0, t);
    CPCOMMIT();

    float Oa[8][4];
#pragma unroll
    for (int j = 0; j < 8; j++)
#pragma unroll
        for (int c = 0; c < 4; c++) Oa[j][c] = 0.f;
    float m0r = -1e30f, m1r = -1e30f, l0r = 0.f, l1r = 0.f;

    const uint32_t arow_off = (uint32_t)((w * 16 + (lane & 15)) * AROWB + (lane >> 4) * 16);
    const uint32_t brow_off = (uint32_t)(((lane & 7) + ((lane & 16) >> 1)) * AROWB +
                                         ((lane >> 3) & 1) * 16);
    const uint32_t vrow_off = (uint32_t)((lane & 15) * AROWB + (lane >> 4) * 16);

    for (int kt = 0; kt < 8; ++kt) {
        CPWAIT(0);
        __syncthreads();
        if (kt + 1 < 8) {
            attn_load_kv(sb + AST0 + (uint32_t)((kt + 1) & 1) * ASTG, qkv, b, hd,
                         kt + 1, t);
            CPCOMMIT();
        }
        const uint32_t stg = sb + AST0 + (uint32_t)(kt & 1) * ASTG;

        // ---- S = Q K^T ----
        float st[8][4];
#pragma unroll
        for (int j = 0; j < 8; j++)
#pragma unroll
            for (int c = 0; c < 4; c++) st[j][c] = 0.f;
#pragma unroll
        for (int kc = 0; kc < 4; ++kc) {
            uint32_t fa[4];
            LDSM4(fa, sb + AQ_OFF + arow_off + kc * 32);
#pragma unroll
            for (int g = 0; g < 4; ++g) {
                uint32_t fb[4];
                LDSM4(fb, stg + AK_OFF + brow_off + g * (16 * AROWB) + kc * 32);
                MMA_F16(st[2 * g],     fa, fb[0], fb[1]);
                MMA_F16(st[2 * g + 1], fa, fb[2], fb[3]);
            }
        }

        // ---- online softmax in base-2 ----
        float mx0 = -1e30f, mx1 = -1e30f;
#pragma unroll
        for (int j = 0; j < 8; j++) {
            st[j][0] *= C_SCALE; st[j][1] *= C_SCALE;
            st[j][2] *= C_SCALE; st[j][3] *= C_SCALE;
            mx0 = fmaxf(mx0, fmaxf(st[j][0], st[j][1]));
            mx1 = fmaxf(mx1, fmaxf(st[j][2], st[j][3]));
        }
        mx0 = fmaxf(mx0, __shfl_xor_sync(0xffffffffu, mx0, 1));
        mx0 = fmaxf(mx0, __shfl_xor_sync(0xffffffffu, mx0, 2));
        mx1 = fmaxf(mx1, __shfl_xor_sync(0xffffffffu, mx1, 1));
        mx1 = fmaxf(mx1, __shfl_xor_sync(0xffffffffu, mx1, 2));
        const float nm0 = fmaxf(m0r, mx0), nm1 = fmaxf(m1r, mx1);
        const float al0 = exp2f(m0r - nm0), al1 = exp2f(m1r - nm1);

        uint32_t pp[8][2];
        float s0 = 0.f, s1 = 0.f;
#pragma unroll
        for (int j = 0; j < 8; j++) {
            uint32_t q0p = pack_h2(st[j][0] - nm0, st[j][1] - nm0);
            uint32_t q1p = pack_h2(st[j][2] - nm1, st[j][3] - nm1);
            EX2_H2(pp[j][0], q0p);
            EX2_H2(pp[j][1], q1p);
            float2 v0 = unpack_h2(pp[j][0]);
            float2 v1 = unpack_h2(pp[j][1]);
            s0 += v0.x + v0.y;
            s1 += v1.x + v1.y;
        }
        s0 += __shfl_xor_sync(0xffffffffu, s0, 1);
        s0 += __shfl_xor_sync(0xffffffffu, s0, 2);
        s1 += __shfl_xor_sync(0xffffffffu, s1, 1);
        s1 += __shfl_xor_sync(0xffffffffu, s1, 2);
        l0r = l0r * al0 + s0;
        l1r = l1r * al1 + s1;
        m0r = nm0; m1r = nm1;
#pragma unroll
        for (int j = 0; j < 8; j++) {
            Oa[j][0] *= al0; Oa[j][1] *= al0;
            Oa[j][2] *= al1; Oa[j][3] *= al1;
        }

        // ---- O += P V ----
#pragma unroll
        for (int kc = 0; kc < 4; ++kc) {
            uint32_t ph[4];
            ph[0] = pp[2 * kc][0];
            ph[1] = pp[2 * kc][1];
            ph[2] = pp[2 * kc + 1][0];
            ph[3] = pp[2 * kc + 1][1];
            const uint32_t vbase = stg + AV_OFF + (uint32_t)(kc * 16 * AROWB) + vrow_off;
#pragma unroll
            for (int g = 0; g < 4; ++g) {
                uint32_t fv[4];
                LDSM4T(fv, vbase + g * 32);
                MMA_F16(Oa[2 * g],     ph, fv[0], fv[1]);
                MMA_F16(Oa[2 * g + 1], ph, fv[2], fv[3]);
            }
        }
    }

    // ---- epilogue: ctx (single fp16) ----
    const float inv0 = 1.f / l0r;
    const float inv1 = 1.f / l1r;
    const int r_lo = q0 + w * 16 + (lane >> 2);
    const int col0 = hd + (lane & 3) * 2;
#pragma unroll
    for (int j = 0; j < 8; j++) {
        const int col = col0 + j * 8;
        size_t o0 = ((size_t)(r_lo * BBB + b)) * 1024 + col;
        size_t o1 = ((size_t)((r_lo + 8) * BBB + b)) * 1024 + col;
        *reinterpret_cast<__half2*>(ctx + o0) =
            __halves2half2(__float2half_rn(Oa[j][0] * inv0),
                           __float2half_rn(Oa[j][1] * inv0));
        *reinterpret_cast<__half2*>(ctx + o1) =
            __halves2half2(__float2half_rn(Oa[j][2] * inv1),
                           __float2half_rn(Oa[j][3] * inv1));
    }
}

// ---------------------------------------------------------------------------
// 4) LayerNorm, warp-shuffle reductions (+ fp16 emit)
// ---------------------------------------------------------------------------
__global__ __launch_bounds__(256)
void ln_kernel(const float* __restrict__ a, const float* __restrict__ r,
               const float* __restrict__ g, const float* __restrict__ b,
               float* __restrict__ out, __half* __restrict__ of) {
    __shared__ float red1[8];
    __shared__ float red2[8];
    const int t = threadIdx.x;
    const int lane = t & 31;
    const int w = t >> 5;
    const size_t row = blockIdx.x;
    float4 v = reinterpret_cast<const float4*>(a + row * 1024)[t];
    if (r != nullptr) {
        float4 rv = reinterpret_cast<const float4*>(r + row * 1024)[t];
        v.x += rv.x; v.y += rv.y; v.z += rv.z; v.w += rv.w;
    }
    float s = v.x + v.y + v.z + v.w;
#pragma unroll
    for (int o = 16; o > 0; o >>= 1) s += __shfl_xor_sync(0xffffffffu, s, o);
    if (lane == 0) red1[w] = s;
    __syncthreads();
    float mu = (red1[0] + red1[1] + red1[2] + red1[3] +
                red1[4] + red1[5] + red1[6] + red1[7]) * (1.f / 1024.f);
    float dx = v.x - mu, dy = v.y - mu, dz = v.z - mu, dw = v.w - mu;
    float q = dx * dx + dy * dy + dz * dz + dw * dw;
#pragma unroll
    for (int o = 16; o > 0; o >>= 1) q += __shfl_xor_sync(0xffffffffu, q, o);
    if (lane == 0) red2[w] = q;
    __syncthreads();
    float var = (red2[0] + red2[1] + red2[2] + red2[3] +
                 red2[4] + red2[5] + red2[6] + red2[7]) * (1.f / 1024.f);
    float inv = rsqrtf(var + 1e-5f);
    float4 g4 = reinterpret_cast<const float4*>(g)[t];
    float4 b4 = reinterpret_cast<const float4*>(b)[t];
    float4 o4;
    o4.x = dx * inv * g4.x + b4.x;
    o4.y = dy * inv * g4.y + b4.y;
    o4.z = dz * inv * g4.z + b4.z;
    o4.w = dw * inv * g4.w + b4.w;
    reinterpret_cast<float4*>(out + row * 1024)[t] = o4;
    if (of != nullptr) {
        reinterpret_cast<__half2*>(of + row * 1024)[2 * t] =
            __halves2half2(__float2half_rn(o4.x), __float2half_rn(o4.y));
        reinterpret_cast<__half2*>(of + row * 1024)[2 * t + 1] =
            __halves2half2(__float2half_rn(o4.z), __float2half_rn(o4.w));
    }
}

// ---------------------------------------------------------------------------
// Host orchestration
// ---------------------------------------------------------------------------
extern "C" void kernel_launch(void* const* d_in, const int* in_sizes, int n_in,
                              void* d_out, int out_size) {
    (void)in_sizes; (void)n_in; (void)out_size;
    const float* x    = (const float*)d_in[0];
    const float* Wqkv = (const float*)d_in[1];
    const float* bqkv = (const float*)d_in[2];
    const float* Wo   = (const float*)d_in[3];
    const float* bo   = (const float*)d_in[4];
    const float* W1   = (const float*)d_in[5];
    const float* b1   = (const float*)d_in[6];
    const float* W2   = (const float*)d_in[7];
    const float* b2   = (const float*)d_in[8];
    const float* ln1g = (const float*)d_in[9];
    const float* ln1b = (const float*)d_in[10];
    const float* ln2g = (const float*)d_in[11];
    const float* ln2b = (const float*)d_in[12];
    const float* lnfg = (const float*)d_in[13];
    const float* lnfb = (const float*)d_in[14];
    const float* Wout = (const float*)d_in[15];
    const float* bout = (const float*)d_in[16];
    float* out = (float*)d_out;

    float *h, *tmp, *pe;
    __half *hf, *ff, *qvh, *wh, *wl;
    cudaGetSymbolAddress((void**)&h,   g_h);
    cudaGetSymbolAddress((void**)&tmp, g_tmp);
    cudaGetSymbolAddress((void**)&pe,  g_pe);
    cudaGetSymbolAddress((void**)&hf,  g_hf);
    cudaGetSymbolAddress((void**)&ff,  g_ff);
    cudaGetSymbolAddress((void**)&qvh, g_qkvh);
    cudaGetSymbolAddress((void**)&wh,  g_wh);
    cudaGetSymbolAddress((void**)&wl,  g_wl);

    cudaFuncSetAttribute(gemm_mma<0, 0, 1, 0>, cudaFuncAttributeMaxDynamicSharedMemorySize, GEMM_SMEM);
    cudaFuncSetAttribute(gemm_mma<0, 0, 0, 0>, cudaFuncAttributeMaxDynamicSharedMemorySize, GEMM_SMEM);
    cudaFuncSetAttribute(gemm_mma<1, 0, 1, 0>, cudaFuncAttributeMaxDynamicSharedMemorySize, GEMM_SMEM);
    cudaFuncSetAttribute(gemm_mma<0, 1, 0, 1>, cudaFuncAttributeMaxDynamicSharedMemorySize, GEMM_SMEM);
    cudaFuncSetAttribute(attn_mma_kernel, cudaFuncAttributeMaxDynamicSharedMemorySize, ATTN_SMEM);

    cvt_split_all<<<(F4_ALL + 255) / 256, 256>>>(Wqkv, Wo, W1, W2, Wout, wh, wl);
    pe_table_kernel<<<(SSS * DDD) / 256, 256>>>(pe);
    add_pe_kernel<<<(TTT * DDD / 4) / 256, 256>>>(x, pe, h, hf);

    for (int l = 0; l < LLL; l++) {
        const __half* wq_h = wh + OFF_QKV + (size_t)l * 3145728;
        const __half* wo_h = wh + OFF_WO + (size_t)l * 1048576;
        const __half* w1_h = wh + OFF_W1 + (size_t)l * 2097152;
        const __half* w2_h = wh + OFF_W2 + (size_t)l * 2097152;

        // qkv (single fp16) = h @ Wqkv^T + bqkv   [single-pass]
        gemm_mma<0, 0, 1, 0><<<dim3(3072 / 128, TTT / 128), 256, GEMM_SMEM>>>(
            hf, wq_h, nullptr, bqkv + (size_t)l * 3072, nullptr, qvh,
            TTT, 3072, 1024);
        // ctx (fp16) = flash attention (single-pass)
        attn_mma_kernel<<<dim3(SSS / 128, BBB * HHH), 256, ATTN_SMEM>>>(qvh, ff);
        // tmp = ctx @ Wo^T + bo   [single-pass]
        gemm_mma<0, 0, 0, 0><<<dim3(1024 / 128, TTT / 128), 256, GEMM_SMEM>>>(
            ff, wo_h, nullptr, bo + (size_t)l * 1024, tmp, nullptr,
            TTT, 1024, 1024);
        // h = LN(h + tmp), emit fp16
        ln_kernel<<<TTT, 256>>>(h, tmp, ln1g + (size_t)l * 1024, ln1b + (size_t)l * 1024,
                                h, hf);
        // ff (fp16) = relu(h @ W1^T + b1)   [single-pass]
        gemm_mma<1, 0, 1, 0><<<dim3(2048 / 128, TTT / 128), 256, GEMM_SMEM>>>(
            hf, w1_h, nullptr, b1 + (size_t)l * 2048, nullptr, ff,
            TTT, 2048, 1024);
        // tmp = ff @ W2^T + b2   [single-pass]
        gemm_mma<0, 0, 0, 0><<<dim3(1024 / 128, TTT / 128), 256, GEMM_SMEM>>>(
            ff, w2_h, nullptr, b2 + (size_t)l * 1024, tmp, nullptr,
            TTT, 1024, 2048);
        // h = LN(h + ff2), emit fp16
        ln_kernel<<<TTT, 256>>>(h, tmp, ln2g + (size_t)l * 1024, ln2b + (size_t)l * 1024,
                                h, hf);
    }

    ln_kernel<<<TTT, 256>>>(h, nullptr, lnfg, lnfb, h, hf);
    // out = h_final @ Wout^T + bout   [2-pass, direct fp32 output]
    gemm_mma<0, 1, 0, 1><<<dim3(DMEMM / 128, TTT / 128), 256, GEMM_SMEM>>>(
        hf, wh + OFF_WOUT, wl + OFF_WOUT, bout, out, nullptr,
        TTT, DMEMM, 1024);
}

// round 12
// speedup vs baseline: 2.6228x; 1.1326x over previous
#include <cuda_runtime.h>
#include <cuda_fp16.h>
#include <math.h>
#include <stdint.h>

// Problem constants
#define BBB 32
#define SSS 512
#define DDD 1024
#define HHH 16
#define DHH 64
#define LLL 4
#define DFFF 2048
#define DMEMM 512
#define TTT (BBB * SSS)   // 16384 tokens

// ---------------------------------------------------------------------------
// Scratch (static device globals)
// ---------------------------------------------------------------------------
__device__ float g_h[(size_t)TTT * DDD];              //  64 MB residual fp32
__device__ float g_pe[(size_t)SSS * DDD];             //   2 MB
__device__ __half g_tmph[(size_t)TTT * DDD];          //  32 MB residual delta fp16
__device__ __half g_hf[(size_t)TTT * DDD];            //  32 MB activations fp16
__device__ __half g_ff[(size_t)TTT * DFFF];           //  64 MB ctx / ff fp16
__device__ __half g_qkvh[(size_t)TTT * 3 * DDD];      //  96 MB qkv fp16
#define WTOT 34078720ULL
__device__ __half g_wh[WTOT];                         //  68 MB weights hi
__device__ __half g_wl[WTOT];                         //  68 MB weights lo (Wout only)

#define OFF_QKV 0ULL
#define OFF_WO  12582912ULL
#define OFF_W1  16777216ULL
#define OFF_W2  25165824ULL
#define OFF_WOUT 33554432ULL

// ---------------------------------------------------------------------------
// PTX helpers (baseline sm_80+)
// ---------------------------------------------------------------------------
__device__ __forceinline__ uint32_t smem_u32(const void* p) {
    uint32_t a;
    asm("{ .reg .u64 t; cvta.to.shared.u64 t, %1; cvt.u32.u64 %0, t; }" : "=r"(a) : "l"(p));
    return a;
}

#define CP16(saddr, gptr) \
    asm volatile("cp.async.cg.shared.global [%0], [%1], 16;" :: "r"(saddr), "l"(gptr))
#define CPCOMMIT() asm volatile("cp.async.commit_group;" ::: "memory")
#define CPWAIT(n)  asm volatile("cp.async.wait_group %0;" :: "n"(n) : "memory")

#define LDSM4(r, addr)                                                          \
    asm volatile("ldmatrix.sync.aligned.m8n8.x4.shared.b16 {%0,%1,%2,%3}, [%4];" \
        : "=r"((r)[0]), "=r"((r)[1]), "=r"((r)[2]), "=r"((r)[3]) : "r"(addr))

#define LDSM4T(r, addr)                                                          \
    asm volatile("ldmatrix.sync.aligned.m8n8.x4.trans.shared.b16 {%0,%1,%2,%3}, [%4];" \
        : "=r"((r)[0]), "=r"((r)[1]), "=r"((r)[2]), "=r"((r)[3]) : "r"(addr))

#define MMA_F16(d, a, b0v, b1v)                                                 \
    asm volatile("mma.sync.aligned.m16n8k16.row.col.f32.f16.f16.f32 "           \
        "{%0,%1,%2,%3}, {%4,%5,%6,%7}, {%8,%9}, {%0,%1,%2,%3};"                 \
        : "+f"((d)[0]), "+f"((d)[1]), "+f"((d)[2]), "+f"((d)[3])                \
        : "r"((a)[0]), "r"((a)[1]), "r"((a)[2]), "r"((a)[3]), "r"(b0v), "r"(b1v))

#define EX2_H2(d, s) asm("ex2.approx.f16x2 %0, %1;" : "=r"(d) : "r"(s))

__device__ __forceinline__ void split_f16(float v, __half& h, __half& l) {
    h = __float2half_rn(v);
    l = __float2half_rn(v - __half2float(h));
}
__device__ __forceinline__ uint32_t pack_h2(float a, float b) {
    uint32_t r;
    asm("cvt.rn.f16x2.f32 %0, %1, %2;" : "=r"(r) : "f"(b), "f"(a));
    return r;
}
__device__ __forceinline__ float2 unpack_h2(uint32_t u) {
    __half2 h = *reinterpret_cast<__half2*>(&u);
    return __half22float2(h);
}

// ---------------------------------------------------------------------------
// 0) merged weight split (fp16 hi/lo), one launch
// ---------------------------------------------------------------------------
#define F4_QKV 3145728
#define F4_WO  (F4_QKV + 1048576)
#define F4_W1  (F4_WO + 2097152)
#define F4_W2  (F4_W1 + 2097152)
#define F4_ALL (F4_W2 + 131072)

__global__ __launch_bounds__(256)
void cvt_split_all(const float* __restrict__ Wqkv, const float* __restrict__ Wo,
                   const float* __restrict__ W1, const float* __restrict__ W2,
                   const float* __restrict__ Wout,
                   __half* __restrict__ hi, __half* __restrict__ lo) {
    int i = blockIdx.x * 256 + threadIdx.x;
    if (i >= F4_ALL) return;
    const float* src;
    int li;
    if (i < F4_QKV)      { src = Wqkv; li = i; }
    else if (i < F4_WO)  { src = Wo;   li = i - F4_QKV; }
    else if (i < F4_W1)  { src = W1;   li = i - F4_WO; }
    else if (i < F4_W2)  { src = W2;   li = i - F4_W1; }
    else                 { src = Wout; li = i - F4_W2; }
    float4 v = reinterpret_cast<const float4*>(src)[li];
    __half h0, h1, h2, h3, l0, l1, l2, l3;
    split_f16(v.x, h0, l0); split_f16(v.y, h1, l1);
    split_f16(v.z, h2, l2); split_f16(v.w, h3, l3);
    reinterpret_cast<__half2*>(hi)[2 * i]     = __halves2half2(h0, h1);
    reinterpret_cast<__half2*>(hi)[2 * i + 1] = __halves2half2(h2, h3);
    reinterpret_cast<__half2*>(lo)[2 * i]     = __halves2half2(l0, l1);
    reinterpret_cast<__half2*>(lo)[2 * i + 1] = __halves2half2(l2, l3);
}

// ---------------------------------------------------------------------------
// 1a) PE table
// ---------------------------------------------------------------------------
__global__ __launch_bounds__(256)
void pe_table_kernel(float* __restrict__ pe) {
    int idx = blockIdx.x * 256 + threadIdx.x;
    int d = idx & (DDD - 1);
    int s = idx >> 10;
    float div = expf((float)(d & ~1) * (-9.2103403719761836f / (float)DDD));
    float ang = (float)s * div;
    pe[idx] = (d & 1) ? cosf(ang) : sinf(ang);
}

// ---------------------------------------------------------------------------
// 1b) h[s,b,:] = x[b,s,:] + PE[s,:]   (+ fp16 emit)
// ---------------------------------------------------------------------------
__global__ __launch_bounds__(256)
void add_pe_kernel(const float* __restrict__ x, const float* __restrict__ pe,
                   float* __restrict__ h, __half* __restrict__ hf) {
    int i4 = blockIdx.x * 256 + threadIdx.x;
    int d4  = i4 & 255;
    int row = i4 >> 8;
    int s   = row >> 5;
    int b   = row & 31;
    float4 xv = reinterpret_cast<const float4*>(x)[((size_t)(b * SSS + s) << 8) + d4];
    float4 pv = reinterpret_cast<const float4*>(pe)[((size_t)s << 8) + d4];
    float4 v;
    v.x = xv.x + pv.x; v.y = xv.y + pv.y; v.z = xv.z + pv.z; v.w = xv.w + pv.w;
    reinterpret_cast<float4*>(h)[i4] = v;
    reinterpret_cast<__half2*>(hf)[2 * i4] =
        __halves2half2(__float2half_rn(v.x), __float2half_rn(v.y));
    reinterpret_cast<__half2*>(hf)[2 * i4 + 1] =
        __halves2half2(__float2half_rn(v.z), __float2half_rn(v.w));
}

// ---------------------------------------------------------------------------
// 2) HMMA GEMM, fp16, BK=64: C = A @ (Wh [+ Wl])^T + bias
//    Stage: A (128x64, 144B rows) | Wh | [Wl]; 16 k-chunks for K=1024.
//    OUTMODE: 0 = float C, 1 = fp16 Ch.  RELU optional.  PERM fuses transpose.
// ---------------------------------------------------------------------------
#define SROWB 144
#define SEG_B 18432u                    // one 128x64 fp16 buffer (padded)
#define STAGE1 36864u                   // single-pass stage (A + Wh)
#define STAGE2 55296u                   // two-pass stage (A + Wh + Wl)
#define GEMM_SMEM1 (2 * 36864)
#define GEMM_SMEM2 (2 * 55296)

template <int PERM, int TWOPASS>
__device__ __forceinline__ void load_stage(
    uint32_t sbase, const __half* __restrict__ A,
    const __half* __restrict__ Wh, const __half* __restrict__ Wl,
    int m0, int n0, int K, int k0, int t) {
#pragma unroll
    for (int i = 0; i < (TWOPASS ? 12 : 8); ++i) {
        int u = t + i * 256;                 // 0..3071 (or 0..2047)
        int sel = u >> 10;                   // 0 A, 1 Wh, 2 Wl
        int v = u & 1023;
        int row = v >> 3, seg = v & 7;
        const __half* src;
        if (sel == 0) {
            int garow = m0 + row;
            if (PERM) garow = ((garow & 511) << 5) | (garow >> 9);
            src = A + (size_t)garow * K + k0 + seg * 8;
        } else if (sel == 1) {
            src = Wh + (size_t)(n0 + row) * K + k0 + seg * 8;
        } else {
            src = Wl + (size_t)(n0 + row) * K + k0 + seg * 8;
        }
        uint32_t dst = sbase + (uint32_t)sel * SEG_B + (uint32_t)(row * SROWB + seg * 16);
        CP16(dst, src);
    }
}

template <int RELU, int PERM, int OUTMODE, int TWOPASS>
__global__ __launch_bounds__(256, 2)
void gemm_mma(const __half* __restrict__ A,
              const __half* __restrict__ Wh, const __half* __restrict__ Wl,
              const float* __restrict__ bias, float* __restrict__ C,
              __half* __restrict__ Ch,
              int M, int N, int K) {
    extern __shared__ char smem[];
    const uint32_t sb = smem_u32(smem);
    constexpr uint32_t STG = TWOPASS ? STAGE2 : STAGE1;
    const int t    = threadIdx.x;
    const int lane = t & 31;
    const int w    = t >> 5;
    const int wm   = w & 1;
    const int wn   = w >> 1;
    const int m0   = blockIdx.y * 128;
    const int n0   = blockIdx.x * 128;

    float acc[4][4][4];
#pragma unroll
    for (int a = 0; a < 4; a++)
#pragma unroll
        for (int b = 0; b < 4; b++)
#pragma unroll
            for (int c = 0; c < 4; c++) acc[a][b][c] = 0.f;

    const uint32_t a_off = (uint32_t)((wm * 64 + (lane & 15)) * SROWB + (lane >> 4) * 16);
    const int brow = wn * 32 + (lane & 7) + ((lane & 16) >> 1);
    const uint32_t b_off = (uint32_t)(brow * SROWB + ((lane >> 3) & 1) * 16);

    const int NC = K >> 6;              // chunks of 64
    load_stage<PERM, TWOPASS>(sb, A, Wh, Wl, m0, n0, K, 0, t);
    CPCOMMIT();

    for (int c = 0; c < NC; ++c) {
        CPWAIT(0);
        __syncthreads();
        if (c + 1 < NC) {
            load_stage<PERM, TWOPASS>(sb + (uint32_t)((c + 1) & 1) * STG,
                                      A, Wh, Wl, m0, n0, K, (c + 1) << 6, t);
            CPCOMMIT();
        }
        const uint32_t stb = sb + (uint32_t)(c & 1) * STG;
#pragma unroll
        for (int ks = 0; ks < 4; ++ks) {
            const uint32_t ao = stb + a_off + ks * 32;
            const uint32_t bo = stb + SEG_B + b_off + ks * 32;
            uint32_t fa[4][4];
#pragma unroll
            for (int mi = 0; mi < 4; ++mi)
                LDSM4(fa[mi], ao + mi * (16 * SROWB));
#pragma unroll
            for (int nj = 0; nj < 2; ++nj) {
                uint32_t fbh[4];
                LDSM4(fbh, bo + nj * (16 * SROWB));
#pragma unroll
                for (int mi = 0; mi < 4; ++mi) {
                    MMA_F16(acc[mi][2 * nj],     fa[mi], fbh[0], fbh[1]);
                    MMA_F16(acc[mi][2 * nj + 1], fa[mi], fbh[2], fbh[3]);
                }
                if (TWOPASS) {
                    uint32_t fbl[4];
                    LDSM4(fbl, bo + SEG_B + nj * (16 * SROWB));
#pragma unroll
                    for (int mi = 0; mi < 4; ++mi) {
                        MMA_F16(acc[mi][2 * nj],     fa[mi], fbl[0], fbl[1]);
                        MMA_F16(acc[mi][2 * nj + 1], fa[mi], fbl[2], fbl[3]);
                    }
                }
            }
        }
    }

    const int qrow = lane >> 2;
    const int qcol = (lane & 3) * 2;
#pragma unroll
    for (int mi = 0; mi < 4; ++mi) {
        const int row0 = m0 + wm * 64 + mi * 16 + qrow;
#pragma unroll
        for (int ni = 0; ni < 4; ++ni) {
            const int col = n0 + wn * 32 + ni * 8 + qcol;
            const float bb0 = bias[col];
            const float bb1 = bias[col + 1];
            float v00 = acc[mi][ni][0] + bb0;
            float v01 = acc[mi][ni][1] + bb1;
            float v10 = acc[mi][ni][2] + bb0;
            float v11 = acc[mi][ni][3] + bb1;
            if (RELU) {
                v00 = fmaxf(v00, 0.f); v01 = fmaxf(v01, 0.f);
                v10 = fmaxf(v10, 0.f); v11 = fmaxf(v11, 0.f);
            }
            if (OUTMODE == 0) {
                *reinterpret_cast<float2*>(C + (size_t)row0 * N + col) =
                    make_float2(v00, v01);
                *reinterpret_cast<float2*>(C + (size_t)(row0 + 8) * N + col) =
                    make_float2(v10, v11);
            } else {
                *reinterpret_cast<__half2*>(Ch + (size_t)row0 * N + col) =
                    __halves2half2(__float2half_rn(v00), __float2half_rn(v01));
                *reinterpret_cast<__half2*>(Ch + (size_t)(row0 + 8) * N + col) =
                    __halves2half2(__float2half_rn(v10), __float2half_rn(v11));
            }
        }
    }
}

// ---------------------------------------------------------------------------
// 3) HMMA flash attention, all-fp16 single-pass, base-2 softmax (ex2.f16x2)
// ---------------------------------------------------------------------------
#define AROWB 144
#define AQ_OFF 0u
#define AST0   18432u
#define ASTG   18432u
#define AK_OFF 0u
#define AV_OFF 9216u
#define ATTN_SMEM (18432 + 2 * 18432)
// 0.125 (1/sqrt(64)) * log2(e)
#define C_SCALE 0.18033688011112042f

__device__ __forceinline__ void attn_load_kv(
    uint32_t sbase, const __half* __restrict__ qkv, int b, int hd, int kt, int t) {
#pragma unroll
    for (int i = 0; i < 4; ++i) {
        int u = t + i * 256;             // 0..1023
        int sel = u >> 9;                // 0 K, 1 V
        int v = u & 511;
        int row = v >> 3, seg = v & 7;
        int off = sel ? 2048 : 1024;
        const __half* src =
            qkv + ((size_t)((kt * 64 + row) * BBB + b)) * 3072 + off + hd + seg * 8;
        uint32_t dst = sbase + (uint32_t)sel * 9216u + (uint32_t)(row * AROWB + seg * 16);
        CP16(dst, src);
    }
}

__global__ __launch_bounds__(256, 2)
void attn_mma_kernel(const __half* __restrict__ qkv, __half* __restrict__ ctx) {
    extern __shared__ char smem[];
    const uint32_t sb = smem_u32(smem);
    const int t    = threadIdx.x;
    const int lane = t & 31;
    const int w    = t >> 5;
    const int b    = blockIdx.y >> 4;
    const int h    = blockIdx.y & 15;
    const int q0   = blockIdx.x * 128;
    const int hd   = h * DHH;

    // load Q (128 x 64 fp16)
#pragma unroll
    for (int i = 0; i < 4; ++i) {
        int u = t + i * 256;
        int row = u >> 3, seg = u & 7;
        const __half* src = qkv + ((size_t)((q0 + row) * BBB + b)) * 3072 + hd + seg * 8;
        uint32_t dst = sb + AQ_OFF + (uint32_t)(row * AROWB + seg * 16);
        CP16(dst, src);
    }
    CPCOMMIT();
    attn_load_kv(sb + AST0, qkv, b, hd, 0, t);
    CPCOMMIT();

    float Oa[8][4];
#pragma unroll
    for (int j = 0; j < 8; j++)
#pragma unroll
        for (int c = 0; c < 4; c++) Oa[j][c] = 0.f;
    float m0r = -1e30f, m1r = -1e30f, l0r = 0.f, l1r = 0.f;

    const uint32_t arow_off = (uint32_t)((w * 16 + (lane & 15)) * AROWB + (lane >> 4) * 16);
    const uint32_t brow_off = (uint32_t)(((lane & 7) + ((lane & 16) >> 1)) * AROWB +
                                         ((lane >> 3) & 1) * 16);
    const uint32_t vrow_off = (uint32_t)((lane & 15) * AROWB + (lane >> 4) * 16);

    for (int kt = 0; kt < 8; ++kt) {
        CPWAIT(0);
        __syncthreads();
        if (kt + 1 < 8) {
            attn_load_kv(sb + AST0 + (uint32_t)((kt + 1) & 1) * ASTG, qkv, b, hd,
                         kt + 1, t);
            CPCOMMIT();
        }
        const uint32_t stg = sb + AST0 + (uint32_t)(kt & 1) * ASTG;

        // ---- S = Q K^T ----
        float st[8][4];
#pragma unroll
        for (int j = 0; j < 8; j++)
#pragma unroll
            for (int c = 0; c < 4; c++) st[j][c] = 0.f;
#pragma unroll
        for (int kc = 0; kc < 4; ++kc) {
            uint32_t fa[4];
            LDSM4(fa, sb + AQ_OFF + arow_off + kc * 32);
#pragma unroll
            for (int g = 0; g < 4; ++g) {
                uint32_t fb[4];
                LDSM4(fb, stg + AK_OFF + brow_off + g * (16 * AROWB) + kc * 32);
                MMA_F16(st[2 * g],     fa, fb[0], fb[1]);
                MMA_F16(st[2 * g + 1], fa, fb[2], fb[3]);
            }
        }

        // ---- online softmax in base-2 ----
        float mx0 = -1e30f, mx1 = -1e30f;
#pragma unroll
        for (int j = 0; j < 8; j++) {
            st[j][0] *= C_SCALE; st[j][1] *= C_SCALE;
            st[j][2] *= C_SCALE; st[j][3] *= C_SCALE;
            mx0 = fmaxf(mx0, fmaxf(st[j][0], st[j][1]));
            mx1 = fmaxf(mx1, fmaxf(st[j][2], st[j][3]));
        }
        mx0 = fmaxf(mx0, __shfl_xor_sync(0xffffffffu, mx0, 1));
        mx0 = fmaxf(mx0, __shfl_xor_sync(0xffffffffu, mx0, 2));
        mx1 = fmaxf(mx1, __shfl_xor_sync(0xffffffffu, mx1, 1));
        mx1 = fmaxf(mx1, __shfl_xor_sync(0xffffffffu, mx1, 2));
        const float nm0 = fmaxf(m0r, mx0), nm1 = fmaxf(m1r, mx1);
        const float al0 = exp2f(m0r - nm0), al1 = exp2f(m1r - nm1);

        uint32_t pp[8][2];
        float s0 = 0.f, s1 = 0.f;
#pragma unroll
        for (int j = 0; j < 8; j++) {
            uint32_t q0p = pack_h2(st[j][0] - nm0, st[j][1] - nm0);
            uint32_t q1p = pack_h2(st[j][2] - nm1, st[j][3] - nm1);
            EX2_H2(pp[j][0], q0p);
            EX2_H2(pp[j][1], q1p);
            float2 v0 = unpack_h2(pp[j][0]);
            float2 v1 = unpack_h2(pp[j][1]);
            s0 += v0.x + v0.y;
            s1 += v1.x + v1.y;
        }
        s0 += __shfl_xor_sync(0xffffffffu, s0, 1);
        s0 += __shfl_xor_sync(0xffffffffu, s0, 2);
        s1 += __shfl_xor_sync(0xffffffffu, s1, 1);
        s1 += __shfl_xor_sync(0xffffffffu, s1, 2);
        l0r = l0r * al0 + s0;
        l1r = l1r * al1 + s1;
        m0r = nm0; m1r = nm1;
#pragma unroll
        for (int j = 0; j < 8; j++) {
            Oa[j][0] *= al0; Oa[j][1] *= al0;
            Oa[j][2] *= al1; Oa[j][3] *= al1;
        }

        // ---- O += P V ----
#pragma unroll
        for (int kc = 0; kc < 4; ++kc) {
            uint32_t ph[4];
            ph[0] = pp[2 * kc][0];
            ph[1] = pp[2 * kc][1];
            ph[2] = pp[2 * kc + 1][0];
            ph[3] = pp[2 * kc + 1][1];
            const uint32_t vbase = stg + AV_OFF + (uint32_t)(kc * 16 * AROWB) + vrow_off;
#pragma unroll
            for (int g = 0; g < 4; ++g) {
                uint32_t fv[4];
                LDSM4T(fv, vbase + g * 32);
                MMA_F16(Oa[2 * g],     ph, fv[0], fv[1]);
                MMA_F16(Oa[2 * g + 1], ph, fv[2], fv[3]);
            }
        }
    }

    // ---- epilogue: ctx (single fp16) ----
    const float inv0 = 1.f / l0r;
    const float inv1 = 1.f / l1r;
    const int r_lo = q0 + w * 16 + (lane >> 2);
    const int col0 = hd + (lane & 3) * 2;
#pragma unroll
    for (int j = 0; j < 8; j++) {
        const int col = col0 + j * 8;
        size_t o0 = ((size_t)(r_lo * BBB + b)) * 1024 + col;
        size_t o1 = ((size_t)((r_lo + 8) * BBB + b)) * 1024 + col;
        *reinterpret_cast<__half2*>(ctx + o0) =
            __halves2half2(__float2half_rn(Oa[j][0] * inv0),
                           __float2half_rn(Oa[j][1] * inv0));
        *reinterpret_cast<__half2*>(ctx + o1) =
            __halves2half2(__float2half_rn(Oa[j][2] * inv1),
                           __float2half_rn(Oa[j][3] * inv1));
    }
}

// ---------------------------------------------------------------------------
// 4) LayerNorm: out = LN(a + r_fp16) * g + b   (+ fp16 emit)
// ---------------------------------------------------------------------------
__global__ __launch_bounds__(256)
void ln_kernel(const float* __restrict__ a, const __half* __restrict__ r,
               const float* __restrict__ g, const float* __restrict__ b,
               float* __restrict__ out, __half* __restrict__ of) {
    __shared__ float red1[8];
    __shared__ float red2[8];
    const int t = threadIdx.x;
    const int lane = t & 31;
    const int w = t >> 5;
    const size_t row = blockIdx.x;
    float4 v = reinterpret_cast<const float4*>(a + row * 1024)[t];
    if (r != nullptr) {
        __half2 r0 = reinterpret_cast<const __half2*>(r + row * 1024)[2 * t];
        __half2 r1 = reinterpret_cast<const __half2*>(r + row * 1024)[2 * t + 1];
        float2 f0 = __half22float2(r0);
        float2 f1 = __half22float2(r1);
        v.x += f0.x; v.y += f0.y; v.z += f1.x; v.w += f1.y;
    }
    float s = v.x + v.y + v.z + v.w;
#pragma unroll
    for (int o = 16; o > 0; o >>= 1) s += __shfl_xor_sync(0xffffffffu, s, o);
    if (lane == 0) red1[w] = s;
    __syncthreads();
    float mu = (red1[0] + red1[1] + red1[2] + red1[3] +
                red1[4] + red1[5] + red1[6] + red1[7]) * (1.f / 1024.f);
    float dx = v.x - mu, dy = v.y - mu, dz = v.z - mu, dw = v.w - mu;
    float q = dx * dx + dy * dy + dz * dz + dw * dw;
#pragma unroll
    for (int o = 16; o > 0; o >>= 1) q += __shfl_xor_sync(0xffffffffu, q, o);
    if (lane == 0) red2[w] = q;
    __syncthreads();
    float var = (red2[0] + red2[1] + red2[2] + red2[3] +
                 red2[4] + red2[5] + red2[6] + red2[7]) * (1.f / 1024.f);
    float inv = rsqrtf(var + 1e-5f);
    float4 g4 = reinterpret_cast<const float4*>(g)[t];
    float4 b4 = reinterpret_cast<const float4*>(b)[t];
    float4 o4;
    o4.x = dx * inv * g4.x + b4.x;
    o4.y = dy * inv * g4.y + b4.y;
    o4.z = dz * inv * g4.z + b4.z;
    o4.w = dw * inv * g4.w + b4.w;
    reinterpret_cast<float4*>(out + row * 1024)[t] = o4;
    if (of != nullptr) {
        reinterpret_cast<__half2*>(of + row * 1024)[2 * t] =
            __halves2half2(__float2half_rn(o4.x), __float2half_rn(o4.y));
        reinterpret_cast<__half2*>(of + row * 1024)[2 * t + 1] =
            __halves2half2(__float2half_rn(o4.z), __float2half_rn(o4.w));
    }
}

// ---------------------------------------------------------------------------
// Host orchestration
// ---------------------------------------------------------------------------
extern "C" void kernel_launch(void* const* d_in, const int* in_sizes, int n_in,
                              void* d_out, int out_size) {
    (void)in_sizes; (void)n_in; (void)out_size;
    const float* x    = (const float*)d_in[0];
    const float* Wqkv = (const float*)d_in[1];
    const float* bqkv = (const float*)d_in[2];
    const float* Wo   = (const float*)d_in[3];
    const float* bo   = (const float*)d_in[4];
    const float* W1   = (const float*)d_in[5];
    const float* b1   = (const float*)d_in[6];
    const float* W2   = (const float*)d_in[7];
    const float* b2   = (const float*)d_in[8];
    const float* ln1g = (const float*)d_in[9];
    const float* ln1b = (const float*)d_in[10];
    const float* ln2g = (const float*)d_in[11];
    const float* ln2b = (const float*)d_in[12];
    const float* lnfg = (const float*)d_in[13];
    const float* lnfb = (const float*)d_in[14];
    const float* Wout = (const float*)d_in[15];
    const float* bout = (const float*)d_in[16];
    float* out = (float*)d_out;

    float *h, *pe;
    __half *hf, *ff, *qvh, *wh, *wl, *tmph;
    cudaGetSymbolAddress((void**)&h,    g_h);
    cudaGetSymbolAddress((void**)&pe,   g_pe);
    cudaGetSymbolAddress((void**)&tmph, g_tmph);
    cudaGetSymbolAddress((void**)&hf,   g_hf);
    cudaGetSymbolAddress((void**)&ff,   g_ff);
    cudaGetSymbolAddress((void**)&qvh,  g_qkvh);
    cudaGetSymbolAddress((void**)&wh,   g_wh);
    cudaGetSymbolAddress((void**)&wl,   g_wl);

    cudaFuncSetAttribute(gemm_mma<0, 0, 1, 0>, cudaFuncAttributeMaxDynamicSharedMemorySize, GEMM_SMEM1);
    cudaFuncSetAttribute(gemm_mma<1, 0, 1, 0>, cudaFuncAttributeMaxDynamicSharedMemorySize, GEMM_SMEM1);
    cudaFuncSetAttribute(gemm_mma<0, 1, 0, 1>, cudaFuncAttributeMaxDynamicSharedMemorySize, GEMM_SMEM2);
    cudaFuncSetAttribute(attn_mma_kernel, cudaFuncAttributeMaxDynamicSharedMemorySize, ATTN_SMEM);

    cvt_split_all<<<(F4_ALL + 255) / 256, 256>>>(Wqkv, Wo, W1, W2, Wout, wh, wl);
    pe_table_kernel<<<(SSS * DDD) / 256, 256>>>(pe);
    add_pe_kernel<<<(TTT * DDD / 4) / 256, 256>>>(x, pe, h, hf);

    for (int l = 0; l < LLL; l++) {
        const __half* wq_h = wh + OFF_QKV + (size_t)l * 3145728;
        const __half* wo_h = wh + OFF_WO + (size_t)l * 1048576;
        const __half* w1_h = wh + OFF_W1 + (size_t)l * 2097152;
        const __half* w2_h = wh + OFF_W2 + (size_t)l * 2097152;

        // qkv (fp16) = h @ Wqkv^T + bqkv
        gemm_mma<0, 0, 1, 0><<<dim3(3072 / 128, TTT / 128), 256, GEMM_SMEM1>>>(
            hf, wq_h, nullptr, bqkv + (size_t)l * 3072, nullptr, qvh,
            TTT, 3072, 1024);
        // ctx (fp16) = flash attention
        attn_mma_kernel<<<dim3(SSS / 128, BBB * HHH), 256, ATTN_SMEM>>>(qvh, ff);
        // tmph (fp16) = ctx @ Wo^T + bo
        gemm_mma<0, 0, 1, 0><<<dim3(1024 / 128, TTT / 128), 256, GEMM_SMEM1>>>(
            ff, wo_h, nullptr, bo + (size_t)l * 1024, nullptr, tmph,
            TTT, 1024, 1024);
        // h = LN(h + tmph), emit fp16
        ln_kernel<<<TTT, 256>>>(h, tmph, ln1g + (size_t)l * 1024, ln1b + (size_t)l * 1024,
                                h, hf);
        // ff (fp16) = relu(h @ W1^T + b1)
        gemm_mma<1, 0, 1, 0><<<dim3(2048 / 128, TTT / 128), 256, GEMM_SMEM1>>>(
            hf, w1_h, nullptr, b1 + (size_t)l * 2048, nullptr, ff,
            TTT, 2048, 1024);
        // tmph (fp16) = ff @ W2^T + b2
        gemm_mma<0, 0, 1, 0><<<dim3(1024 / 128, TTT / 128), 256, GEMM_SMEM1>>>(
            ff, w2_h, nullptr, b2 + (size_t)l * 1024, nullptr, tmph,
            TTT, 1024, 2048);
        // h = LN(h + tmph), emit fp16
        ln_kernel<<<TTT, 256>>>(h, tmph, ln2g + (size_t)l * 1024, ln2b + (size_t)l * 1024,
                                h, hf);
    }

    ln_kernel<<<TTT, 256>>>(h, nullptr, lnfg, lnfb, h, hf);
    // out = h_final @ Wout^T + bout   [2-pass weights, fp32 out, fused transpose]
    gemm_mma<0, 1, 0, 1><<<dim3(DMEMM / 128, TTT / 128), 256, GEMM_SMEM2>>>(
        hf, wh + OFF_WOUT, wl + OFF_WOUT, bout, out, nullptr,
        TTT, DMEMM, 1024);
}

// round 13
// speedup vs baseline: 2.6617x; 1.0149x over previous
#include <cuda_runtime.h>
#include <cuda_fp16.h>
#include <math.h>
#include <stdint.h>

// Problem constants
#define BBB 32
#define SSS 512
#define DDD 1024
#define HHH 16
#define DHH 64
#define LLL 4
#define DFFF 2048
#define DMEMM 512
#define TTT (BBB * SSS)   // 16384 tokens

// ---------------------------------------------------------------------------
// Scratch (static device globals)
// ---------------------------------------------------------------------------
__device__ float g_h[(size_t)TTT * DDD];              //  64 MB residual fp32
__device__ float g_pe[(size_t)SSS * DDD];             //   2 MB
__device__ __half g_tmph[(size_t)TTT * DDD];          //  32 MB residual delta fp16
__device__ __half g_hf[(size_t)TTT * DDD];            //  32 MB activations fp16
__device__ __half g_ff[(size_t)TTT * DFFF];           //  64 MB ctx / ff fp16
__device__ __half g_qkvh[(size_t)TTT * 3 * DDD];      //  96 MB qkv fp16
#define WTOT 34078720ULL
__device__ __half g_wh[WTOT];                         //  68 MB weights fp16

#define OFF_QKV 0ULL
#define OFF_WO  12582912ULL
#define OFF_W1  16777216ULL
#define OFF_W2  25165824ULL
#define OFF_WOUT 33554432ULL

// ---------------------------------------------------------------------------
// PTX helpers (baseline sm_80+)
// ---------------------------------------------------------------------------
__device__ __forceinline__ uint32_t smem_u32(const void* p) {
    uint32_t a;
    asm("{ .reg .u64 t; cvta.to.shared.u64 t, %1; cvt.u32.u64 %0, t; }" : "=r"(a) : "l"(p));
    return a;
}

#define CP16(saddr, gptr) \
    asm volatile("cp.async.cg.shared.global [%0], [%1], 16;" :: "r"(saddr), "l"(gptr))
#define CPCOMMIT() asm volatile("cp.async.commit_group;" ::: "memory")
#define CPWAIT(n)  asm volatile("cp.async.wait_group %0;" :: "n"(n) : "memory")

#define LDSM4(r, addr)                                                          \
    asm volatile("ldmatrix.sync.aligned.m8n8.x4.shared.b16 {%0,%1,%2,%3}, [%4];" \
        : "=r"((r)[0]), "=r"((r)[1]), "=r"((r)[2]), "=r"((r)[3]) : "r"(addr))

#define LDSM4T(r, addr)                                                          \
    asm volatile("ldmatrix.sync.aligned.m8n8.x4.trans.shared.b16 {%0,%1,%2,%3}, [%4];" \
        : "=r"((r)[0]), "=r"((r)[1]), "=r"((r)[2]), "=r"((r)[3]) : "r"(addr))

#define MMA_F16(d, a, b0v, b1v)                                                 \
    asm volatile("mma.sync.aligned.m16n8k16.row.col.f32.f16.f16.f32 "           \
        "{%0,%1,%2,%3}, {%4,%5,%6,%7}, {%8,%9}, {%0,%1,%2,%3};"                 \
        : "+f"((d)[0]), "+f"((d)[1]), "+f"((d)[2]), "+f"((d)[3])                \
        : "r"((a)[0]), "r"((a)[1]), "r"((a)[2]), "r"((a)[3]), "r"(b0v), "r"(b1v))

#define EX2_H2(d, s) asm("ex2.approx.f16x2 %0, %1;" : "=r"(d) : "r"(s))

__device__ __forceinline__ uint32_t pack_h2(float a, float b) {
    uint32_t r;
    asm("cvt.rn.f16x2.f32 %0, %1, %2;" : "=r"(r) : "f"(b), "f"(a));
    return r;
}
__device__ __forceinline__ float2 unpack_h2(uint32_t u) {
    __half2 h = *reinterpret_cast<__half2*>(&u);
    return __half22float2(h);
}

// ---------------------------------------------------------------------------
// 0) merged weight convert (fp16), one launch
// ---------------------------------------------------------------------------
#define F4_QKV 3145728
#define F4_WO  (F4_QKV + 1048576)
#define F4_W1  (F4_WO + 2097152)
#define F4_W2  (F4_W1 + 2097152)
#define F4_ALL (F4_W2 + 131072)

__global__ __launch_bounds__(256)
void cvt_all(const float* __restrict__ Wqkv, const float* __restrict__ Wo,
             const float* __restrict__ W1, const float* __restrict__ W2,
             const float* __restrict__ Wout, __half* __restrict__ hi) {
    int i = blockIdx.x * 256 + threadIdx.x;
    if (i >= F4_ALL) return;
    const float* src;
    int li;
    if (i < F4_QKV)      { src = Wqkv; li = i; }
    else if (i < F4_WO)  { src = Wo;   li = i - F4_QKV; }
    else if (i < F4_W1)  { src = W1;   li = i - F4_WO; }
    else if (i < F4_W2)  { src = W2;   li = i - F4_W1; }
    else                 { src = Wout; li = i - F4_W2; }
    float4 v = reinterpret_cast<const float4*>(src)[li];
    reinterpret_cast<__half2*>(hi)[2 * i] =
        __halves2half2(__float2half_rn(v.x), __float2half_rn(v.y));
    reinterpret_cast<__half2*>(hi)[2 * i + 1] =
        __halves2half2(__float2half_rn(v.z), __float2half_rn(v.w));
}

// ---------------------------------------------------------------------------
// 1a) PE table
// ---------------------------------------------------------------------------
__global__ __launch_bounds__(256)
void pe_table_kernel(float* __restrict__ pe) {
    int idx = blockIdx.x * 256 + threadIdx.x;
    int d = idx & (DDD - 1);
    int s = idx >> 10;
    float div = expf((float)(d & ~1) * (-9.2103403719761836f / (float)DDD));
    float ang = (float)s * div;
    pe[idx] = (d & 1) ? cosf(ang) : sinf(ang);
}

// ---------------------------------------------------------------------------
// 1b) h[s,b,:] = x[b,s,:] + PE[s,:]   (+ fp16 emit)
// ---------------------------------------------------------------------------
__global__ __launch_bounds__(256)
void add_pe_kernel(const float* __restrict__ x, const float* __restrict__ pe,
                   float* __restrict__ h, __half* __restrict__ hf) {
    int i4 = blockIdx.x * 256 + threadIdx.x;
    int d4  = i4 & 255;
    int row = i4 >> 8;
    int s   = row >> 5;
    int b   = row & 31;
    float4 xv = reinterpret_cast<const float4*>(x)[((size_t)(b * SSS + s) << 8) + d4];
    float4 pv = reinterpret_cast<const float4*>(pe)[((size_t)s << 8) + d4];
    float4 v;
    v.x = xv.x + pv.x; v.y = xv.y + pv.y; v.z = xv.z + pv.z; v.w = xv.w + pv.w;
    reinterpret_cast<float4*>(h)[i4] = v;
    reinterpret_cast<__half2*>(hf)[2 * i4] =
        __halves2half2(__float2half_rn(v.x), __float2half_rn(v.y));
    reinterpret_cast<__half2*>(hf)[2 * i4 + 1] =
        __halves2half2(__float2half_rn(v.z), __float2half_rn(v.w));
}

// ---------------------------------------------------------------------------
// 2) HMMA GEMM, fp16, BK=64, 3-stage cp.async pipeline.
//    C = A @ Wh^T + bias.  OUTMODE: 0 = float C, 1 = fp16 Ch.
//    Inner loop restructured: fb held, fa streamed per-mi (low live regs).
// ---------------------------------------------------------------------------
#define SROWB 144
#define SEG_B 18432u                    // one 128x64 fp16 buffer (padded)
#define STG_B 36864u                    // stage (A + W)
#define GEMM_SMEM (3 * 36864)

template <int PERM>
__device__ __forceinline__ void load_stage(
    uint32_t sbase, const __half* __restrict__ A, const __half* __restrict__ Wh,
    int m0, int n0, int K, int k0, int t) {
#pragma unroll
    for (int i = 0; i < 8; ++i) {
        int u = t + i * 256;                 // 0..2047
        int sel = u >> 10;                   // 0 A, 1 Wh
        int v = u & 1023;
        int row = v >> 3, seg = v & 7;
        const __half* src;
        if (sel == 0) {
            int garow = m0 + row;
            if (PERM) garow = ((garow & 511) << 5) | (garow >> 9);
            src = A + (size_t)garow * K + k0 + seg * 8;
        } else {
            src = Wh + (size_t)(n0 + row) * K + k0 + seg * 8;
        }
        uint32_t dst = sbase + (uint32_t)sel * SEG_B + (uint32_t)(row * SROWB + seg * 16);
        CP16(dst, src);
    }
}

template <int RELU, int PERM, int OUTMODE>
__global__ __launch_bounds__(256, 2)
void gemm_mma(const __half* __restrict__ A, const __half* __restrict__ Wh,
              const float* __restrict__ bias, float* __restrict__ C,
              __half* __restrict__ Ch,
              int M, int N, int K) {
    extern __shared__ char smem[];
    const uint32_t sb = smem_u32(smem);
    const int t    = threadIdx.x;
    const int lane = t & 31;
    const int w    = t >> 5;
    const int wm   = w & 1;
    const int wn   = w >> 1;
    const int m0   = blockIdx.y * 128;
    const int n0   = blockIdx.x * 128;

    float acc[4][4][4];
#pragma unroll
    for (int a = 0; a < 4; a++)
#pragma unroll
        for (int b = 0; b < 4; b++)
#pragma unroll
            for (int c = 0; c < 4; c++) acc[a][b][c] = 0.f;

    const uint32_t a_off = (uint32_t)((wm * 64 + (lane & 15)) * SROWB + (lane >> 4) * 16);
    const int brow = wn * 32 + (lane & 7) + ((lane & 16) >> 1);
    const uint32_t b_off = (uint32_t)(brow * SROWB + ((lane >> 3) & 1) * 16);

    const int NC = K >> 6;              // chunks of 64
    load_stage<PERM>(sb, A, Wh, m0, n0, K, 0, t);
    CPCOMMIT();
    if (NC > 1) {
        load_stage<PERM>(sb + STG_B, A, Wh, m0, n0, K, 64, t);
    }
    CPCOMMIT();

    int buf = 0;
    for (int c = 0; c < NC; ++c) {
        CPWAIT(1);                       // chunk c's group complete
        __syncthreads();
        if (c + 2 < NC) {
            int nb = buf + 2; if (nb >= 3) nb -= 3;
            load_stage<PERM>(sb + (uint32_t)nb * STG_B, A, Wh, m0, n0, K,
                             (c + 2) << 6, t);
        }
        CPCOMMIT();                      // keep group count in lockstep
        const uint32_t stb = sb + (uint32_t)buf * STG_B;
#pragma unroll
        for (int ks = 0; ks < 4; ++ks) {
            const uint32_t ao = stb + a_off + ks * 32;
            const uint32_t bo = stb + SEG_B + b_off + ks * 32;
            uint32_t fb0[4], fb1[4];
            LDSM4(fb0, bo);
            LDSM4(fb1, bo + 16 * SROWB);
#pragma unroll
            for (int mi = 0; mi < 4; ++mi) {
                uint32_t fa[4];
                LDSM4(fa, ao + mi * (16 * SROWB));
                MMA_F16(acc[mi][0], fa, fb0[0], fb0[1]);
                MMA_F16(acc[mi][1], fa, fb0[2], fb0[3]);
                MMA_F16(acc[mi][2], fa, fb1[0], fb1[1]);
                MMA_F16(acc[mi][3], fa, fb1[2], fb1[3]);
            }
        }
        if (++buf == 3) buf = 0;
    }

    const int qrow = lane >> 2;
    const int qcol = (lane & 3) * 2;
#pragma unroll
    for (int mi = 0; mi < 4; ++mi) {
        const int row0 = m0 + wm * 64 + mi * 16 + qrow;
#pragma unroll
        for (int ni = 0; ni < 4; ++ni) {
            const int col = n0 + wn * 32 + ni * 8 + qcol;
            const float bb0 = bias[col];
            const float bb1 = bias[col + 1];
            float v00 = acc[mi][ni][0] + bb0;
            float v01 = acc[mi][ni][1] + bb1;
            float v10 = acc[mi][ni][2] + bb0;
            float v11 = acc[mi][ni][3] + bb1;
            if (RELU) {
                v00 = fmaxf(v00, 0.f); v01 = fmaxf(v01, 0.f);
                v10 = fmaxf(v10, 0.f); v11 = fmaxf(v11, 0.f);
            }
            if (OUTMODE == 0) {
                *reinterpret_cast<float2*>(C + (size_t)row0 * N + col) =
                    make_float2(v00, v01);
                *reinterpret_cast<float2*>(C + (size_t)(row0 + 8) * N + col) =
                    make_float2(v10, v11);
            } else {
                *reinterpret_cast<__half2*>(Ch + (size_t)row0 * N + col) =
                    __halves2half2(__float2half_rn(v00), __float2half_rn(v01));
                *reinterpret_cast<__half2*>(Ch + (size_t)(row0 + 8) * N + col) =
                    __halves2half2(__float2half_rn(v10), __float2half_rn(v11));
            }
        }
    }
}

// ---------------------------------------------------------------------------
// 3) HMMA flash attention, all-fp16 single-pass, base-2 softmax (ex2.f16x2)
// ---------------------------------------------------------------------------
#define AROWB 144
#define AQ_OFF 0u
#define AST0   18432u
#define ASTG   18432u
#define AK_OFF 0u
#define AV_OFF 9216u
#define ATTN_SMEM (18432 + 2 * 18432)
// 0.125 (1/sqrt(64)) * log2(e)
#define C_SCALE 0.18033688011112042f

__device__ __forceinline__ void attn_load_kv(
    uint32_t sbase, const __half* __restrict__ qkv, int b, int hd, int kt, int t) {
#pragma unroll
    for (int i = 0; i < 4; ++i) {
        int u = t + i * 256;             // 0..1023
        int sel = u >> 9;                // 0 K, 1 V
        int v = u & 511;
        int row = v >> 3, seg = v & 7;
        int off = sel ? 2048 : 1024;
        const __half* src =
            qkv + ((size_t)((kt * 64 + row) * BBB + b)) * 3072 + off + hd + seg * 8;
        uint32_t dst = sbase + (uint32_t)sel * 9216u + (uint32_t)(row * AROWB + seg * 16);
        CP16(dst, src);
    }
}

__global__ __launch_bounds__(256, 2)
void attn_mma_kernel(const __half* __restrict__ qkv, __half* __restrict__ ctx) {
    extern __shared__ char smem[];
    const uint32_t sb = smem_u32(smem);
    const int t    = threadIdx.x;
    const int lane = t & 31;
    const int w    = t >> 5;
    const int b    = blockIdx.y >> 4;
    const int h    = blockIdx.y & 15;
    const int q0   = blockIdx.x * 128;
    const int hd   = h * DHH;

    // load Q (128 x 64 fp16)
#pragma unroll
    for (int i = 0; i < 4; ++i) {
        int u = t + i * 256;
        int row = u >> 3, seg = u & 7;
        const __half* src = qkv + ((size_t)((q0 + row) * BBB + b)) * 3072 + hd + seg * 8;
        uint32_t dst = sb + AQ_OFF + (uint32_t)(row * AROWB + seg * 16);
        CP16(dst, src);
    }
    CPCOMMIT();
    attn_load_kv(sb + AST0, qkv, b, hd, 0, t);
    CPCOMMIT();

    float Oa[8][4];
#pragma unroll
    for (int j = 0; j < 8; j++)
#pragma unroll
        for (int c = 0; c < 4; c++) Oa[j][c] = 0.f;
    float m0r = -1e30f, m1r = -1e30f, l0r = 0.f, l1r = 0.f;

    const uint32_t arow_off = (uint32_t)((w * 16 + (lane & 15)) * AROWB + (lane >> 4) * 16);
    const uint32_t brow_off = (uint32_t)(((lane & 7) + ((lane & 16) >> 1)) * AROWB +
                                         ((lane >> 3) & 1) * 16);
    const uint32_t vrow_off = (uint32_t)((lane & 15) * AROWB + (lane >> 4) * 16);

    for (int kt = 0; kt < 8; ++kt) {
        CPWAIT(0);
        __syncthreads();
        if (kt + 1 < 8) {
            attn_load_kv(sb + AST0 + (uint32_t)((kt + 1) & 1) * ASTG, qkv, b, hd,
                         kt + 1, t);
            CPCOMMIT();
        }
        const uint32_t stg = sb + AST0 + (uint32_t)(kt & 1) * ASTG;

        // ---- S = Q K^T ----
        float st[8][4];
#pragma unroll
        for (int j = 0; j < 8; j++)
#pragma unroll
            for (int c = 0; c < 4; c++) st[j][c] = 0.f;
#pragma unroll
        for (int kc = 0; kc < 4; ++kc) {
            uint32_t fa[4];
            LDSM4(fa, sb + AQ_OFF + arow_off + kc * 32);
#pragma unroll
            for (int g = 0; g < 4; ++g) {
                uint32_t fb[4];
                LDSM4(fb, stg + AK_OFF + brow_off + g * (16 * AROWB) + kc * 32);
                MMA_F16(st[2 * g],     fa, fb[0], fb[1]);
                MMA_F16(st[2 * g + 1], fa, fb[2], fb[3]);
            }
        }

        // ---- online softmax in base-2 ----
        float mx0 = -1e30f, mx1 = -1e30f;
#pragma unroll
        for (int j = 0; j < 8; j++) {
            st[j][0] *= C_SCALE; st[j][1] *= C_SCALE;
            st[j][2] *= C_SCALE; st[j][3] *= C_SCALE;
            mx0 = fmaxf(mx0, fmaxf(st[j][0], st[j][1]));
            mx1 = fmaxf(mx1, fmaxf(st[j][2], st[j][3]));
        }
        mx0 = fmaxf(mx0, __shfl_xor_sync(0xffffffffu, mx0, 1));
        mx0 = fmaxf(mx0, __shfl_xor_sync(0xffffffffu, mx0, 2));
        mx1 = fmaxf(mx1, __shfl_xor_sync(0xffffffffu, mx1, 1));
        mx1 = fmaxf(mx1, __shfl_xor_sync(0xffffffffu, mx1, 2));
        const float nm0 = fmaxf(m0r, mx0), nm1 = fmaxf(m1r, mx1);
        const float al0 = exp2f(m0r - nm0), al1 = exp2f(m1r - nm1);

        uint32_t pp[8][2];
        float s0 = 0.f, s1 = 0.f;
#pragma unroll
        for (int j = 0; j < 8; j++) {
            uint32_t q0p = pack_h2(st[j][0] - nm0, st[j][1] - nm0);
            uint32_t q1p = pack_h2(st[j][2] - nm1, st[j][3] - nm1);
            EX2_H2(pp[j][0], q0p);
            EX2_H2(pp[j][1], q1p);
            float2 v0 = unpack_h2(pp[j][0]);
            float2 v1 = unpack_h2(pp[j][1]);
            s0 += v0.x + v0.y;
            s1 += v1.x + v1.y;
        }
        s0 += __shfl_xor_sync(0xffffffffu, s0, 1);
        s0 += __shfl_xor_sync(0xffffffffu, s0, 2);
        s1 += __shfl_xor_sync(0xffffffffu, s1, 1);
        s1 += __shfl_xor_sync(0xffffffffu, s1, 2);
        l0r = l0r * al0 + s0;
        l1r = l1r * al1 + s1;
        m0r = nm0; m1r = nm1;
#pragma unroll
        for (int j = 0; j < 8; j++) {
            Oa[j][0] *= al0; Oa[j][1] *= al0;
            Oa[j][2] *= al1; Oa[j][3] *= al1;
        }

        // ---- O += P V ----
#pragma unroll
        for (int kc = 0; kc < 4; ++kc) {
            uint32_t ph[4];
            ph[0] = pp[2 * kc][0];
            ph[1] = pp[2 * kc][1];
            ph[2] = pp[2 * kc + 1][0];
            ph[3] = pp[2 * kc + 1][1];
            const uint32_t vbase = stg + AV_OFF + (uint32_t)(kc * 16 * AROWB) + vrow_off;
#pragma unroll
            for (int g = 0; g < 4; ++g) {
                uint32_t fv[4];
                LDSM4T(fv, vbase + g * 32);
                MMA_F16(Oa[2 * g],     ph, fv[0], fv[1]);
                MMA_F16(Oa[2 * g + 1], ph, fv[2], fv[3]);
            }
        }
    }

    // ---- epilogue: ctx (single fp16) ----
    const float inv0 = 1.f / l0r;
    const float inv1 = 1.f / l1r;
    const int r_lo = q0 + w * 16 + (lane >> 2);
    const int col0 = hd + (lane & 3) * 2;
#pragma unroll
    for (int j = 0; j < 8; j++) {
        const int col = col0 + j * 8;
        size_t o0 = ((size_t)(r_lo * BBB + b)) * 1024 + col;
        size_t o1 = ((size_t)((r_lo + 8) * BBB + b)) * 1024 + col;
        *reinterpret_cast<__half2*>(ctx + o0) =
            __halves2half2(__float2half_rn(Oa[j][0] * inv0),
                           __float2half_rn(Oa[j][1] * inv0));
        *reinterpret_cast<__half2*>(ctx + o1) =
            __halves2half2(__float2half_rn(Oa[j][2] * inv1),
                           __float2half_rn(Oa[j][3] * inv1));
    }
}

// ---------------------------------------------------------------------------
// 4) LayerNorm: out = LN(a + r_fp16) * g + b   (+ fp16 emit)
// ---------------------------------------------------------------------------
__global__ __launch_bounds__(256)
void ln_kernel(const float* __restrict__ a, const __half* __restrict__ r,
               const float* __restrict__ g, const float* __restrict__ b,
               float* __restrict__ out, __half* __restrict__ of) {
    __shared__ float red1[8];
    __shared__ float red2[8];
    const int t = threadIdx.x;
    const int lane = t & 31;
    const int w = t >> 5;
    const size_t row = blockIdx.x;
    float4 v = reinterpret_cast<const float4*>(a + row * 1024)[t];
    if (r != nullptr) {
        __half2 r0 = reinterpret_cast<const __half2*>(r + row * 1024)[2 * t];
        __half2 r1 = reinterpret_cast<const __half2*>(r + row * 1024)[2 * t + 1];
        float2 f0 = __half22float2(r0);
        float2 f1 = __half22float2(r1);
        v.x += f0.x; v.y += f0.y; v.z += f1.x; v.w += f1.y;
    }
    float s = v.x + v.y + v.z + v.w;
#pragma unroll
    for (int o = 16; o > 0; o >>= 1) s += __shfl_xor_sync(0xffffffffu, s, o);
    if (lane == 0) red1[w] = s;
    __syncthreads();
    float mu = (red1[0] + red1[1] + red1[2] + red1[3] +
                red1[4] + red1[5] + red1[6] + red1[7]) * (1.f / 1024.f);
    float dx = v.x - mu, dy = v.y - mu, dz = v.z - mu, dw = v.w - mu;
    float q = dx * dx + dy * dy + dz * dz + dw * dw;
#pragma unroll
    for (int o = 16; o > 0; o >>= 1) q += __shfl_xor_sync(0xffffffffu, q, o);
    if (lane == 0) red2[w] = q;
    __syncthreads();
    float var = (red2[0] + red2[1] + red2[2] + red2[3] +
                 red2[4] + red2[5] + red2[6] + red2[7]) * (1.f / 1024.f);
    float inv = rsqrtf(var + 1e-5f);
    float4 g4 = reinterpret_cast<const float4*>(g)[t];
    float4 b4 = reinterpret_cast<const float4*>(b)[t];
    float4 o4;
    o4.x = dx * inv * g4.x + b4.x;
    o4.y = dy * inv * g4.y + b4.y;
    o4.z = dz * inv * g4.z + b4.z;
    o4.w = dw * inv * g4.w + b4.w;
    reinterpret_cast<float4*>(out + row * 1024)[t] = o4;
    if (of != nullptr) {
        reinterpret_cast<__half2*>(of + row * 1024)[2 * t] =
            __halves2half2(__float2half_rn(o4.x), __float2half_rn(o4.y));
        reinterpret_cast<__half2*>(of + row * 1024)[2 * t + 1] =
            __halves2half2(__float2half_rn(o4.z), __float2half_rn(o4.w));
    }
}

// ---------------------------------------------------------------------------
// Host orchestration
// ---------------------------------------------------------------------------
extern "C" void kernel_launch(void* const* d_in, const int* in_sizes, int n_in,
                              void* d_out, int out_size) {
    (void)in_sizes; (void)n_in; (void)out_size;
    const float* x    = (const float*)d_in[0];
    const float* Wqkv = (const float*)d_in[1];
    const float* bqkv = (const float*)d_in[2];
    const float* Wo   = (const float*)d_in[3];
    const float* bo   = (const float*)d_in[4];
    const float* W1   = (const float*)d_in[5];
    const float* b1   = (const float*)d_in[6];
    const float* W2   = (const float*)d_in[7];
    const float* b2   = (const float*)d_in[8];
    const float* ln1g = (const float*)d_in[9];
    const float* ln1b = (const float*)d_in[10];
    const float* ln2g = (const float*)d_in[11];
    const float* ln2b = (const float*)d_in[12];
    const float* lnfg = (const float*)d_in[13];
    const float* lnfb = (const float*)d_in[14];
    const float* Wout = (const float*)d_in[15];
    const float* bout = (const float*)d_in[16];
    float* out = (float*)d_out;

    float *h, *pe;
    __half *hf, *ff, *qvh, *wh, *tmph;
    cudaGetSymbolAddress((void**)&h,    g_h);
    cudaGetSymbolAddress((void**)&pe,   g_pe);
    cudaGetSymbolAddress((void**)&tmph, g_tmph);
    cudaGetSymbolAddress((void**)&hf,   g_hf);
    cudaGetSymbolAddress((void**)&ff,   g_ff);
    cudaGetSymbolAddress((void**)&qvh,  g_qkvh);
    cudaGetSymbolAddress((void**)&wh,   g_wh);

    cudaFuncSetAttribute(gemm_mma<0, 0, 1>, cudaFuncAttributeMaxDynamicSharedMemorySize, GEMM_SMEM);
    cudaFuncSetAttribute(gemm_mma<1, 0, 1>, cudaFuncAttributeMaxDynamicSharedMemorySize, GEMM_SMEM);
    cudaFuncSetAttribute(gemm_mma<0, 1, 0>, cudaFuncAttributeMaxDynamicSharedMemorySize, GEMM_SMEM);
    cudaFuncSetAttribute(attn_mma_kernel, cudaFuncAttributeMaxDynamicSharedMemorySize, ATTN_SMEM);

    cvt_all<<<(F4_ALL + 255) / 256, 256>>>(Wqkv, Wo, W1, W2, Wout, wh);
    pe_table_kernel<<<(SSS * DDD) / 256, 256>>>(pe);
    add_pe_kernel<<<(TTT * DDD / 4) / 256, 256>>>(x, pe, h, hf);

    for (int l = 0; l < LLL; l++) {
        const __half* wq_h = wh + OFF_QKV + (size_t)l * 3145728;
        const __half* wo_h = wh + OFF_WO + (size_t)l * 1048576;
        const __half* w1_h = wh + OFF_W1 + (size_t)l * 2097152;
        const __half* w2_h = wh + OFF_W2 + (size_t)l * 2097152;

        // qkv (fp16) = h @ Wqkv^T + bqkv
        gemm_mma<0, 0, 1><<<dim3(3072 / 128, TTT / 128), 256, GEMM_SMEM>>>(
            hf, wq_h, bqkv + (size_t)l * 3072, nullptr, qvh, TTT, 3072, 1024);
        // ctx (fp16) = flash attention
        attn_mma_kernel<<<dim3(SSS / 128, BBB * HHH), 256, ATTN_SMEM>>>(qvh, ff);
        // tmph (fp16) = ctx @ Wo^T + bo
        gemm_mma<0, 0, 1><<<dim3(1024 / 128, TTT / 128), 256, GEMM_SMEM>>>(
            ff, wo_h, bo + (size_t)l * 1024, nullptr, tmph, TTT, 1024, 1024);
        // h = LN(h + tmph), emit fp16
        ln_kernel<<<TTT, 256>>>(h, tmph, ln1g + (size_t)l * 1024, ln1b + (size_t)l * 1024,
                                h, hf);
        // ff (fp16) = relu(h @ W1^T + b1)
        gemm_mma<1, 0, 1><<<dim3(2048 / 128, TTT / 128), 256, GEMM_SMEM>>>(
            hf, w1_h, b1 + (size_t)l * 2048, nullptr, ff, TTT, 2048, 1024);
        // tmph (fp16) = ff @ W2^T + b2
        gemm_mma<0, 0, 1><<<dim3(1024 / 128, TTT / 128), 256, GEMM_SMEM>>>(
            ff, w2_h, b2 + (size_t)l * 1024, nullptr, tmph, TTT, 1024, 2048);
        // h = LN(h + tmph), emit fp16
        ln_kernel<<<TTT, 256>>>(h, tmph, ln2g + (size_t)l * 1024, ln2b + (size_t)l * 1024,
                                h, hf);
    }

    ln_kernel<<<TTT, 256>>>(h, nullptr, lnfg, lnfb, h, hf);
    // out = h_final @ Wout^T + bout   [fp32 out, fused transpose]
    gemm_mma<0, 1, 0><<<dim3(DMEMM / 128, TTT / 128), 256, GEMM_SMEM>>>(
        hf, wh + OFF_WOUT, bout, out, nullptr, TTT, DMEMM, 1024);
}

// round 14
// speedup vs baseline: 2.7086x; 1.0176x over previous
#include <cuda_runtime.h>
#include <cuda_fp16.h>
#include <math.h>
#include <stdint.h>

// Problem constants
#define BBB 32
#define SSS 512
#define DDD 1024
#define HHH 16
#define DHH 64
#define LLL 4
#define DFFF 2048
#define DMEMM 512
#define TTT (BBB * SSS)   // 16384 tokens

// ---------------------------------------------------------------------------
// Scratch (static device globals)
// ---------------------------------------------------------------------------
__device__ float g_pe[(size_t)SSS * DDD];             //   2 MB
__device__ __half g_tmph[(size_t)TTT * DDD];          //  32 MB residual delta fp16
__device__ __half g_hf[(size_t)TTT * DDD];            //  32 MB residual fp16
__device__ __half g_ff[(size_t)TTT * DFFF];           //  64 MB ctx / ff fp16
__device__ __half g_qkvh[(size_t)TTT * 3 * DDD];      //  96 MB qkv fp16
#define WTOT 34078720ULL
__device__ __half g_wh[WTOT];                         //  68 MB weights fp16

#define OFF_QKV 0ULL
#define OFF_WO  12582912ULL
#define OFF_W1  16777216ULL
#define OFF_W2  25165824ULL
#define OFF_WOUT 33554432ULL

// ---------------------------------------------------------------------------
// PTX helpers (baseline sm_80+)
// ---------------------------------------------------------------------------
__device__ __forceinline__ uint32_t smem_u32(const void* p) {
    uint32_t a;
    asm("{ .reg .u64 t; cvta.to.shared.u64 t, %1; cvt.u32.u64 %0, t; }" : "=r"(a) : "l"(p));
    return a;
}

#define CP16(saddr, gptr) \
    asm volatile("cp.async.cg.shared.global [%0], [%1], 16;" :: "r"(saddr), "l"(gptr))
#define CPCOMMIT() asm volatile("cp.async.commit_group;" ::: "memory")
#define CPWAIT(n)  asm volatile("cp.async.wait_group %0;" :: "n"(n) : "memory")

#define LDSM4(r, addr)                                                          \
    asm volatile("ldmatrix.sync.aligned.m8n8.x4.shared.b16 {%0,%1,%2,%3}, [%4];" \
        : "=r"((r)[0]), "=r"((r)[1]), "=r"((r)[2]), "=r"((r)[3]) : "r"(addr))

#define LDSM4T(r, addr)                                                          \
    asm volatile("ldmatrix.sync.aligned.m8n8.x4.trans.shared.b16 {%0,%1,%2,%3}, [%4];" \
        : "=r"((r)[0]), "=r"((r)[1]), "=r"((r)[2]), "=r"((r)[3]) : "r"(addr))

#define MMA_F16(d, a, b0v, b1v)                                                 \
    asm volatile("mma.sync.aligned.m16n8k16.row.col.f32.f16.f16.f32 "           \
        "{%0,%1,%2,%3}, {%4,%5,%6,%7}, {%8,%9}, {%0,%1,%2,%3};"                 \
        : "+f"((d)[0]), "+f"((d)[1]), "+f"((d)[2]), "+f"((d)[3])                \
        : "r"((a)[0]), "r"((a)[1]), "r"((a)[2]), "r"((a)[3]), "r"(b0v), "r"(b1v))

#define EX2_H2(d, s) asm("ex2.approx.f16x2 %0, %1;" : "=r"(d) : "r"(s))

__device__ __forceinline__ uint32_t pack_h2(float a, float b) {
    uint32_t r;
    asm("cvt.rn.f16x2.f32 %0, %1, %2;" : "=r"(r) : "f"(b), "f"(a));
    return r;
}
__device__ __forceinline__ float2 unpack_h2(uint32_t u) {
    __half2 h = *reinterpret_cast<__half2*>(&u);
    return __half22float2(h);
}

// ---------------------------------------------------------------------------
// 0) merged weight convert (fp16), one launch
// ---------------------------------------------------------------------------
#define F4_QKV 3145728
#define F4_WO  (F4_QKV + 1048576)
#define F4_W1  (F4_WO + 2097152)
#define F4_W2  (F4_W1 + 2097152)
#define F4_ALL (F4_W2 + 131072)

__global__ __launch_bounds__(256)
void cvt_all(const float* __restrict__ Wqkv, const float* __restrict__ Wo,
             const float* __restrict__ W1, const float* __restrict__ W2,
             const float* __restrict__ Wout, __half* __restrict__ hi) {
    int i = blockIdx.x * 256 + threadIdx.x;
    if (i >= F4_ALL) return;
    const float* src;
    int li;
    if (i < F4_QKV)      { src = Wqkv; li = i; }
    else if (i < F4_WO)  { src = Wo;   li = i - F4_QKV; }
    else if (i < F4_W1)  { src = W1;   li = i - F4_WO; }
    else if (i < F4_W2)  { src = W2;   li = i - F4_W1; }
    else                 { src = Wout; li = i - F4_W2; }
    float4 v = reinterpret_cast<const float4*>(src)[li];
    reinterpret_cast<__half2*>(hi)[2 * i] =
        __halves2half2(__float2half_rn(v.x), __float2half_rn(v.y));
    reinterpret_cast<__half2*>(hi)[2 * i + 1] =
        __halves2half2(__float2half_rn(v.z), __float2half_rn(v.w));
}

// ---------------------------------------------------------------------------
// 1a) PE table
// ---------------------------------------------------------------------------
__global__ __launch_bounds__(256)
void pe_table_kernel(float* __restrict__ pe) {
    int idx = blockIdx.x * 256 + threadIdx.x;
    int d = idx & (DDD - 1);
    int s = idx >> 10;
    float div = expf((float)(d & ~1) * (-9.2103403719761836f / (float)DDD));
    float ang = (float)s * div;
    pe[idx] = (d & 1) ? cosf(ang) : sinf(ang);
}

// ---------------------------------------------------------------------------
// 1b) hf[s,b,:] = fp16(x[b,s,:] + PE[s,:])
// ---------------------------------------------------------------------------
__global__ __launch_bounds__(256)
void add_pe_kernel(const float* __restrict__ x, const float* __restrict__ pe,
                   __half* __restrict__ hf) {
    int i4 = blockIdx.x * 256 + threadIdx.x;
    int d4  = i4 & 255;
    int row = i4 >> 8;
    int s   = row >> 5;
    int b   = row & 31;
    float4 xv = reinterpret_cast<const float4*>(x)[((size_t)(b * SSS + s) << 8) + d4];
    float4 pv = reinterpret_cast<const float4*>(pe)[((size_t)s << 8) + d4];
    reinterpret_cast<__half2*>(hf)[2 * i4] =
        __halves2half2(__float2half_rn(xv.x + pv.x), __float2half_rn(xv.y + pv.y));
    reinterpret_cast<__half2*>(hf)[2 * i4 + 1] =
        __halves2half2(__float2half_rn(xv.z + pv.z), __float2half_rn(xv.w + pv.w));
}

// ---------------------------------------------------------------------------
// 2) HMMA GEMM, fp16, BK=64, 3-stage cp.async pipeline.
//    C = A @ Wh^T + bias.  OUTMODE: 0 = float C, 1 = fp16 Ch.
// ---------------------------------------------------------------------------
#define SROWB 144
#define SEG_B 18432u
#define STG_B 36864u
#define GEMM_SMEM (3 * 36864)

template <int PERM>
__device__ __forceinline__ void load_stage(
    uint32_t sbase, const __half* __restrict__ A, const __half* __restrict__ Wh,
    int m0, int n0, int K, int k0, int t) {
#pragma unroll
    for (int i = 0; i < 8; ++i) {
        int u = t + i * 256;
        int sel = u >> 10;                   // 0 A, 1 Wh
        int v = u & 1023;
        int row = v >> 3, seg = v & 7;
        const __half* src;
        if (sel == 0) {
            int garow = m0 + row;
            if (PERM) garow = ((garow & 511) << 5) | (garow >> 9);
            src = A + (size_t)garow * K + k0 + seg * 8;
        } else {
            src = Wh + (size_t)(n0 + row) * K + k0 + seg * 8;
        }
        uint32_t dst = sbase + (uint32_t)sel * SEG_B + (uint32_t)(row * SROWB + seg * 16);
        CP16(dst, src);
    }
}

template <int RELU, int PERM, int OUTMODE>
__global__ __launch_bounds__(256, 2)
void gemm_mma(const __half* __restrict__ A, const __half* __restrict__ Wh,
              const float* __restrict__ bias, float* __restrict__ C,
              __half* __restrict__ Ch,
              int M, int N, int K) {
    extern __shared__ char smem[];
    const uint32_t sb = smem_u32(smem);
    const int t    = threadIdx.x;
    const int lane = t & 31;
    const int w    = t >> 5;
    const int wm   = w & 1;
    const int wn   = w >> 1;
    const int m0   = blockIdx.y * 128;
    const int n0   = blockIdx.x * 128;

    float acc[4][4][4];
#pragma unroll
    for (int a = 0; a < 4; a++)
#pragma unroll
        for (int b = 0; b < 4; b++)
#pragma unroll
            for (int c = 0; c < 4; c++) acc[a][b][c] = 0.f;

    const uint32_t a_off = (uint32_t)((wm * 64 + (lane & 15)) * SROWB + (lane >> 4) * 16);
    const int brow = wn * 32 + (lane & 7) + ((lane & 16) >> 1);
    const uint32_t b_off = (uint32_t)(brow * SROWB + ((lane >> 3) & 1) * 16);

    const int NC = K >> 6;
    load_stage<PERM>(sb, A, Wh, m0, n0, K, 0, t);
    CPCOMMIT();
    if (NC > 1) {
        load_stage<PERM>(sb + STG_B, A, Wh, m0, n0, K, 64, t);
    }
    CPCOMMIT();

    int buf = 0;
    for (int c = 0; c < NC; ++c) {
        CPWAIT(1);
        __syncthreads();
        if (c + 2 < NC) {
            int nb = buf + 2; if (nb >= 3) nb -= 3;
            load_stage<PERM>(sb + (uint32_t)nb * STG_B, A, Wh, m0, n0, K,
                             (c + 2) << 6, t);
        }
        CPCOMMIT();
        const uint32_t stb = sb + (uint32_t)buf * STG_B;
#pragma unroll
        for (int ks = 0; ks < 4; ++ks) {
            const uint32_t ao = stb + a_off + ks * 32;
            const uint32_t bo = stb + SEG_B + b_off + ks * 32;
            uint32_t fb0[4], fb1[4];
            LDSM4(fb0, bo);
            LDSM4(fb1, bo + 16 * SROWB);
#pragma unroll
            for (int mi = 0; mi < 4; ++mi) {
                uint32_t fa[4];
                LDSM4(fa, ao + mi * (16 * SROWB));
                MMA_F16(acc[mi][0], fa, fb0[0], fb0[1]);
                MMA_F16(acc[mi][1], fa, fb0[2], fb0[3]);
                MMA_F16(acc[mi][2], fa, fb1[0], fb1[1]);
                MMA_F16(acc[mi][3], fa, fb1[2], fb1[3]);
            }
        }
        if (++buf == 3) buf = 0;
    }

    const int qrow = lane >> 2;
    const int qcol = (lane & 3) * 2;
#pragma unroll
    for (int mi = 0; mi < 4; ++mi) {
        const int row0 = m0 + wm * 64 + mi * 16 + qrow;
#pragma unroll
        for (int ni = 0; ni < 4; ++ni) {
            const int col = n0 + wn * 32 + ni * 8 + qcol;
            const float bb0 = bias[col];
            const float bb1 = bias[col + 1];
            float v00 = acc[mi][ni][0] + bb0;
            float v01 = acc[mi][ni][1] + bb1;
            float v10 = acc[mi][ni][2] + bb0;
            float v11 = acc[mi][ni][3] + bb1;
            if (RELU) {
                v00 = fmaxf(v00, 0.f); v01 = fmaxf(v01, 0.f);
                v10 = fmaxf(v10, 0.f); v11 = fmaxf(v11, 0.f);
            }
            if (OUTMODE == 0) {
                *reinterpret_cast<float2*>(C + (size_t)row0 * N + col) =
                    make_float2(v00, v01);
                *reinterpret_cast<float2*>(C + (size_t)(row0 + 8) * N + col) =
                    make_float2(v10, v11);
            } else {
                *reinterpret_cast<__half2*>(Ch + (size_t)row0 * N + col) =
                    __halves2half2(__float2half_rn(v00), __float2half_rn(v01));
                *reinterpret_cast<__half2*>(Ch + (size_t)(row0 + 8) * N + col) =
                    __halves2half2(__float2half_rn(v10), __float2half_rn(v11));
            }
        }
    }
}

// ---------------------------------------------------------------------------
// 3) HMMA flash attention, all-fp16 single-pass, base-2 softmax (ex2.f16x2)
// ---------------------------------------------------------------------------
#define AROWB 144
#define AQ_OFF 0u
#define AST0   18432u
#define ASTG   18432u
#define AK_OFF 0u
#define AV_OFF 9216u
#define ATTN_SMEM (18432 + 2 * 18432)
// 0.125 (1/sqrt(64)) * log2(e)
#define C_SCALE 0.18033688011112042f

__device__ __forceinline__ void attn_load_kv(
    uint32_t sbase, const __half* __restrict__ qkv, int b, int hd, int kt, int t) {
#pragma unroll
    for (int i = 0; i < 4; ++i) {
        int u = t + i * 256;
        int sel = u >> 9;                // 0 K, 1 V
        int v = u & 511;
        int row = v >> 3, seg = v & 7;
        int off = sel ? 2048 : 1024;
        const __half* src =
            qkv + ((size_t)((kt * 64 + row) * BBB + b)) * 3072 + off + hd + seg * 8;
        uint32_t dst = sbase + (uint32_t)sel * 9216u + (uint32_t)(row * AROWB + seg * 16);
        CP16(dst, src);
    }
}

__global__ __launch_bounds__(256, 2)
void attn_mma_kernel(const __half* __restrict__ qkv, __half* __restrict__ ctx) {
    extern __shared__ char smem[];
    const uint32_t sb = smem_u32(smem);
    const int t    = threadIdx.x;
    const int lane = t & 31;
    const int w    = t >> 5;
    const int b    = blockIdx.y >> 4;
    const int h    = blockIdx.y & 15;
    const int q0   = blockIdx.x * 128;
    const int hd   = h * DHH;

#pragma unroll
    for (int i = 0; i < 4; ++i) {
        int u = t + i * 256;
        int row = u >> 3, seg = u & 7;
        const __half* src = qkv + ((size_t)((q0 + row) * BBB + b)) * 3072 + hd + seg * 8;
        uint32_t dst = sb + AQ_OFF + (uint32_t)(row * AROWB + seg * 16);
        CP16(dst, src);
    }
    CPCOMMIT();
    attn_load_kv(sb + AST0, qkv, b, hd, 0, t);
    CPCOMMIT();

    float Oa[8][4];
#pragma unroll
    for (int j = 0; j < 8; j++)
#pragma unroll
        for (int c = 0; c < 4; c++) Oa[j][c] = 0.f;
    float m0r = -1e30f, m1r = -1e30f, l0r = 0.f, l1r = 0.f;

    const uint32_t arow_off = (uint32_t)((w * 16 + (lane & 15)) * AROWB + (lane >> 4) * 16);
    const uint32_t brow_off = (uint32_t)(((lane & 7) + ((lane & 16) >> 1)) * AROWB +
                                         ((lane >> 3) & 1) * 16);
    const uint32_t vrow_off = (uint32_t)((lane & 15) * AROWB + (lane >> 4) * 16);

    for (int kt = 0; kt < 8; ++kt) {
        CPWAIT(0);
        __syncthreads();
        if (kt + 1 < 8) {
            attn_load_kv(sb + AST0 + (uint32_t)((kt + 1) & 1) * ASTG, qkv, b, hd,
                         kt + 1, t);
            CPCOMMIT();
        }
        const uint32_t stg = sb + AST0 + (uint32_t)(kt & 1) * ASTG;

        float st[8][4];
#pragma unroll
        for (int j = 0; j < 8; j++)
#pragma unroll
            for (int c = 0; c < 4; c++) st[j][c] = 0.f;
#pragma unroll
        for (int kc = 0; kc < 4; ++kc) {
            uint32_t fa[4];
            LDSM4(fa, sb + AQ_OFF + arow_off + kc * 32);
#pragma unroll
            for (int g = 0; g < 4; ++g) {
                uint32_t fb[4];
                LDSM4(fb, stg + AK_OFF + brow_off + g * (16 * AROWB) + kc * 32);
                MMA_F16(st[2 * g],     fa, fb[0], fb[1]);
                MMA_F16(st[2 * g + 1], fa, fb[2], fb[3]);
            }
        }

        float mx0 = -1e30f, mx1 = -1e30f;
#pragma unroll
        for (int j = 0; j < 8; j++) {
            st[j][0] *= C_SCALE; st[j][1] *= C_SCALE;
            st[j][2] *= C_SCALE; st[j][3] *= C_SCALE;
            mx0 = fmaxf(mx0, fmaxf(st[j][0], st[j][1]));
            mx1 = fmaxf(mx1, fmaxf(st[j][2], st[j][3]));
        }
        mx0 = fmaxf(mx0, __shfl_xor_sync(0xffffffffu, mx0, 1));
        mx0 = fmaxf(mx0, __shfl_xor_sync(0xffffffffu, mx0, 2));
        mx1 = fmaxf(mx1, __shfl_xor_sync(0xffffffffu, mx1, 1));
        mx1 = fmaxf(mx1, __shfl_xor_sync(0xffffffffu, mx1, 2));
        const float nm0 = fmaxf(m0r, mx0), nm1 = fmaxf(m1r, mx1);
        const float al0 = exp2f(m0r - nm0), al1 = exp2f(m1r - nm1);

        uint32_t pp[8][2];
        float s0 = 0.f, s1 = 0.f;
#pragma unroll
        for (int j = 0; j < 8; j++) {
            uint32_t q0p = pack_h2(st[j][0] - nm0, st[j][1] - nm0);
            uint32_t q1p = pack_h2(st[j][2] - nm1, st[j][3] - nm1);
            EX2_H2(pp[j][0], q0p);
            EX2_H2(pp[j][1], q1p);
            float2 v0 = unpack_h2(pp[j][0]);
            float2 v1 = unpack_h2(pp[j][1]);
            s0 += v0.x + v0.y;
            s1 += v1.x + v1.y;
        }
        s0 += __shfl_xor_sync(0xffffffffu, s0, 1);
        s0 += __shfl_xor_sync(0xffffffffu, s0, 2);
        s1 += __shfl_xor_sync(0xffffffffu, s1, 1);
        s1 += __shfl_xor_sync(0xffffffffu, s1, 2);
        l0r = l0r * al0 + s0;
        l1r = l1r * al1 + s1;
        m0r = nm0; m1r = nm1;
#pragma unroll
        for (int j = 0; j < 8; j++) {
            Oa[j][0] *= al0; Oa[j][1] *= al0;
            Oa[j][2] *= al1; Oa[j][3] *= al1;
        }

#pragma unroll
        for (int kc = 0; kc < 4; ++kc) {
            uint32_t ph[4];
            ph[0] = pp[2 * kc][0];
            ph[1] = pp[2 * kc][1];
            ph[2] = pp[2 * kc + 1][0];
            ph[3] = pp[2 * kc + 1][1];
            const uint32_t vbase = stg + AV_OFF + (uint32_t)(kc * 16 * AROWB) + vrow_off;
#pragma unroll
            for (int g = 0; g < 4; ++g) {
                uint32_t fv[4];
                LDSM4T(fv, vbase + g * 32);
                MMA_F16(Oa[2 * g],     ph, fv[0], fv[1]);
                MMA_F16(Oa[2 * g + 1], ph, fv[2], fv[3]);
            }
        }
    }

    const float inv0 = 1.f / l0r;
    const float inv1 = 1.f / l1r;
    const int r_lo = q0 + w * 16 + (lane >> 2);
    const int col0 = hd + (lane & 3) * 2;
#pragma unroll
    for (int j = 0; j < 8; j++) {
        const int col = col0 + j * 8;
        size_t o0 = ((size_t)(r_lo * BBB + b)) * 1024 + col;
        size_t o1 = ((size_t)((r_lo + 8) * BBB + b)) * 1024 + col;
        *reinterpret_cast<__half2*>(ctx + o0) =
            __halves2half2(__float2half_rn(Oa[j][0] * inv0),
                           __float2half_rn(Oa[j][1] * inv0));
        *reinterpret_cast<__half2*>(ctx + o1) =
            __halves2half2(__float2half_rn(Oa[j][2] * inv1),
                           __float2half_rn(Oa[j][3] * inv1));
    }
}

// ---------------------------------------------------------------------------
// 4) LayerNorm, fp16 in/out, fp32 math: out = LN(a + r) * g + b
// ---------------------------------------------------------------------------
__global__ __launch_bounds__(256)
void ln_kernel(const __half* __restrict__ a, const __half* __restrict__ r,
               const float* __restrict__ g, const float* __restrict__ b,
               __half* __restrict__ out) {
    __shared__ float red1[8];
    __shared__ float red2[8];
    const int t = threadIdx.x;
    const int lane = t & 31;
    const int w = t >> 5;
    const size_t row = blockIdx.x;
    __half2 a0 = reinterpret_cast<const __half2*>(a + row * 1024)[2 * t];
    __half2 a1 = reinterpret_cast<const __half2*>(a + row * 1024)[2 * t + 1];
    float2 f0 = __half22float2(a0);
    float2 f1 = __half22float2(a1);
    float4 v = make_float4(f0.x, f0.y, f1.x, f1.y);
    if (r != nullptr) {
        __half2 r0 = reinterpret_cast<const __half2*>(r + row * 1024)[2 * t];
        __half2 r1 = reinterpret_cast<const __half2*>(r + row * 1024)[2 * t + 1];
        float2 g0 = __half22float2(r0);
        float2 g1 = __half22float2(r1);
        v.x += g0.x; v.y += g0.y; v.z += g1.x; v.w += g1.y;
    }
    float s = v.x + v.y + v.z + v.w;
#pragma unroll
    for (int o = 16; o > 0; o >>= 1) s += __shfl_xor_sync(0xffffffffu, s, o);
    if (lane == 0) red1[w] = s;
    __syncthreads();
    float mu = (red1[0] + red1[1] + red1[2] + red1[3] +
                red1[4] + red1[5] + red1[6] + red1[7]) * (1.f / 1024.f);
    float dx = v.x - mu, dy = v.y - mu, dz = v.z - mu, dw = v.w - mu;
    float q = dx * dx + dy * dy + dz * dz + dw * dw;
#pragma unroll
    for (int o = 16; o > 0; o >>= 1) q += __shfl_xor_sync(0xffffffffu, q, o);
    if (lane == 0) red2[w] = q;
    __syncthreads();
    float var = (red2[0] + red2[1] + red2[2] + red2[3] +
                 red2[4] + red2[5] + red2[6] + red2[7]) * (1.f / 1024.f);
    float inv = rsqrtf(var + 1e-5f);
    float4 g4 = reinterpret_cast<const float4*>(g)[t];
    float4 b4 = reinterpret_cast<const float4*>(b)[t];
    float o0 = dx * inv * g4.x + b4.x;
    float o1 = dy * inv * g4.y + b4.y;
    float o2 = dz * inv * g4.z + b4.z;
    float o3 = dw * inv * g4.w + b4.w;
    reinterpret_cast<__half2*>(out + row * 1024)[2 * t] =
        __halves2half2(__float2half_rn(o0), __float2half_rn(o1));
    reinterpret_cast<__half2*>(out + row * 1024)[2 * t + 1] =
        __halves2half2(__float2half_rn(o2), __float2half_rn(o3));
}

// ---------------------------------------------------------------------------
// Host orchestration
// ---------------------------------------------------------------------------
extern "C" void kernel_launch(void* const* d_in, const int* in_sizes, int n_in,
                              void* d_out, int out_size) {
    (void)in_sizes; (void)n_in; (void)out_size;
    const float* x    = (const float*)d_in[0];
    const float* Wqkv = (const float*)d_in[1];
    const float* bqkv = (const float*)d_in[2];
    const float* Wo   = (const float*)d_in[3];
    const float* bo   = (const float*)d_in[4];
    const float* W1   = (const float*)d_in[5];
    const float* b1   = (const float*)d_in[6];
    const float* W2   = (const float*)d_in[7];
    const float* b2   = (const float*)d_in[8];
    const float* ln1g = (const float*)d_in[9];
    const float* ln1b = (const float*)d_in[10];
    const float* ln2g = (const float*)d_in[11];
    const float* ln2b = (const float*)d_in[12];
    const float* lnfg = (const float*)d_in[13];
    const float* lnfb = (const float*)d_in[14];
    const float* Wout = (const float*)d_in[15];
    const float* bout = (const float*)d_in[16];
    float* out = (float*)d_out;

    float *pe;
    __half *hf, *ff, *qvh, *wh, *tmph;
    cudaGetSymbolAddress((void**)&pe,   g_pe);
    cudaGetSymbolAddress((void**)&tmph, g_tmph);
    cudaGetSymbolAddress((void**)&hf,   g_hf);
    cudaGetSymbolAddress((void**)&ff,   g_ff);
    cudaGetSymbolAddress((void**)&qvh,  g_qkvh);
    cudaGetSymbolAddress((void**)&wh,   g_wh);

    cudaFuncSetAttribute(gemm_mma<0, 0, 1>, cudaFuncAttributeMaxDynamicSharedMemorySize, GEMM_SMEM);
    cudaFuncSetAttribute(gemm_mma<1, 0, 1>, cudaFuncAttributeMaxDynamicSharedMemorySize, GEMM_SMEM);
    cudaFuncSetAttribute(gemm_mma<0, 1, 0>, cudaFuncAttributeMaxDynamicSharedMemorySize, GEMM_SMEM);
    cudaFuncSetAttribute(attn_mma_kernel, cudaFuncAttributeMaxDynamicSharedMemorySize, ATTN_SMEM);

    cvt_all<<<(F4_ALL + 255) / 256, 256>>>(Wqkv, Wo, W1, W2, Wout, wh);
    pe_table_kernel<<<(SSS * DDD) / 256, 256>>>(pe);
    add_pe_kernel<<<(TTT * DDD / 4) / 256, 256>>>(x, pe, hf);

    for (int l = 0; l < LLL; l++) {
        const __half* wq_h = wh + OFF_QKV + (size_t)l * 3145728;
        const __half* wo_h = wh + OFF_WO + (size_t)l * 1048576;
        const __half* w1_h = wh + OFF_W1 + (size_t)l * 2097152;
        const __half* w2_h = wh + OFF_W2 + (size_t)l * 2097152;

        // qkv (fp16) = hf @ Wqkv^T + bqkv
        gemm_mma<0, 0, 1><<<dim3(3072 / 128, TTT / 128), 256, GEMM_SMEM>>>(
            hf, wq_h, bqkv + (size_t)l * 3072, nullptr, qvh, TTT, 3072, 1024);
        // ctx (fp16) = flash attention
        attn_mma_kernel<<<dim3(SSS / 128, BBB * HHH), 256, ATTN_SMEM>>>(qvh, ff);
        // tmph (fp16) = ctx @ Wo^T + bo
        gemm_mma<0, 0, 1><<<dim3(1024 / 128, TTT / 128), 256, GEMM_SMEM>>>(
            ff, wo_h, bo + (size_t)l * 1024, nullptr, tmph, TTT, 1024, 1024);
        // hf = LN(hf + tmph)
        ln_kernel<<<TTT, 256>>>(hf, tmph, ln1g + (size_t)l * 1024,
                                ln1b + (size_t)l * 1024, hf);
        // ff (fp16) = relu(hf @ W1^T + b1)
        gemm_mma<1, 0, 1><<<dim3(2048 / 128, TTT / 128), 256, GEMM_SMEM>>>(
            hf, w1_h, b1 + (size_t)l * 2048, nullptr, ff, TTT, 2048, 1024);
        // tmph (fp16) = ff @ W2^T + b2
        gemm_mma<0, 0, 1><<<dim3(1024 / 128, TTT / 128), 256, GEMM_SMEM>>>(
            ff, w2_h, b2 + (size_t)l * 1024, nullptr, tmph, TTT, 1024, 2048);
        // hf = LN(hf + tmph)
        ln_kernel<<<TTT, 256>>>(hf, tmph, ln2g + (size_t)l * 1024,
                                ln2b + (size_t)l * 1024, hf);
    }

    // final norm
    ln_kernel<<<TTT, 256>>>(hf, nullptr, lnfg, lnfb, hf);
    // out = hf_final @ Wout^T + bout   [fp32 out, fused transpose]
    gemm_mma<0, 1, 0><<<dim3(DMEMM / 128, TTT / 128), 256, GEMM_SMEM>>>(
        hf, wh + OFF_WOUT, bout, out, nullptr, TTT, DMEMM, 1024);
}